// round 2
// baseline (speedup 1.0000x reference)
#include <cuda_runtime.h>
#include <math.h>

// ---------------- dims ----------------
#define Bsz 2
#define Tn  2048
#define Cn  1024
#define Vn  32000
#define Ln  4
#define En  3
#define Hn  4096
#define BT  (Bsz*Tn)   // 4096 tokens

// ---------------- scratch (__device__ globals; no allocs) ----------------
__device__ float g_X  [BT*Cn];
__device__ float g_HS [BT*Cn];
__device__ float g_MIX[BT*Cn];   // reused as RS (= r*state) after scan
__device__ float g_R  [BT*Cn];
__device__ float g_K  [BT*Cn];
__device__ float g_V  [BT*Cn];
__device__ float g_ST [BT*Cn];
__device__ float g_H  [BT*Cn];
__device__ float g_HZ [BT*2*Cn];
__device__ float g_HID[(size_t)BT*Hn];
__device__ float g_SC [BT];
__device__ int   g_CNT[En];
__device__ int   g_LIST[En*BT];

// ---------------- embedding gather ----------------
__global__ void embed_k(const int* __restrict__ idx, const float* __restrict__ emb) {
    int i = blockIdx.x*blockDim.x + threadIdx.x;
    if (i >= BT*Cn) return;
    int row = i >> 10, c = i & 1023;
    g_X[i] = emb[(size_t)idx[row]*Cn + c];
}

// ---------------- LayerNorm (block per row, 256 thr, C=1024) ----------------
__global__ void ln_k(const float* __restrict__ in, const float* __restrict__ g,
                     const float* __restrict__ b, float* __restrict__ out) {
    int row = blockIdx.x;
    const float* p = in + (size_t)row*Cn;
    float v[4];
    float s = 0.f, ss = 0.f;
#pragma unroll
    for (int j = 0; j < 4; j++) {
        v[j] = p[threadIdx.x + j*256];
        s  += v[j];
        ss += v[j]*v[j];
    }
#pragma unroll
    for (int o = 16; o > 0; o >>= 1) {
        s  += __shfl_xor_sync(0xffffffffu, s,  o);
        ss += __shfl_xor_sync(0xffffffffu, ss, o);
    }
    __shared__ float sh[2][8];
    int w = threadIdx.x >> 5;
    if ((threadIdx.x & 31) == 0) { sh[0][w] = s; sh[1][w] = ss; }
    __syncthreads();
    s = 0.f; ss = 0.f;
#pragma unroll
    for (int j = 0; j < 8; j++) { s += sh[0][j]; ss += sh[1][j]; }
    float mean = s * (1.f/Cn);
    float var  = ss * (1.f/Cn) - mean*mean;
    float rstd = rsqrtf(var + 1e-5f);
    float* o = out + (size_t)row*Cn;
#pragma unroll
    for (int j = 0; j < 4; j++) {
        int c = threadIdx.x + j*256;
        o[c] = (v[j]-mean)*rstd*g[c] + b[c];
    }
}

// ---------------- token-shift mix ----------------
__global__ void mix_k() {
    int i = blockIdx.x*blockDim.x + threadIdx.x;
    if (i >= BT*Cn) return;
    int t = (i >> 10) & (Tn - 1);
    float prev = t ? g_HS[i - Cn] : 0.f;
    g_MIX[i] = 0.5f*(g_HS[i] + prev);
}

// ---------------- rwkv state scan + r*state (serial over T per (b,c)) ----------------
__global__ void scan_k() {
    int lane = blockIdx.x*blockDim.x + threadIdx.x;
    if (lane >= Bsz*Cn) return;
    int b = lane >> 10, c = lane & 1023;
    size_t base = (size_t)b*Tn*Cn + c;
    float acc = 0.f;
#pragma unroll 4
    for (int t = 0; t < Tn; t++) {
        size_t id = base + (size_t)t*Cn;
        acc += g_K[id]*g_V[id];
        float st = acc / (float)(t+1);
        g_ST[id]  = st;
        g_MIX[id] = g_R[id]*st;   // RS reuse of MIX buffer
    }
}

// ---------------- routing: conf/affinity dots, argmax, compaction ----------------
__global__ void zcnt_k() { if (threadIdx.x < En) g_CNT[threadIdx.x] = 0; }

__global__ void route_k(const float* __restrict__ wc,   // [E,C] this layer
                        const float* __restrict__ wa,   // [C,E] this layer
                        const float* __restrict__ shp)  // [E]
{
    int bt = blockIdx.x;
    const float* hp = g_H + (size_t)bt*Cn;
    float p[6] = {0,0,0,0,0,0};
    for (int c = threadIdx.x; c < Cn; c += 128) {
        float hv = hp[c];
        p[0] += hv*wc[c];
        p[1] += hv*wc[Cn + c];
        p[2] += hv*wc[2*Cn + c];
        p[3] += hv*wa[c*En + 0];
        p[4] += hv*wa[c*En + 1];
        p[5] += hv*wa[c*En + 2];
    }
#pragma unroll
    for (int o = 16; o > 0; o >>= 1)
#pragma unroll
        for (int q = 0; q < 6; q++) p[q] += __shfl_xor_sync(0xffffffffu, p[q], o);
    __shared__ float sm[4][6];
    int w = threadIdx.x >> 5;
    if ((threadIdx.x & 31) == 0) {
#pragma unroll
        for (int q = 0; q < 6; q++) sm[w][q] = p[q];
    }
    __syncthreads();
    if (threadIdx.x == 0) {
        float d[6];
#pragma unroll
        for (int q = 0; q < 6; q++) d[q] = sm[0][q] + sm[1][q] + sm[2][q] + sm[3][q];
        float best = -3.4e38f, wcf = 0.f;
        int wi = 0;
#pragma unroll
        for (int e = 0; e < En; e++) {
            float conf = 1.f/(1.f + expf(-d[e]));
            float bid  = conf*shp[e] + d[3+e];
            if (bid > best) { best = bid; wi = e; wcf = conf; }  // strict > => first-max, matches argmax
        }
        g_SC[bt] = wcf / (wcf + 1e-6f);
        int pos = atomicAdd(&g_CNT[wi], 1);
        g_LIST[wi*BT + pos] = bt;
    }
}

// ---------------- hz = concat(h, state) ----------------
__global__ void hz_k() {
    int i = blockIdx.x*blockDim.x + threadIdx.x;
    if (i >= BT*2*Cn) return;
    int row = i >> 11;
    int c = i & (2*Cn - 1);
    g_HZ[i] = (c < Cn) ? g_H[(size_t)row*Cn + c] : g_ST[(size_t)row*Cn + c - Cn];
}

// ---------------- fp32 SGEMM: 128x128x16, 256 thr, 8x8/thr ----------------
// MODE 0: C=acc   1: C=sigmoid(acc)   2: C+=acc   3: C=relu(acc)
// MODE 4: scatter: tok=rows[m]; X[tok*N+n] += acc*scal[tok]
// gatherA: A row index = rows[m] (token id); cntp: dynamic M (tiles early-exit)
template<int MODE>
__global__ void __launch_bounds__(256) gemm_k(
    const float* __restrict__ A, const float* __restrict__ Bm, float* __restrict__ Cm,
    int K, int N,
    const int* __restrict__ rows, const int* __restrict__ cntp,
    const float* __restrict__ scal, int gatherA)
{
    int Meff = cntp ? *cntp : BT;
    int m0 = blockIdx.y * 128;
    if (m0 >= Meff) return;

    __shared__ float As[16][132];
    __shared__ float Bs[16][128];

    int tid = threadIdx.x;
    int am = tid >> 2;
    int ak = (tid & 3) << 2;
    int bk = tid >> 5;
    int bn = (tid & 31) << 2;
    const float* Bp = Bm + (size_t)blockIdx.x*128 + bn;

    const float* Ap[2];
#pragma unroll
    for (int i = 0; i < 2; i++) {
        int m = m0 + am + i*64;
        int mm = (m < Meff) ? m : (Meff - 1);
        int gr = gatherA ? rows[mm] : mm;
        Ap[i] = A + (size_t)gr*K + ak;
    }

    float acc[8][8];
#pragma unroll
    for (int i = 0; i < 8; i++)
#pragma unroll
        for (int j = 0; j < 8; j++) acc[i][j] = 0.f;

    int tx = tid & 15, ty = tid >> 4;

    for (int k0 = 0; k0 < K; k0 += 16) {
#pragma unroll
        for (int i = 0; i < 2; i++) {
            float4 va = *(const float4*)(Ap[i] + k0);
            As[ak+0][am + i*64] = va.x;
            As[ak+1][am + i*64] = va.y;
            As[ak+2][am + i*64] = va.z;
            As[ak+3][am + i*64] = va.w;
        }
#pragma unroll
        for (int i = 0; i < 2; i++) {
            *(float4*)&Bs[bk + i*8][bn] = *(const float4*)(Bp + (size_t)(k0 + bk + i*8)*N);
        }
        __syncthreads();
#pragma unroll
        for (int kk = 0; kk < 16; kk++) {
            float a[8], bfr[8];
            *(float4*)(a)     = *(const float4*)&As[kk][ty*8];
            *(float4*)(a + 4) = *(const float4*)&As[kk][ty*8 + 4];
            *(float4*)(bfr)     = *(const float4*)&Bs[kk][tx*8];
            *(float4*)(bfr + 4) = *(const float4*)&Bs[kk][tx*8 + 4];
#pragma unroll
            for (int i = 0; i < 8; i++)
#pragma unroll
                for (int j = 0; j < 8; j++)
                    acc[i][j] = fmaf(a[i], bfr[j], acc[i][j]);
        }
        __syncthreads();
    }

    int cn = blockIdx.x*128 + tx*8;
#pragma unroll
    for (int i = 0; i < 8; i++) {
        int m = m0 + ty*8 + i;
        if (m >= Meff) break;
        if (MODE == 4) {
            int tok = rows[m];
            float sc = scal[tok];
            float* xr = Cm + (size_t)tok*N + cn;
#pragma unroll
            for (int j = 0; j < 8; j++) xr[j] += acc[i][j]*sc;
        } else {
            float* cr = Cm + (size_t)m*N + cn;
#pragma unroll
            for (int j = 0; j < 8; j++) {
                float v = acc[i][j];
                if (MODE == 1) v = 1.f/(1.f + expf(-v));
                else if (MODE == 2) v += cr[j];
                else if (MODE == 3) v = fmaxf(v, 0.f);
                cr[j] = v;
            }
        }
    }
}

// ---------------- launch ----------------
extern "C" void kernel_launch(void* const* d_in, const int* in_sizes, int n_in,
                              void* d_out, int out_size)
{
    const int*   idx   = (const int*)  d_in[0];
    const float* shares= (const float*)d_in[1];
    const float* emb   = (const float*)d_in[2];
    const float* ln1g  = (const float*)d_in[3];
    const float* ln1b  = (const float*)d_in[4];
    const float* ln2g  = (const float*)d_in[5];
    const float* ln2b  = (const float*)d_in[6];
    const float* Wr    = (const float*)d_in[7];
    const float* Wk    = (const float*)d_in[8];
    const float* Wv    = (const float*)d_in[9];
    const float* Wo    = (const float*)d_in[10];
    const float* W1    = (const float*)d_in[11];
    const float* W2    = (const float*)d_in[12];
    const float* wconf = (const float*)d_in[13];
    const float* Wl1   = (const float*)d_in[14];
    const float* Wl2   = (const float*)d_in[15];
    // d_in[16] = W_diff (unused by forward)
    const float* Waff  = (const float*)d_in[17];
    const float* lnfg  = (const float*)d_in[18];
    const float* lnfb  = (const float*)d_in[19];
    const float* headW = (const float*)d_in[20];
    float* out = (float*)d_out;
    (void)in_sizes; (void)n_in; (void)out_size;

    float *X, *HS, *MIX, *Rb, *Kb, *Vb, *ST, *Hh, *HZ, *HID, *SC;
    int *CNT, *LIST;
    cudaGetSymbolAddress((void**)&X,   g_X);
    cudaGetSymbolAddress((void**)&HS,  g_HS);
    cudaGetSymbolAddress((void**)&MIX, g_MIX);
    cudaGetSymbolAddress((void**)&Rb,  g_R);
    cudaGetSymbolAddress((void**)&Kb,  g_K);
    cudaGetSymbolAddress((void**)&Vb,  g_V);
    cudaGetSymbolAddress((void**)&ST,  g_ST);
    cudaGetSymbolAddress((void**)&Hh,  g_H);
    cudaGetSymbolAddress((void**)&HZ,  g_HZ);
    cudaGetSymbolAddress((void**)&HID, g_HID);
    cudaGetSymbolAddress((void**)&SC,  g_SC);
    cudaGetSymbolAddress((void**)&CNT, g_CNT);
    cudaGetSymbolAddress((void**)&LIST,g_LIST);

    embed_k<<<(BT*Cn)/256, 256>>>(idx, emb);

    dim3 gC(Cn/128, BT/128);   // N=1024 outputs
    dim3 gH(Hn/128, BT/128);   // N=4096 outputs

    for (int l = 0; l < Ln; l++) {
        ln_k<<<BT, 256>>>(X, ln1g + (size_t)l*Cn, ln1b + (size_t)l*Cn, HS);
        mix_k<<<(BT*Cn)/256, 256>>>();

        gemm_k<1><<<gC, 256>>>(MIX, Wr + (size_t)l*Cn*Cn, Rb, Cn, Cn, nullptr, nullptr, nullptr, 0);
        gemm_k<0><<<gC, 256>>>(MIX, Wk + (size_t)l*Cn*Cn, Kb, Cn, Cn, nullptr, nullptr, nullptr, 0);
        gemm_k<0><<<gC, 256>>>(MIX, Wv + (size_t)l*Cn*Cn, Vb, Cn, Cn, nullptr, nullptr, nullptr, 0);

        scan_k<<<16, 128>>>();   // writes ST and RS (into MIX)

        gemm_k<2><<<gC, 256>>>(MIX, Wo + (size_t)l*Cn*Cn, X, Cn, Cn, nullptr, nullptr, nullptr, 0);

        ln_k<<<BT, 256>>>(X, ln2g + (size_t)l*Cn, ln2b + (size_t)l*Cn, Hh);

        zcnt_k<<<1, 32>>>();
        route_k<<<BT, 128>>>(wconf + (size_t)l*En*Cn, Waff + (size_t)l*Cn*En, shares + (size_t)l*En);
        hz_k<<<(BT*2*Cn)/256, 256>>>();

        for (int e = 0; e < 2; e++) {
            gemm_k<3><<<gH, 256>>>(Hh,  W1 + ((size_t)l*2 + e)*Cn*Hn, HID, Cn, Hn,
                                   LIST + e*BT, CNT + e, nullptr, 1);
            gemm_k<4><<<gC, 256>>>(HID, W2 + ((size_t)l*2 + e)*Hn*Cn, X,   Hn, Cn,
                                   LIST + e*BT, CNT + e, SC, 0);
        }
        gemm_k<3><<<gH, 256>>>(HZ,  Wl1 + (size_t)l*2*Cn*Hn, HID, 2*Cn, Hn,
                               LIST + 2*BT, CNT + 2, nullptr, 1);
        gemm_k<4><<<gC, 256>>>(HID, Wl2 + (size_t)l*Hn*Cn,   X,   Hn,   Cn,
                               LIST + 2*BT, CNT + 2, SC, 0);
    }

    ln_k<<<BT, 256>>>(X, lnfg, lnfb, Hh);
    gemm_k<0><<<dim3(Vn/128, BT/128), 256>>>(Hh, headW, out, Cn, Vn, nullptr, nullptr, nullptr, 0);
}

// round 3
// speedup vs baseline: 1.2500x; 1.2500x over previous
#include <cuda_runtime.h>
#include <math.h>

// ---------------- dims ----------------
#define Bsz 2
#define Tn  2048
#define Cn  1024
#define Vn  32000
#define Ln  4
#define En  3
#define Hn  4096
#define BT  (Bsz*Tn)   // 4096 tokens
#define CH  16         // scan chunks
#define CL  (Tn/CH)    // 128 steps per chunk

// ---------------- scratch (__device__ globals; no allocs) ----------------
__device__ float g_X  [BT*Cn];
__device__ float g_HS [BT*Cn];
__device__ float g_MIX[BT*Cn];   // reused as RS (= r*state) after scan
__device__ float g_R  [BT*Cn];
__device__ float g_K  [BT*Cn];
__device__ float g_V  [BT*Cn];
__device__ float g_ST [BT*Cn];
__device__ float g_H  [BT*Cn];
__device__ float g_HZ [BT*2*Cn];
__device__ float g_HID[(size_t)BT*Hn];
__device__ float g_SC [BT];
__device__ float g_PART[Bsz*CH*Cn];
__device__ int   g_CNT[En];
__device__ int   g_LIST[En*BT];

// ---------------- f32x2 helpers ----------------
__device__ __forceinline__ unsigned long long pack2(float x) {
    unsigned long long r;
    unsigned int u = __float_as_uint(x);
    asm("mov.b64 %0, {%1, %1};" : "=l"(r) : "r"(u));
    return r;
}
__device__ __forceinline__ void fma2(unsigned long long& d, unsigned long long a, unsigned long long b) {
    asm("fma.rn.f32x2 %0, %1, %2, %0;" : "+l"(d) : "l"(a), "l"(b));
}
__device__ __forceinline__ float2 unpack2(unsigned long long v) {
    float2 f;
    f.x = __uint_as_float((unsigned int)v);
    f.y = __uint_as_float((unsigned int)(v >> 32));
    return f;
}

// ---------------- embedding gather ----------------
__global__ void embed_k(const int* __restrict__ idx, const float* __restrict__ emb) {
    int i = blockIdx.x*blockDim.x + threadIdx.x;
    if (i >= BT*Cn) return;
    int row = i >> 10, c = i & 1023;
    g_X[i] = emb[(size_t)idx[row]*Cn + c];
}

// ---------------- LayerNorm (block per row, 256 thr, C=1024) ----------------
__global__ void ln_k(const float* __restrict__ in, const float* __restrict__ g,
                     const float* __restrict__ b, float* __restrict__ out) {
    int row = blockIdx.x;
    const float* p = in + (size_t)row*Cn;
    float v[4];
    float s = 0.f, ss = 0.f;
#pragma unroll
    for (int j = 0; j < 4; j++) {
        v[j] = p[threadIdx.x + j*256];
        s  += v[j];
        ss += v[j]*v[j];
    }
#pragma unroll
    for (int o = 16; o > 0; o >>= 1) {
        s  += __shfl_xor_sync(0xffffffffu, s,  o);
        ss += __shfl_xor_sync(0xffffffffu, ss, o);
    }
    __shared__ float sh[2][8];
    int w = threadIdx.x >> 5;
    if ((threadIdx.x & 31) == 0) { sh[0][w] = s; sh[1][w] = ss; }
    __syncthreads();
    s = 0.f; ss = 0.f;
#pragma unroll
    for (int j = 0; j < 8; j++) { s += sh[0][j]; ss += sh[1][j]; }
    float mean = s * (1.f/Cn);
    float var  = ss * (1.f/Cn) - mean*mean;
    float rstd = rsqrtf(var + 1e-5f);
    float* o = out + (size_t)row*Cn;
#pragma unroll
    for (int j = 0; j < 4; j++) {
        int c = threadIdx.x + j*256;
        o[c] = (v[j]-mean)*rstd*g[c] + b[c];
    }
}

// ---------------- token-shift mix ----------------
__global__ void mix_k() {
    int i = blockIdx.x*blockDim.x + threadIdx.x;
    if (i >= BT*Cn) return;
    int t = (i >> 10) & (Tn - 1);
    float prev = t ? g_HS[i - Cn] : 0.f;
    g_MIX[i] = 0.5f*(g_HS[i] + prev);
}

// ---------------- 3-phase rwkv scan ----------------
// phase 1: per-chunk partial sums of k*v
__global__ void scan1_k() {
    int i = blockIdx.x*blockDim.x + threadIdx.x;   // over Bsz*CH*Cn = 32768
    if (i >= Bsz*CH*Cn) return;
    int c  = i & 1023;
    int ch = (i >> 10) & (CH - 1);
    int b  = i >> 14;
    size_t base = (size_t)b*Tn*Cn + (size_t)ch*CL*Cn + c;
    float s = 0.f;
#pragma unroll 4
    for (int t = 0; t < CL; t++) {
        size_t id = base + (size_t)t*Cn;
        s += g_K[id]*g_V[id];
    }
    g_PART[i] = s;
}
// phase 2: exclusive prefix over chunks per (b,c)
__global__ void scan2_k() {
    int i = blockIdx.x*blockDim.x + threadIdx.x;   // over Bsz*Cn = 2048
    if (i >= Bsz*Cn) return;
    int c = i & 1023, b = i >> 10;
    float run = 0.f;
#pragma unroll
    for (int ch = 0; ch < CH; ch++) {
        int id = ((b*CH + ch) << 10) | c;
        float p = g_PART[id];
        g_PART[id] = run;
        run += p;
    }
}
// phase 3: finish serial within chunk, write ST and RS (=r*state, into MIX)
__global__ void scan3_k() {
    int i = blockIdx.x*blockDim.x + threadIdx.x;
    if (i >= Bsz*CH*Cn) return;
    int c  = i & 1023;
    int ch = (i >> 10) & (CH - 1);
    int b  = i >> 14;
    size_t base = (size_t)b*Tn*Cn + (size_t)ch*CL*Cn + c;
    float acc = g_PART[i];
    int t0 = ch*CL;
#pragma unroll 4
    for (int t = 0; t < CL; t++) {
        size_t id = base + (size_t)t*Cn;
        acc += g_K[id]*g_V[id];
        float st = acc / (float)(t0 + t + 1);
        g_ST[id]  = st;
        g_MIX[id] = g_R[id]*st;
    }
}

// ---------------- routing: conf/affinity dots, argmax, compaction ----------------
__global__ void zcnt_k() { if (threadIdx.x < En) g_CNT[threadIdx.x] = 0; }

__global__ void route_k(const float* __restrict__ wc,   // [E,C] this layer
                        const float* __restrict__ wa,   // [C,E] this layer
                        const float* __restrict__ shp)  // [E]
{
    int bt = blockIdx.x;
    const float* hp = g_H + (size_t)bt*Cn;
    float p[6] = {0,0,0,0,0,0};
    for (int c = threadIdx.x; c < Cn; c += 128) {
        float hv = hp[c];
        p[0] += hv*wc[c];
        p[1] += hv*wc[Cn + c];
        p[2] += hv*wc[2*Cn + c];
        p[3] += hv*wa[c*En + 0];
        p[4] += hv*wa[c*En + 1];
        p[5] += hv*wa[c*En + 2];
    }
#pragma unroll
    for (int o = 16; o > 0; o >>= 1)
#pragma unroll
        for (int q = 0; q < 6; q++) p[q] += __shfl_xor_sync(0xffffffffu, p[q], o);
    __shared__ float sm[4][6];
    int w = threadIdx.x >> 5;
    if ((threadIdx.x & 31) == 0) {
#pragma unroll
        for (int q = 0; q < 6; q++) sm[w][q] = p[q];
    }
    __syncthreads();
    if (threadIdx.x == 0) {
        float d[6];
#pragma unroll
        for (int q = 0; q < 6; q++) d[q] = sm[0][q] + sm[1][q] + sm[2][q] + sm[3][q];
        float best = -3.4e38f, wcf = 0.f;
        int wi = 0;
#pragma unroll
        for (int e = 0; e < En; e++) {
            float conf = 1.f/(1.f + expf(-d[e]));
            float bid  = conf*shp[e] + d[3+e];
            if (bid > best) { best = bid; wi = e; wcf = conf; }
        }
        g_SC[bt] = wcf / (wcf + 1e-6f);
        int pos = atomicAdd(&g_CNT[wi], 1);
        g_LIST[wi*BT + pos] = bt;
    }
}

// ---------------- hz = concat(h, state) ----------------
__global__ void hz_k() {
    int i = blockIdx.x*blockDim.x + threadIdx.x;
    if (i >= BT*2*Cn) return;
    int row = i >> 11;
    int c = i & (2*Cn - 1);
    g_HZ[i] = (c < Cn) ? g_H[(size_t)row*Cn + c] : g_ST[(size_t)row*Cn + c - Cn];
}

// ---------------- fp32 SGEMM via packed f32x2 FMA: 128x128x16, 256 thr, 8x8/thr
// MODE 0: C=acc   1: C=sigmoid(acc)   2: C+=acc   3: C=relu(acc)
// MODE 4: scatter: tok=rows[m]; X[tok*N+n] += acc*scal[tok]
template<int MODE>
__global__ void __launch_bounds__(256) gemm_k(
    const float* __restrict__ A, const float* __restrict__ Bm, float* __restrict__ Cm,
    int K, int N,
    const int* __restrict__ rows, const int* __restrict__ cntp,
    const float* __restrict__ scal, int gatherA)
{
    int Meff = cntp ? *cntp : BT;
    int m0 = blockIdx.y * 128;
    if (m0 >= Meff) return;

    __shared__ float As[16][132];
    __shared__ float Bs[16][128];

    int tid = threadIdx.x;
    int am = tid >> 2;
    int ak = (tid & 3) << 2;
    int bk = tid >> 5;
    int bn = (tid & 31) << 2;
    const float* Bp = Bm + (size_t)blockIdx.x*128 + bn;

    const float* Ap[2];
#pragma unroll
    for (int i = 0; i < 2; i++) {
        int m = m0 + am + i*64;
        int mm = (m < Meff) ? m : (Meff - 1);
        int gr = gatherA ? rows[mm] : mm;
        Ap[i] = A + (size_t)gr*K + ak;
    }

    unsigned long long acc2[8][4];
#pragma unroll
    for (int i = 0; i < 8; i++)
#pragma unroll
        for (int j = 0; j < 4; j++) acc2[i][j] = 0ull;

    int tx = tid & 15, ty = tid >> 4;

    for (int k0 = 0; k0 < K; k0 += 16) {
#pragma unroll
        for (int i = 0; i < 2; i++) {
            float4 va = *(const float4*)(Ap[i] + k0);
            As[ak+0][am + i*64] = va.x;
            As[ak+1][am + i*64] = va.y;
            As[ak+2][am + i*64] = va.z;
            As[ak+3][am + i*64] = va.w;
        }
#pragma unroll
        for (int i = 0; i < 2; i++) {
            *(float4*)&Bs[bk + i*8][bn] = *(const float4*)(Bp + (size_t)(k0 + bk + i*8)*N);
        }
        __syncthreads();
#pragma unroll
        for (int kk = 0; kk < 16; kk++) {
            float a[8];
            *(float4*)(a)     = *(const float4*)&As[kk][ty*8];
            *(float4*)(a + 4) = *(const float4*)&As[kk][ty*8 + 4];
            unsigned long long bfr[4];
            {
                ulonglong2 t0 = *(const ulonglong2*)&Bs[kk][tx*8];
                ulonglong2 t1 = *(const ulonglong2*)&Bs[kk][tx*8 + 4];
                bfr[0] = t0.x; bfr[1] = t0.y; bfr[2] = t1.x; bfr[3] = t1.y;
            }
#pragma unroll
            for (int i = 0; i < 8; i++) {
                unsigned long long a2 = pack2(a[i]);
#pragma unroll
                for (int j = 0; j < 4; j++) fma2(acc2[i][j], a2, bfr[j]);
            }
        }
        __syncthreads();
    }

    int cn = blockIdx.x*128 + tx*8;
#pragma unroll
    for (int i = 0; i < 8; i++) {
        int m = m0 + ty*8 + i;
        if (m >= Meff) break;
        float av[8];
#pragma unroll
        for (int j = 0; j < 4; j++) {
            float2 f = unpack2(acc2[i][j]);
            av[2*j] = f.x; av[2*j+1] = f.y;
        }
        if (MODE == 4) {
            int tok = rows[m];
            float sc = scal[tok];
            float* xr = Cm + (size_t)tok*N + cn;
#pragma unroll
            for (int j = 0; j < 8; j++) xr[j] += av[j]*sc;
        } else {
            float* cr = Cm + (size_t)m*N + cn;
#pragma unroll
            for (int j = 0; j < 8; j++) {
                float v = av[j];
                if (MODE == 1) v = 1.f/(1.f + expf(-v));
                else if (MODE == 2) v += cr[j];
                else if (MODE == 3) v = fmaxf(v, 0.f);
                cr[j] = v;
            }
        }
    }
}

// ---------------- launch ----------------
extern "C" void kernel_launch(void* const* d_in, const int* in_sizes, int n_in,
                              void* d_out, int out_size)
{
    const int*   idx   = (const int*)  d_in[0];
    const float* shares= (const float*)d_in[1];
    const float* emb   = (const float*)d_in[2];
    const float* ln1g  = (const float*)d_in[3];
    const float* ln1b  = (const float*)d_in[4];
    const float* ln2g  = (const float*)d_in[5];
    const float* ln2b  = (const float*)d_in[6];
    const float* Wr    = (const float*)d_in[7];
    const float* Wk    = (const float*)d_in[8];
    const float* Wv    = (const float*)d_in[9];
    const float* Wo    = (const float*)d_in[10];
    const float* W1    = (const float*)d_in[11];
    const float* W2    = (const float*)d_in[12];
    const float* wconf = (const float*)d_in[13];
    const float* Wl1   = (const float*)d_in[14];
    const float* Wl2   = (const float*)d_in[15];
    // d_in[16] = W_diff (unused by forward)
    const float* Waff  = (const float*)d_in[17];
    const float* lnfg  = (const float*)d_in[18];
    const float* lnfb  = (const float*)d_in[19];
    const float* headW = (const float*)d_in[20];
    float* out = (float*)d_out;
    (void)in_sizes; (void)n_in; (void)out_size;

    float *X, *HS, *MIX, *Rb, *Kb, *Vb, *ST, *Hh, *HZ, *HID, *SC;
    int *CNT, *LIST;
    cudaGetSymbolAddress((void**)&X,   g_X);
    cudaGetSymbolAddress((void**)&HS,  g_HS);
    cudaGetSymbolAddress((void**)&MIX, g_MIX);
    cudaGetSymbolAddress((void**)&Rb,  g_R);
    cudaGetSymbolAddress((void**)&Kb,  g_K);
    cudaGetSymbolAddress((void**)&Vb,  g_V);
    cudaGetSymbolAddress((void**)&ST,  g_ST);
    cudaGetSymbolAddress((void**)&Hh,  g_H);
    cudaGetSymbolAddress((void**)&HZ,  g_HZ);
    cudaGetSymbolAddress((void**)&HID, g_HID);
    cudaGetSymbolAddress((void**)&SC,  g_SC);
    cudaGetSymbolAddress((void**)&CNT, g_CNT);
    cudaGetSymbolAddress((void**)&LIST,g_LIST);

    embed_k<<<(BT*Cn)/256, 256>>>(idx, emb);

    dim3 gC(Cn/128, BT/128);   // N=1024 outputs
    dim3 gH(Hn/128, BT/128);   // N=4096 outputs

    for (int l = 0; l < Ln; l++) {
        ln_k<<<BT, 256>>>(X, ln1g + (size_t)l*Cn, ln1b + (size_t)l*Cn, HS);
        mix_k<<<(BT*Cn)/256, 256>>>();

        gemm_k<1><<<gC, 256>>>(MIX, Wr + (size_t)l*Cn*Cn, Rb, Cn, Cn, nullptr, nullptr, nullptr, 0);
        gemm_k<0><<<gC, 256>>>(MIX, Wk + (size_t)l*Cn*Cn, Kb, Cn, Cn, nullptr, nullptr, nullptr, 0);
        gemm_k<0><<<gC, 256>>>(MIX, Wv + (size_t)l*Cn*Cn, Vb, Cn, Cn, nullptr, nullptr, nullptr, 0);

        scan1_k<<<(Bsz*CH*Cn)/256, 256>>>();
        scan2_k<<<(Bsz*Cn)/256, 256>>>();
        scan3_k<<<(Bsz*CH*Cn)/256, 256>>>();

        gemm_k<2><<<gC, 256>>>(MIX, Wo + (size_t)l*Cn*Cn, X, Cn, Cn, nullptr, nullptr, nullptr, 0);

        ln_k<<<BT, 256>>>(X, ln2g + (size_t)l*Cn, ln2b + (size_t)l*Cn, Hh);

        zcnt_k<<<1, 32>>>();
        route_k<<<BT, 128>>>(wconf + (size_t)l*En*Cn, Waff + (size_t)l*Cn*En, shares + (size_t)l*En);
        hz_k<<<(BT*2*Cn)/256, 256>>>();

        for (int e = 0; e < 2; e++) {
            gemm_k<3><<<gH, 256>>>(Hh,  W1 + ((size_t)l*2 + e)*Cn*Hn, HID, Cn, Hn,
                                   LIST + e*BT, CNT + e, nullptr, 1);
            gemm_k<4><<<gC, 256>>>(HID, W2 + ((size_t)l*2 + e)*Hn*Cn, X,   Hn, Cn,
                                   LIST + e*BT, CNT + e, SC, 0);
        }
        gemm_k<3><<<gH, 256>>>(HZ,  Wl1 + (size_t)l*2*Cn*Hn, HID, 2*Cn, Hn,
                               LIST + 2*BT, CNT + 2, nullptr, 1);
        gemm_k<4><<<gC, 256>>>(HID, Wl2 + (size_t)l*Hn*Cn,   X,   Hn,   Cn,
                               LIST + 2*BT, CNT + 2, SC, 0);
    }

    ln_k<<<BT, 256>>>(X, lnfg, lnfb, Hh);
    gemm_k<0><<<dim3(Vn/128, BT/128), 256>>>(Hh, headW, out, Cn, Vn, nullptr, nullptr, nullptr, 0);
}

// round 5
// speedup vs baseline: 1.6393x; 1.3114x over previous
#include <cuda_runtime.h>
#include <cuda_bf16.h>
#include <math.h>
#include <stdint.h>

// ---------------- dims ----------------
#define Bsz 2
#define Tn  2048
#define Cn  1024
#define Vn  32000
#define Ln  4
#define En  3
#define Hn  4096
#define BT  (Bsz*Tn)   // 4096 tokens
#define CH  16         // scan chunks
#define CL  (Tn/CH)
#define KC  64         // GEMM K-chunk (bf16 elems)

#define CC  (Cn*Cn)                     // 1,048,576
#define WPL (32*CC)                     // weights per layer (elems)
#define WHEAD ((size_t)4*WPL)           // head base
#define WTOT  ((size_t)4*WPL + (size_t)Cn*Vn)

// smem: 2 stages x 6 tiles x (128 x 64 bf16 = 16KB)
#define TILE_B 16384
#define STAGE_B (6*TILE_B)
#define SMEMB (2*STAGE_B)               // 196608

// ---------------- scratch (__device__ globals; no allocs) ----------------
__device__ float g_X  [BT*Cn];
__device__ float g_HS [BT*Cn];
__device__ float g_R  [BT*Cn];
__device__ float g_K  [BT*Cn];
__device__ float g_V  [BT*Cn];
__device__ float g_ST [BT*Cn];
__device__ float g_H  [BT*Cn];
__device__ float g_SC [BT];
__device__ float g_PART[Bsz*CH*Cn];
__device__ int   g_CNT[En];
__device__ int   g_LIST[En*BT];

// bf16 triples (Markidis 3-way splits)
__device__ __nv_bfloat16 g_MX1[BT*Cn], g_MX2[BT*Cn], g_MX3[BT*Cn];     // mix, then rs
__device__ __nv_bfloat16 g_HB1[BT*Cn], g_HB2[BT*Cn], g_HB3[BT*Cn];     // h (ln2 / lnf)
__device__ __nv_bfloat16 g_HZ1[BT*2*Cn], g_HZ2[BT*2*Cn], g_HZ3[BT*2*Cn];
__device__ __nv_bfloat16 g_HD1[(size_t)BT*Hn], g_HD2[(size_t)BT*Hn], g_HD3[(size_t)BT*Hn];
__device__ __nv_bfloat16 g_WT1[WTOT], g_WT2[WTOT], g_WT3[WTOT];        // transposed weight splits

// ---------------- helpers ----------------
__device__ __forceinline__ void split3(float v, __nv_bfloat16& b1, __nv_bfloat16& b2, __nv_bfloat16& b3) {
    b1 = __float2bfloat16_rn(v);
    float r = v - __bfloat162float(b1);
    b2 = __float2bfloat16_rn(r);
    float r2 = r - __bfloat162float(b2);
    b3 = __float2bfloat16_rn(r2);
}

__device__ __forceinline__ uint32_t smem_u32(const void* p) {
    uint32_t a;
    asm("{ .reg .u64 t; cvta.to.shared.u64 t, %1; cvt.u32.u64 %0, t; }" : "=r"(a) : "l"(p));
    return a;
}

#define CP16(dst, src) asm volatile("cp.async.cg.shared.global [%0], [%1], 16;" :: "r"(dst), "l"(src) : "memory")
#define CP_COMMIT()    asm volatile("cp.async.commit_group;" ::: "memory")
#define CP_WAIT1()     asm volatile("cp.async.wait_group 1;" ::: "memory")
#define CP_WAIT0()     asm volatile("cp.async.wait_group 0;" ::: "memory")

#define LDSM4(r, a) \
    asm volatile("ldmatrix.sync.aligned.m8n8.x4.shared.b16 {%0,%1,%2,%3}, [%4];" \
        : "=r"((r)[0]), "=r"((r)[1]), "=r"((r)[2]), "=r"((r)[3]) : "r"(a))

#define MMA16816(d, a, b0v, b1v) \
    asm volatile("mma.sync.aligned.m16n8k16.row.col.f32.bf16.bf16.f32 " \
        "{%0,%1,%2,%3}, {%4,%5,%6,%7}, {%8,%9}, {%0,%1,%2,%3};" \
        : "+f"((d)[0]), "+f"((d)[1]), "+f"((d)[2]), "+f"((d)[3]) \
        : "r"((a)[0]), "r"((a)[1]), "r"((a)[2]), "r"((a)[3]), "r"(b0v), "r"(b1v))

// ---------------- embedding gather ----------------
__global__ void embed_k(const int* __restrict__ idx, const float* __restrict__ emb) {
    int i = blockIdx.x*blockDim.x + threadIdx.x;
    if (i >= BT*Cn) return;
    int row = i >> 10, c = i & 1023;
    g_X[i] = emb[(size_t)idx[row]*Cn + c];
}

// ---------------- LayerNorm; optional bf16 triple emission ----------------
template<bool TRIP>
__global__ void ln_k(const float* __restrict__ in, const float* __restrict__ g,
                     const float* __restrict__ b, float* __restrict__ out,
                     __nv_bfloat16* o1, __nv_bfloat16* o2, __nv_bfloat16* o3) {
    int row = blockIdx.x;
    const float* p = in + (size_t)row*Cn;
    float v[4];
    float s = 0.f, ss = 0.f;
#pragma unroll
    for (int j = 0; j < 4; j++) {
        v[j] = p[threadIdx.x + j*256];
        s  += v[j];
        ss += v[j]*v[j];
    }
#pragma unroll
    for (int o = 16; o > 0; o >>= 1) {
        s  += __shfl_xor_sync(0xffffffffu, s,  o);
        ss += __shfl_xor_sync(0xffffffffu, ss, o);
    }
    __shared__ float sh[2][8];
    int w = threadIdx.x >> 5;
    if ((threadIdx.x & 31) == 0) { sh[0][w] = s; sh[1][w] = ss; }
    __syncthreads();
    s = 0.f; ss = 0.f;
#pragma unroll
    for (int j = 0; j < 8; j++) { s += sh[0][j]; ss += sh[1][j]; }
    float mean = s * (1.f/Cn);
    float var  = ss * (1.f/Cn) - mean*mean;
    float rstd = rsqrtf(var + 1e-5f);
    float* o = out + (size_t)row*Cn;
#pragma unroll
    for (int j = 0; j < 4; j++) {
        int c = threadIdx.x + j*256;
        float val = (v[j]-mean)*rstd*g[c] + b[c];
        o[c] = val;
        if (TRIP) {
            size_t id = (size_t)row*Cn + c;
            split3(val, o1[id], o2[id], o3[id]);
        }
    }
}

// ---------------- token-shift mix -> MX triple ----------------
__global__ void mix_k() {
    int i = blockIdx.x*blockDim.x + threadIdx.x;
    if (i >= BT*Cn) return;
    int t = (i >> 10) & (Tn - 1);
    float prev = t ? g_HS[i - Cn] : 0.f;
    float mix = 0.5f*(g_HS[i] + prev);
    split3(mix, g_MX1[i], g_MX2[i], g_MX3[i]);
}

// ---------------- 3-phase rwkv scan ----------------
__global__ void scan1_k() {
    int i = blockIdx.x*blockDim.x + threadIdx.x;
    if (i >= Bsz*CH*Cn) return;
    int c  = i & 1023;
    int ch = (i >> 10) & (CH - 1);
    int b  = i >> 14;
    size_t base = (size_t)b*Tn*Cn + (size_t)ch*CL*Cn + c;
    float s = 0.f;
#pragma unroll 4
    for (int t = 0; t < CL; t++) {
        size_t id = base + (size_t)t*Cn;
        s += g_K[id]*g_V[id];
    }
    g_PART[i] = s;
}
__global__ void scan2_k() {
    int i = blockIdx.x*blockDim.x + threadIdx.x;
    if (i >= Bsz*Cn) return;
    int c = i & 1023, b = i >> 10;
    float run = 0.f;
#pragma unroll
    for (int ch = 0; ch < CH; ch++) {
        int id = ((b*CH + ch) << 10) | c;
        float p = g_PART[id];
        g_PART[id] = run;
        run += p;
    }
}
__global__ void scan3_k() {  // writes ST fp32 and RS triple into MX
    int i = blockIdx.x*blockDim.x + threadIdx.x;
    if (i >= Bsz*CH*Cn) return;
    int c  = i & 1023;
    int ch = (i >> 10) & (CH - 1);
    int b  = i >> 14;
    size_t base = (size_t)b*Tn*Cn + (size_t)ch*CL*Cn + c;
    float acc = g_PART[i];
    int t0 = ch*CL;
#pragma unroll 4
    for (int t = 0; t < CL; t++) {
        size_t id = base + (size_t)t*Cn;
        acc += g_K[id]*g_V[id];
        float st = acc / (float)(t0 + t + 1);
        g_ST[id] = st;
        float rs = g_R[id]*st;
        split3(rs, g_MX1[id], g_MX2[id], g_MX3[id]);
    }
}

// ---------------- routing (exact fp32) ----------------
__global__ void zcnt_k() { if (threadIdx.x < En) g_CNT[threadIdx.x] = 0; }

__global__ void route_k(const float* __restrict__ wc, const float* __restrict__ wa,
                        const float* __restrict__ shp) {
    int bt = blockIdx.x;
    const float* hp = g_H + (size_t)bt*Cn;
    float p[6] = {0,0,0,0,0,0};
    for (int c = threadIdx.x; c < Cn; c += 128) {
        float hv = hp[c];
        p[0] += hv*wc[c];
        p[1] += hv*wc[Cn + c];
        p[2] += hv*wc[2*Cn + c];
        p[3] += hv*wa[c*En + 0];
        p[4] += hv*wa[c*En + 1];
        p[5] += hv*wa[c*En + 2];
    }
#pragma unroll
    for (int o = 16; o > 0; o >>= 1)
#pragma unroll
        for (int q = 0; q < 6; q++) p[q] += __shfl_xor_sync(0xffffffffu, p[q], o);
    __shared__ float sm[4][6];
    int w = threadIdx.x >> 5;
    if ((threadIdx.x & 31) == 0)
#pragma unroll
        for (int q = 0; q < 6; q++) sm[w][q] = p[q];
    __syncthreads();
    if (threadIdx.x == 0) {
        float d[6];
#pragma unroll
        for (int q = 0; q < 6; q++) d[q] = sm[0][q] + sm[1][q] + sm[2][q] + sm[3][q];
        float best = -3.4e38f, wcf = 0.f;
        int wi = 0;
#pragma unroll
        for (int e = 0; e < En; e++) {
            float conf = 1.f/(1.f + expf(-d[e]));
            float bid  = conf*shp[e] + d[3+e];
            if (bid > best) { best = bid; wi = e; wcf = conf; }
        }
        g_SC[bt] = wcf / (wcf + 1e-6f);
        int pos = atomicAdd(&g_CNT[wi], 1);
        g_LIST[wi*BT + pos] = bt;
    }
}

// ---------------- hz = concat(h, state) -> triple ----------------
__global__ void hz_k() {
    int i = blockIdx.x*blockDim.x + threadIdx.x;
    if (i >= BT*2*Cn) return;
    int row = i >> 11;
    int c = i & (2*Cn - 1);
    float v = (c < Cn) ? g_H[(size_t)row*Cn + c] : g_ST[(size_t)row*Cn + c - Cn];
    split3(v, g_HZ1[i], g_HZ2[i], g_HZ3[i]);
}

// ---------------- weight transpose + split: W[K,N] fp32 -> Wt[N,K] bf16 x3 ----------------
__global__ void tsplit_k(const float* __restrict__ W,
                         __nv_bfloat16* __restrict__ o1, __nv_bfloat16* __restrict__ o2,
                         __nv_bfloat16* __restrict__ o3, int K, int N) {
    __shared__ __nv_bfloat16 s1[32][33], s2[32][33], s3[32][33];
    int n0 = blockIdx.x*32, k0 = blockIdx.y*32;
    int tx = threadIdx.x, ty = threadIdx.y;
#pragma unroll
    for (int j = 0; j < 4; j++) {
        int k = k0 + ty + j*8;
        float v = W[(size_t)k*N + n0 + tx];
        split3(v, s1[ty+j*8][tx], s2[ty+j*8][tx], s3[ty+j*8][tx]);
    }
    __syncthreads();
#pragma unroll
    for (int j = 0; j < 4; j++) {
        int n = n0 + ty + j*8;
        size_t o = (size_t)n*K + k0 + tx;
        o1[o] = s1[tx][ty+j*8];
        o2[o] = s2[tx][ty+j*8];
        o3[o] = s3[tx][ty+j*8];
    }
}

// ---------------- HMMA split-bf16 GEMM: 128x128 tile, 8 warps (4m x 2n), KC=64 double-buffered
// MODE 0: C=acc   1: C=sigmoid(acc)   2: C+=acc   3: relu->bf16 triple   4: scatter X[tok]+=acc*scal
// NPROD: 6 = full 3-way split products; 3 = {11,12,21}
template<int MODE, int NPROD>
__global__ void __launch_bounds__(256) gemm_mma(
    const __nv_bfloat16* __restrict__ A1, const __nv_bfloat16* __restrict__ A2, const __nv_bfloat16* __restrict__ A3,
    const __nv_bfloat16* __restrict__ B1, const __nv_bfloat16* __restrict__ B2, const __nv_bfloat16* __restrict__ B3,
    float* __restrict__ Cf, __nv_bfloat16* __restrict__ D1, __nv_bfloat16* __restrict__ D2, __nv_bfloat16* __restrict__ D3,
    int K, int N,
    const int* __restrict__ rows, const int* __restrict__ cntp,
    const float* __restrict__ scal, int gatherA)
{
    int Meff = cntp ? *cntp : BT;
    int m0 = blockIdx.y * 128;
    if (m0 >= Meff) return;

    extern __shared__ char smem[];
    uint32_t sbase = smem_u32(smem);

    int tid = threadIdx.x, lane = tid & 31, wid = tid >> 5;
    int wm = wid & 3, wn = wid >> 2;

    // ---- gmem -> smem assignment: 2 threads/row, 64B (4x16B) each ----
    int arow = tid >> 1, half = tid & 1;
    int am = m0 + arow;
    int amc = (am < Meff) ? am : (Meff - 1);
    long ga = gatherA ? rows[amc] : amc;
    const __nv_bfloat16* asrc[3] = {A1 + (size_t)ga*K + half*32,
                                    A2 + (size_t)ga*K + half*32,
                                    A3 + (size_t)ga*K + half*32};
    size_t bro = (size_t)(blockIdx.x*128 + arow)*K + half*32;
    const __nv_bfloat16* bsrc[3] = {B1 + bro, B2 + bro, B3 + bro};

    uint32_t so[4];
#pragma unroll
    for (int q = 0; q < 4; q++) {
        uint32_t o = arow*128 + half*64 + q*16;
        so[q] = o ^ ((o >> 3) & 0x70);
    }

    float acc[2][8][4];
#pragma unroll
    for (int i = 0; i < 2; i++)
#pragma unroll
        for (int j = 0; j < 8; j++)
#pragma unroll
            for (int q = 0; q < 4; q++) acc[i][j][q] = 0.f;

    const int pa[6] = {0,0,1,0,2,1};
    const int pb[6] = {0,1,0,2,0,1};
    int nc = K / KC;

    // ---- pipeline ----
    // load stage c into buffer c&1
    {
        uint32_t sb = sbase;
#pragma unroll
        for (int t = 0; t < 6; t++) {
            const __nv_bfloat16* src = (t < 3) ? asrc[t] : bsrc[t-3];
#pragma unroll
            for (int q = 0; q < 4; q++)
                CP16(sb + t*TILE_B + so[q], src + q*8);
        }
        CP_COMMIT();
    }

    for (int c = 0; c < nc; c++) {
        if (c + 1 < nc) {
            uint32_t sb = sbase + ((c+1) & 1)*STAGE_B;
            size_t kel = (size_t)(c+1)*KC;
#pragma unroll
            for (int t = 0; t < 6; t++) {
                const __nv_bfloat16* src = ((t < 3) ? asrc[t] : bsrc[t-3]) + kel;
#pragma unroll
                for (int q = 0; q < 4; q++)
                    CP16(sb + t*TILE_B + so[q], src + q*8);
            }
            CP_COMMIT();
            CP_WAIT1();
        } else {
            CP_WAIT0();
        }
        __syncthreads();

        uint32_t stg = sbase + (c & 1)*STAGE_B;
#pragma unroll
        for (int p = 0; p < NPROD; p++) {
            uint32_t abase = stg + pa[p]*TILE_B;
            uint32_t bbase = stg + (3 + pb[p])*TILE_B;
#pragma unroll
            for (int ks = 0; ks < 4; ks++) {
                uint32_t afr[2][4];
#pragma unroll
                for (int mf = 0; mf < 2; mf++) {
                    uint32_t r  = wm*32 + mf*16 + (lane & 7) + ((lane & 8) ? 8 : 0);
                    uint32_t of = ks*32 + ((lane & 16) ? 16 : 0);
                    uint32_t bo = r*128 + of;
                    bo ^= (bo >> 3) & 0x70;
                    LDSM4(afr[mf], abase + bo);
                }
                uint32_t bfr[4][4];
#pragma unroll
                for (int nq = 0; nq < 4; nq++) {
                    uint32_t r  = wn*64 + nq*16 + (lane & 7) + ((lane & 16) ? 8 : 0);
                    uint32_t of = ks*32 + ((lane & 8) ? 16 : 0);
                    uint32_t bo = r*128 + of;
                    bo ^= (bo >> 3) & 0x70;
                    LDSM4(bfr[nq], bbase + bo);
                }
#pragma unroll
                for (int mf = 0; mf < 2; mf++)
#pragma unroll
                    for (int nf = 0; nf < 8; nf++)
                        MMA16816(acc[mf][nf], afr[mf], bfr[nf>>1][(nf&1)*2], bfr[nf>>1][(nf&1)*2 + 1]);
            }
        }
        __syncthreads();
    }

    // ---- epilogue ----
    int cbase = blockIdx.x*128 + wn*64;
#pragma unroll
    for (int mf = 0; mf < 2; mf++) {
        int r0 = m0 + wm*32 + mf*16 + (lane >> 2);
#pragma unroll
        for (int nf = 0; nf < 8; nf++) {
            int cc = cbase + nf*8 + (lane & 3)*2;
#pragma unroll
            for (int h = 0; h < 2; h++) {
                int r = r0 + h*8;
                if (r >= Meff) continue;
                float v0 = acc[mf][nf][h*2], v1 = acc[mf][nf][h*2 + 1];
                if (MODE == 4) {
                    int tok = rows[r];
                    float sc = scal[tok];
                    float* xr = Cf + (size_t)tok*N + cc;
                    xr[0] += v0*sc;
                    xr[1] += v1*sc;
                } else if (MODE == 3) {
                    size_t o = (size_t)r*N + cc;
                    v0 = fmaxf(v0, 0.f);
                    v1 = fmaxf(v1, 0.f);
                    split3(v0, D1[o],   D2[o],   D3[o]);
                    split3(v1, D1[o+1], D2[o+1], D3[o+1]);
                } else {
                    float* cr = Cf + (size_t)r*N + cc;
                    if (MODE == 1) {
                        cr[0] = 1.f/(1.f + expf(-v0));
                        cr[1] = 1.f/(1.f + expf(-v1));
                    } else if (MODE == 2) {
                        cr[0] += v0;
                        cr[1] += v1;
                    } else {
                        cr[0] = v0;
                        cr[1] = v1;
                    }
                }
            }
        }
    }
}

// ---------------- launch ----------------
extern "C" void kernel_launch(void* const* d_in, const int* in_sizes, int n_in,
                              void* d_out, int out_size)
{
    const int*   idx   = (const int*)  d_in[0];
    const float* shares= (const float*)d_in[1];
    const float* emb   = (const float*)d_in[2];
    const float* ln1g  = (const float*)d_in[3];
    const float* ln1b  = (const float*)d_in[4];
    const float* ln2g  = (const float*)d_in[5];
    const float* ln2b  = (const float*)d_in[6];
    const float* Wr    = (const float*)d_in[7];
    const float* Wk    = (const float*)d_in[8];
    const float* Wv    = (const float*)d_in[9];
    const float* Wo    = (const float*)d_in[10];
    const float* W1    = (const float*)d_in[11];
    const float* W2    = (const float*)d_in[12];
    const float* wconf = (const float*)d_in[13];
    const float* Wl1   = (const float*)d_in[14];
    const float* Wl2   = (const float*)d_in[15];
    const float* Waff  = (const float*)d_in[17];
    const float* lnfg  = (const float*)d_in[18];
    const float* lnfb  = (const float*)d_in[19];
    const float* headW = (const float*)d_in[20];
    float* out = (float*)d_out;
    (void)in_sizes; (void)n_in; (void)out_size;

    float *X, *Hh, *SC;
    int *CNT, *LIST;
    float *Rb, *Kb, *Vb;
    __nv_bfloat16 *MX1,*MX2,*MX3, *HB1,*HB2,*HB3, *HZ1,*HZ2,*HZ3, *HD1,*HD2,*HD3, *WT1,*WT2,*WT3;
    cudaGetSymbolAddress((void**)&X,   g_X);
    cudaGetSymbolAddress((void**)&Rb,  g_R);
    cudaGetSymbolAddress((void**)&Kb,  g_K);
    cudaGetSymbolAddress((void**)&Vb,  g_V);
    cudaGetSymbolAddress((void**)&Hh,  g_H);
    cudaGetSymbolAddress((void**)&SC,  g_SC);
    cudaGetSymbolAddress((void**)&CNT, g_CNT);
    cudaGetSymbolAddress((void**)&LIST,g_LIST);
    float* HS; cudaGetSymbolAddress((void**)&HS, g_HS);
    cudaGetSymbolAddress((void**)&MX1, g_MX1); cudaGetSymbolAddress((void**)&MX2, g_MX2); cudaGetSymbolAddress((void**)&MX3, g_MX3);
    cudaGetSymbolAddress((void**)&HB1, g_HB1); cudaGetSymbolAddress((void**)&HB2, g_HB2); cudaGetSymbolAddress((void**)&HB3, g_HB3);
    cudaGetSymbolAddress((void**)&HZ1, g_HZ1); cudaGetSymbolAddress((void**)&HZ2, g_HZ2); cudaGetSymbolAddress((void**)&HZ3, g_HZ3);
    cudaGetSymbolAddress((void**)&HD1, g_HD1); cudaGetSymbolAddress((void**)&HD2, g_HD2); cudaGetSymbolAddress((void**)&HD3, g_HD3);
    cudaGetSymbolAddress((void**)&WT1, g_WT1); cudaGetSymbolAddress((void**)&WT2, g_WT2); cudaGetSymbolAddress((void**)&WT3, g_WT3);

    cudaFuncSetAttribute(gemm_mma<0,6>, cudaFuncAttributeMaxDynamicSharedMemorySize, SMEMB);
    cudaFuncSetAttribute(gemm_mma<1,6>, cudaFuncAttributeMaxDynamicSharedMemorySize, SMEMB);
    cudaFuncSetAttribute(gemm_mma<2,6>, cudaFuncAttributeMaxDynamicSharedMemorySize, SMEMB);
    cudaFuncSetAttribute(gemm_mma<3,6>, cudaFuncAttributeMaxDynamicSharedMemorySize, SMEMB);
    cudaFuncSetAttribute(gemm_mma<4,6>, cudaFuncAttributeMaxDynamicSharedMemorySize, SMEMB);
    cudaFuncSetAttribute(gemm_mma<0,3>, cudaFuncAttributeMaxDynamicSharedMemorySize, SMEMB);

    dim3 tb(32, 8);
    // weight arena layout per layer (elems): Wr@0 Wk@CC Wv@2CC Wo@3CC | W1e0@4CC W1e1@8CC |
    // W2e0@12CC W2e1@16CC | Wl1@20CC Wl2@28CC
    for (int l = 0; l < Ln; l++) {
        size_t LB = (size_t)l*WPL;
        tsplit_k<<<dim3(Cn/32, Cn/32), tb>>>(Wr + (size_t)l*CC, WT1+LB,        WT2+LB,        WT3+LB,        Cn, Cn);
        tsplit_k<<<dim3(Cn/32, Cn/32), tb>>>(Wk + (size_t)l*CC, WT1+LB+CC,     WT2+LB+CC,     WT3+LB+CC,     Cn, Cn);
        tsplit_k<<<dim3(Cn/32, Cn/32), tb>>>(Wv + (size_t)l*CC, WT1+LB+2*(size_t)CC, WT2+LB+2*(size_t)CC, WT3+LB+2*(size_t)CC, Cn, Cn);
        tsplit_k<<<dim3(Cn/32, Cn/32), tb>>>(Wo + (size_t)l*CC, WT1+LB+3*(size_t)CC, WT2+LB+3*(size_t)CC, WT3+LB+3*(size_t)CC, Cn, Cn);
        for (int e = 0; e < 2; e++) {
            size_t o1 = LB + (4 + 4*e)*(size_t)CC;
            tsplit_k<<<dim3(Hn/32, Cn/32), tb>>>(W1 + ((size_t)l*2 + e)*Cn*Hn, WT1+o1, WT2+o1, WT3+o1, Cn, Hn);
            size_t o2 = LB + (12 + 4*e)*(size_t)CC;
            tsplit_k<<<dim3(Cn/32, Hn/32), tb>>>(W2 + ((size_t)l*2 + e)*Hn*Cn, WT1+o2, WT2+o2, WT3+o2, Hn, Cn);
        }
        size_t ol1 = LB + 20*(size_t)CC;
        tsplit_k<<<dim3(Hn/32, 2*Cn/32), tb>>>(Wl1 + (size_t)l*2*Cn*Hn, WT1+ol1, WT2+ol1, WT3+ol1, 2*Cn, Hn);
        size_t ol2 = LB + 28*(size_t)CC;
        tsplit_k<<<dim3(Cn/32, Hn/32), tb>>>(Wl2 + (size_t)l*Hn*Cn, WT1+ol2, WT2+ol2, WT3+ol2, Hn, Cn);
    }
    tsplit_k<<<dim3(Vn/32, Cn/32), tb>>>(headW, WT1+WHEAD, WT2+WHEAD, WT3+WHEAD, Cn, Vn);

    embed_k<<<(BT*Cn)/256, 256>>>(idx, emb);

    dim3 gC(Cn/128, BT/128);
    dim3 gH(Hn/128, BT/128);

    for (int l = 0; l < Ln; l++) {
        size_t LB = (size_t)l*WPL;
        ln_k<false><<<BT, 256>>>(X, ln1g + (size_t)l*Cn, ln1b + (size_t)l*Cn, HS, nullptr, nullptr, nullptr);
        mix_k<<<(BT*Cn)/256, 256>>>();

        gemm_mma<1,6><<<gC, 256, SMEMB>>>(MX1,MX2,MX3, WT1+LB,WT2+LB,WT3+LB, Rb, nullptr,nullptr,nullptr, Cn, Cn, nullptr,nullptr,nullptr,0);
        gemm_mma<0,6><<<gC, 256, SMEMB>>>(MX1,MX2,MX3, WT1+LB+CC,WT2+LB+CC,WT3+LB+CC, Kb, nullptr,nullptr,nullptr, Cn, Cn, nullptr,nullptr,nullptr,0);
        gemm_mma<0,6><<<gC, 256, SMEMB>>>(MX1,MX2,MX3, WT1+LB+2*(size_t)CC,WT2+LB+2*(size_t)CC,WT3+LB+2*(size_t)CC, Vb, nullptr,nullptr,nullptr, Cn, Cn, nullptr,nullptr,nullptr,0);

        scan1_k<<<(Bsz*CH*Cn)/256, 256>>>();
        scan2_k<<<(Bsz*Cn)/256, 256>>>();
        scan3_k<<<(Bsz*CH*Cn)/256, 256>>>();

        gemm_mma<2,6><<<gC, 256, SMEMB>>>(MX1,MX2,MX3, WT1+LB+3*(size_t)CC,WT2+LB+3*(size_t)CC,WT3+LB+3*(size_t)CC, X, nullptr,nullptr,nullptr, Cn, Cn, nullptr,nullptr,nullptr,0);

        ln_k<true><<<BT, 256>>>(X, ln2g + (size_t)l*Cn, ln2b + (size_t)l*Cn, Hh, HB1, HB2, HB3);

        zcnt_k<<<1, 32>>>();
        route_k<<<BT, 128>>>(wconf + (size_t)l*En*Cn, Waff + (size_t)l*Cn*En, shares + (size_t)l*En);
        hz_k<<<(BT*2*Cn)/256, 256>>>();

        for (int e = 0; e < 2; e++) {
            size_t o1 = LB + (4 + 4*e)*(size_t)CC;
            size_t o2 = LB + (12 + 4*e)*(size_t)CC;
            gemm_mma<3,6><<<gH, 256, SMEMB>>>(HB1,HB2,HB3, WT1+o1,WT2+o1,WT3+o1, nullptr, HD1,HD2,HD3, Cn, Hn, LIST + e*BT, CNT + e, nullptr, 1);
            gemm_mma<4,6><<<gC, 256, SMEMB>>>(HD1,HD2,HD3, WT1+o2,WT2+o2,WT3+o2, X, nullptr,nullptr,nullptr, Hn, Cn, LIST + e*BT, CNT + e, SC, 0);
        }
        size_t ol1 = LB + 20*(size_t)CC, ol2 = LB + 28*(size_t)CC;
        gemm_mma<3,6><<<gH, 256, SMEMB>>>(HZ1,HZ2,HZ3, WT1+ol1,WT2+ol1,WT3+ol1, nullptr, HD1,HD2,HD3, 2*Cn, Hn, LIST + 2*BT, CNT + 2, nullptr, 1);
        gemm_mma<4,6><<<gC, 256, SMEMB>>>(HD1,HD2,HD3, WT1+ol2,WT2+ol2,WT3+ol2, X, nullptr,nullptr,nullptr, Hn, Cn, LIST + 2*BT, CNT + 2, SC, 0);
    }

    ln_k<true><<<BT, 256>>>(X, lnfg, lnfb, Hh, HB1, HB2, HB3);
    gemm_mma<0,3><<<dim3(Vn/128, BT/128), 256, SMEMB>>>(HB1,HB2,HB3, WT1+WHEAD,WT2+WHEAD,WT3+WHEAD, out, nullptr,nullptr,nullptr, Cn, Vn, nullptr,nullptr,nullptr,0);
}

// round 7
// speedup vs baseline: 1.8442x; 1.1250x over previous
#include <cuda_runtime.h>
#include <cuda_bf16.h>
#include <math.h>
#include <stdint.h>

// ---------------- dims ----------------
#define Bsz 2
#define Tn  2048
#define Cn  1024
#define Vn  32000
#define Ln  4
#define En  3
#define Hn  4096
#define BT  (Bsz*Tn)   // 4096 tokens
#define CH  16         // scan chunks
#define CL  (Tn/CH)
#define KC  32         // GEMM K-chunk (bf16 elems)

#define CC  (Cn*Cn)                     // 1,048,576
#define WPL (32*CC)                     // weights per layer (elems)
#define WHEAD ((size_t)4*WPL)           // head base
#define WTOT  ((size_t)4*WPL + (size_t)Cn*Vn)

// smem: 2 stages x 6 tiles x (128 x 32 bf16 = 8KB)
#define TILE_B 8192
#define STAGE_B (6*TILE_B)
#define SMEMB (2*STAGE_B)               // 98304 -> 2 CTAs/SM

// ---------------- scratch (__device__ globals; no allocs) ----------------
__device__ float g_X  [BT*Cn];
__device__ float g_HS [BT*Cn];
__device__ float g_R  [BT*Cn];
__device__ float g_K  [BT*Cn];
__device__ float g_V  [BT*Cn];
__device__ float g_ST [BT*Cn];
__device__ float g_H  [BT*Cn];
__device__ float g_SC [BT];
__device__ float g_PART[Bsz*CH*Cn];
__device__ int   g_CNT[En];
__device__ int   g_LIST[En*BT];

// bf16 triples (Markidis 3-way splits)
__device__ __nv_bfloat16 g_MX1[BT*Cn], g_MX2[BT*Cn], g_MX3[BT*Cn];     // mix, then rs
__device__ __nv_bfloat16 g_HB1[BT*Cn], g_HB2[BT*Cn], g_HB3[BT*Cn];     // h (ln2 / lnf)
__device__ __nv_bfloat16 g_HZ1[BT*2*Cn], g_HZ2[BT*2*Cn], g_HZ3[BT*2*Cn];
__device__ __nv_bfloat16 g_HD1[(size_t)BT*Hn], g_HD2[(size_t)BT*Hn], g_HD3[(size_t)BT*Hn];
__device__ __nv_bfloat16 g_WT1[WTOT], g_WT2[WTOT], g_WT3[WTOT];        // transposed weight splits

// ---------------- helpers ----------------
__device__ __forceinline__ void split3(float v, __nv_bfloat16& b1, __nv_bfloat16& b2, __nv_bfloat16& b3) {
    b1 = __float2bfloat16_rn(v);
    float r = v - __bfloat162float(b1);
    b2 = __float2bfloat16_rn(r);
    float r2 = r - __bfloat162float(b2);
    b3 = __float2bfloat16_rn(r2);
}

__device__ __forceinline__ uint32_t smem_u32(const void* p) {
    uint32_t a;
    asm("{ .reg .u64 t; cvta.to.shared.u64 t, %1; cvt.u32.u64 %0, t; }" : "=r"(a) : "l"(p));
    return a;
}

#define CP16(dst, src) asm volatile("cp.async.cg.shared.global [%0], [%1], 16;" :: "r"(dst), "l"(src) : "memory")
#define CP_COMMIT()    asm volatile("cp.async.commit_group;" ::: "memory")
#define CP_WAIT1()     asm volatile("cp.async.wait_group 1;" ::: "memory")
#define CP_WAIT0()     asm volatile("cp.async.wait_group 0;" ::: "memory")

#define LDSM4(r, a) \
    asm volatile("ldmatrix.sync.aligned.m8n8.x4.shared.b16 {%0,%1,%2,%3}, [%4];" \
        : "=r"((r)[0]), "=r"((r)[1]), "=r"((r)[2]), "=r"((r)[3]) : "r"(a))

#define MMA16816(d, a, b0v, b1v) \
    asm volatile("mma.sync.aligned.m16n8k16.row.col.f32.bf16.bf16.f32 " \
        "{%0,%1,%2,%3}, {%4,%5,%6,%7}, {%8,%9}, {%0,%1,%2,%3};" \
        : "+f"((d)[0]), "+f"((d)[1]), "+f"((d)[2]), "+f"((d)[3]) \
        : "r"((a)[0]), "r"((a)[1]), "r"((a)[2]), "r"((a)[3]), "r"(b0v), "r"(b1v))

// swizzle for 64B-pitch rows: XOR 16B-column bits [4:6) with row bits [6:8)
__device__ __forceinline__ uint32_t sw64(uint32_t o) { return o ^ ((o >> 2) & 0x30); }

// ---------------- embedding gather ----------------
__global__ void embed_k(const int* __restrict__ idx, const float* __restrict__ emb) {
    int i = blockIdx.x*blockDim.x + threadIdx.x;
    if (i >= BT*Cn) return;
    int row = i >> 10, c = i & 1023;
    g_X[i] = emb[(size_t)idx[row]*Cn + c];
}

// ---------------- LayerNorm; optional bf16 triple emission ----------------
template<bool TRIP>
__global__ void ln_k(const float* __restrict__ in, const float* __restrict__ g,
                     const float* __restrict__ b, float* __restrict__ out,
                     __nv_bfloat16* o1, __nv_bfloat16* o2, __nv_bfloat16* o3) {
    int row = blockIdx.x;
    const float* p = in + (size_t)row*Cn;
    float v[4];
    float s = 0.f, ss = 0.f;
#pragma unroll
    for (int j = 0; j < 4; j++) {
        v[j] = p[threadIdx.x + j*256];
        s  += v[j];
        ss += v[j]*v[j];
    }
#pragma unroll
    for (int o = 16; o > 0; o >>= 1) {
        s  += __shfl_xor_sync(0xffffffffu, s,  o);
        ss += __shfl_xor_sync(0xffffffffu, ss, o);
    }
    __shared__ float sh[2][8];
    int w = threadIdx.x >> 5;
    if ((threadIdx.x & 31) == 0) { sh[0][w] = s; sh[1][w] = ss; }
    __syncthreads();
    s = 0.f; ss = 0.f;
#pragma unroll
    for (int j = 0; j < 8; j++) { s += sh[0][j]; ss += sh[1][j]; }
    float mean = s * (1.f/Cn);
    float var  = ss * (1.f/Cn) - mean*mean;
    float rstd = rsqrtf(var + 1e-5f);
    float* o = out + (size_t)row*Cn;
#pragma unroll
    for (int j = 0; j < 4; j++) {
        int c = threadIdx.x + j*256;
        float val = (v[j]-mean)*rstd*g[c] + b[c];
        o[c] = val;
        if (TRIP) {
            size_t id = (size_t)row*Cn + c;
            split3(val, o1[id], o2[id], o3[id]);
        }
    }
}

// ---------------- token-shift mix -> MX triple ----------------
__global__ void mix_k() {
    int i = blockIdx.x*blockDim.x + threadIdx.x;
    if (i >= BT*Cn) return;
    int t = (i >> 10) & (Tn - 1);
    float prev = t ? g_HS[i - Cn] : 0.f;
    float mix = 0.5f*(g_HS[i] + prev);
    split3(mix, g_MX1[i], g_MX2[i], g_MX3[i]);
}

// ---------------- 3-phase rwkv scan ----------------
__global__ void scan1_k() {
    int i = blockIdx.x*blockDim.x + threadIdx.x;
    if (i >= Bsz*CH*Cn) return;
    int c  = i & 1023;
    int ch = (i >> 10) & (CH - 1);
    int b  = i >> 14;
    size_t base = (size_t)b*Tn*Cn + (size_t)ch*CL*Cn + c;
    float s = 0.f;
#pragma unroll 4
    for (int t = 0; t < CL; t++) {
        size_t id = base + (size_t)t*Cn;
        s += g_K[id]*g_V[id];
    }
    g_PART[i] = s;
}
__global__ void scan2_k() {
    int i = blockIdx.x*blockDim.x + threadIdx.x;
    if (i >= Bsz*Cn) return;
    int c = i & 1023, b = i >> 10;
    float run = 0.f;
#pragma unroll
    for (int ch = 0; ch < CH; ch++) {
        int id = ((b*CH + ch) << 10) | c;
        float p = g_PART[id];
        g_PART[id] = run;
        run += p;
    }
}
__global__ void scan3_k() {  // writes ST fp32 and RS triple into MX
    int i = blockIdx.x*blockDim.x + threadIdx.x;
    if (i >= Bsz*CH*Cn) return;
    int c  = i & 1023;
    int ch = (i >> 10) & (CH - 1);
    int b  = i >> 14;
    size_t base = (size_t)b*Tn*Cn + (size_t)ch*CL*Cn + c;
    float acc = g_PART[i];
    int t0 = ch*CL;
#pragma unroll 4
    for (int t = 0; t < CL; t++) {
        size_t id = base + (size_t)t*Cn;
        acc += g_K[id]*g_V[id];
        float st = acc / (float)(t0 + t + 1);
        g_ST[id] = st;
        float rs = g_R[id]*st;
        split3(rs, g_MX1[id], g_MX2[id], g_MX3[id]);
    }
}

// ---------------- routing (exact fp32) ----------------
__global__ void zcnt_k() { if (threadIdx.x < En) g_CNT[threadIdx.x] = 0; }

__global__ void route_k(const float* __restrict__ wc, const float* __restrict__ wa,
                        const float* __restrict__ shp) {
    int bt = blockIdx.x;
    const float* hp = g_H + (size_t)bt*Cn;
    float p[6] = {0,0,0,0,0,0};
    for (int c = threadIdx.x; c < Cn; c += 128) {
        float hv = hp[c];
        p[0] += hv*wc[c];
        p[1] += hv*wc[Cn + c];
        p[2] += hv*wc[2*Cn + c];
        p[3] += hv*wa[c*En + 0];
        p[4] += hv*wa[c*En + 1];
        p[5] += hv*wa[c*En + 2];
    }
#pragma unroll
    for (int o = 16; o > 0; o >>= 1)
#pragma unroll
        for (int q = 0; q < 6; q++) p[q] += __shfl_xor_sync(0xffffffffu, p[q], o);
    __shared__ float sm[4][6];
    int w = threadIdx.x >> 5;
    if ((threadIdx.x & 31) == 0)
#pragma unroll
        for (int q = 0; q < 6; q++) sm[w][q] = p[q];
    __syncthreads();
    if (threadIdx.x == 0) {
        float d[6];
#pragma unroll
        for (int q = 0; q < 6; q++) d[q] = sm[0][q] + sm[1][q] + sm[2][q] + sm[3][q];
        float best = -3.4e38f, wcf = 0.f;
        int wi = 0;
#pragma unroll
        for (int e = 0; e < En; e++) {
            float conf = 1.f/(1.f + expf(-d[e]));
            float bid  = conf*shp[e] + d[3+e];
            if (bid > best) { best = bid; wi = e; wcf = conf; }
        }
        g_SC[bt] = wcf / (wcf + 1e-6f);
        int pos = atomicAdd(&g_CNT[wi], 1);
        g_LIST[wi*BT + pos] = bt;
    }
}

// ---------------- hz = concat(h, state) -> triple ----------------
__global__ void hz_k() {
    int i = blockIdx.x*blockDim.x + threadIdx.x;
    if (i >= BT*2*Cn) return;
    int row = i >> 11;
    int c = i & (2*Cn - 1);
    float v = (c < Cn) ? g_H[(size_t)row*Cn + c] : g_ST[(size_t)row*Cn + c - Cn];
    split3(v, g_HZ1[i], g_HZ2[i], g_HZ3[i]);
}

// ---------------- weight transpose + split: W[K,N] fp32 -> Wt[N,K] bf16 x3 ----------------
__global__ void tsplit_k(const float* __restrict__ W,
                         __nv_bfloat16* __restrict__ o1, __nv_bfloat16* __restrict__ o2,
                         __nv_bfloat16* __restrict__ o3, int K, int N) {
    __shared__ __nv_bfloat16 s1[32][33], s2[32][33], s3[32][33];
    int n0 = blockIdx.x*32, k0 = blockIdx.y*32;
    int tx = threadIdx.x, ty = threadIdx.y;
#pragma unroll
    for (int j = 0; j < 4; j++) {
        int k = k0 + ty + j*8;
        float v = W[(size_t)k*N + n0 + tx];
        split3(v, s1[ty+j*8][tx], s2[ty+j*8][tx], s3[ty+j*8][tx]);
    }
    __syncthreads();
#pragma unroll
    for (int j = 0; j < 4; j++) {
        int n = n0 + ty + j*8;
        size_t o = (size_t)n*K + k0 + tx;
        o1[o] = s1[tx][ty+j*8];
        o2[o] = s2[tx][ty+j*8];
        o3[o] = s3[tx][ty+j*8];
    }
}

// ---------------- HMMA split-bf16 GEMM: 128x128 tile, 8 warps (4m x 2n), KC=32, 2 CTA/SM
// MODE 0: C=acc   1: C=sigmoid(acc)   2: C+=acc   3: relu->bf16 triple   4: scatter X[tok]+=acc*scal
// NPROD: 6 = full 3-way split products; 3 = {11,12,21}
template<int MODE, int NPROD>
__global__ void __launch_bounds__(256, 2) gemm_mma(
    const __nv_bfloat16* __restrict__ A1, const __nv_bfloat16* __restrict__ A2, const __nv_bfloat16* __restrict__ A3,
    const __nv_bfloat16* __restrict__ B1, const __nv_bfloat16* __restrict__ B2, const __nv_bfloat16* __restrict__ B3,
    float* __restrict__ Cf, __nv_bfloat16* __restrict__ D1, __nv_bfloat16* __restrict__ D2, __nv_bfloat16* __restrict__ D3,
    int K, int N,
    const int* __restrict__ rows, const int* __restrict__ cntp,
    const float* __restrict__ scal, int gatherA)
{
    int Meff = cntp ? *cntp : BT;
    int m0 = blockIdx.y * 128;
    if (m0 >= Meff) return;

    extern __shared__ char smem[];
    uint32_t sbase = smem_u32(smem);

    int tid = threadIdx.x, lane = tid & 31, wid = tid >> 5;
    int wm = wid & 3, wn = wid >> 2;

    // ---- gmem -> smem assignment: 2 threads/row, 32B (2x16B) each ----
    int arow = tid >> 1, half = tid & 1;
    int am = m0 + arow;
    int amc = (am < Meff) ? am : (Meff - 1);
    long ga = gatherA ? rows[amc] : amc;
    const __nv_bfloat16* asrc[3] = {A1 + (size_t)ga*K + half*16,
                                    A2 + (size_t)ga*K + half*16,
                                    A3 + (size_t)ga*K + half*16};
    size_t bro = (size_t)(blockIdx.x*128 + arow)*K + half*16;
    const __nv_bfloat16* bsrc[3] = {B1 + bro, B2 + bro, B3 + bro};

    uint32_t so[2];
#pragma unroll
    for (int q = 0; q < 2; q++)
        so[q] = sw64(arow*64 + half*32 + q*16);

    float acc[2][8][4];
#pragma unroll
    for (int i = 0; i < 2; i++)
#pragma unroll
        for (int j = 0; j < 8; j++)
#pragma unroll
            for (int q = 0; q < 4; q++) acc[i][j][q] = 0.f;

    int nc = K / KC;

    // ---- pipeline: prefetch chunk 0 ----
    {
#pragma unroll
        for (int t = 0; t < 6; t++) {
            if (NPROD == 3 && (t == 2 || t == 5)) continue;
            const __nv_bfloat16* src = (t < 3) ? asrc[t] : bsrc[t-3];
#pragma unroll
            for (int q = 0; q < 2; q++)
                CP16(sbase + t*TILE_B + so[q], src + q*8);
        }
        CP_COMMIT();
    }

    for (int c = 0; c < nc; c++) {
        if (c + 1 < nc) {
            uint32_t sb = sbase + ((c+1) & 1)*STAGE_B;
            size_t kel = (size_t)(c+1)*KC;
#pragma unroll
            for (int t = 0; t < 6; t++) {
                if (NPROD == 3 && (t == 2 || t == 5)) continue;
                const __nv_bfloat16* src = ((t < 3) ? asrc[t] : bsrc[t-3]) + kel;
#pragma unroll
                for (int q = 0; q < 2; q++)
                    CP16(sb + t*TILE_B + so[q], src + q*8);
            }
            CP_COMMIT();
            CP_WAIT1();
        } else {
            CP_WAIT0();
        }
        __syncthreads();

        uint32_t stg = sbase + (c & 1)*STAGE_B;
#pragma unroll
        for (int ks = 0; ks < 2; ks++) {
#pragma unroll
            for (int bs = 0; bs < 3; bs++) {
                constexpr int base_na = (NPROD == 6) ? 3 : 2;
                int na = base_na - bs;
                if (na <= 0) continue;
                uint32_t bbase = stg + (3 + bs)*TILE_B;
                uint32_t bfr[4][4];
#pragma unroll
                for (int nq = 0; nq < 4; nq++) {
                    // B fragment: matrices must be ordered {n0-7 k0-7, n0-7 k8-15, n8-15 k0-7, n8-15 k8-15}
                    // -> row select uses lane&16, k-offset uses lane&8 (DIFFERENT from A!)
                    uint32_t r  = wn*64 + nq*16 + (lane & 7) + ((lane & 16) ? 8 : 0);
                    uint32_t of = ks*32 + ((lane & 8) ? 16 : 0);
                    LDSM4(bfr[nq], bbase + sw64(r*64 + of));
                }
#pragma unroll
                for (int as_ = 0; as_ < 3; as_++) {
                    if (as_ >= na) break;
                    uint32_t abase = stg + as_*TILE_B;
                    uint32_t afr[2][4];
#pragma unroll
                    for (int mf = 0; mf < 2; mf++) {
                        uint32_t r  = wm*32 + mf*16 + (lane & 7) + ((lane & 8) ? 8 : 0);
                        uint32_t of = ks*32 + ((lane & 16) ? 16 : 0);
                        LDSM4(afr[mf], abase + sw64(r*64 + of));
                    }
#pragma unroll
                    for (int mf = 0; mf < 2; mf++)
#pragma unroll
                        for (int nf = 0; nf < 8; nf++)
                            MMA16816(acc[mf][nf], afr[mf], bfr[nf>>1][(nf&1)*2], bfr[nf>>1][(nf&1)*2 + 1]);
                }
            }
        }
        __syncthreads();
    }

    // ---- epilogue ----
    int cbase = blockIdx.x*128 + wn*64;
#pragma unroll
    for (int mf = 0; mf < 2; mf++) {
        int r0 = m0 + wm*32 + mf*16 + (lane >> 2);
#pragma unroll
        for (int nf = 0; nf < 8; nf++) {
            int cc = cbase + nf*8 + (lane & 3)*2;
#pragma unroll
            for (int h = 0; h < 2; h++) {
                int r = r0 + h*8;
                if (r >= Meff) continue;
                float v0 = acc[mf][nf][h*2], v1 = acc[mf][nf][h*2 + 1];
                if (MODE == 4) {
                    int tok = rows[r];
                    float sc = scal[tok];
                    float* xr = Cf + (size_t)tok*N + cc;
                    xr[0] += v0*sc;
                    xr[1] += v1*sc;
                } else if (MODE == 3) {
                    size_t o = (size_t)r*N + cc;
                    v0 = fmaxf(v0, 0.f);
                    v1 = fmaxf(v1, 0.f);
                    split3(v0, D1[o],   D2[o],   D3[o]);
                    split3(v1, D1[o+1], D2[o+1], D3[o+1]);
                } else {
                    float* cr = Cf + (size_t)r*N + cc;
                    if (MODE == 1) {
                        cr[0] = 1.f/(1.f + expf(-v0));
                        cr[1] = 1.f/(1.f + expf(-v1));
                    } else if (MODE == 2) {
                        cr[0] += v0;
                        cr[1] += v1;
                    } else {
                        cr[0] = v0;
                        cr[1] = v1;
                    }
                }
            }
        }
    }
}

// ---------------- launch ----------------
extern "C" void kernel_launch(void* const* d_in, const int* in_sizes, int n_in,
                              void* d_out, int out_size)
{
    const int*   idx   = (const int*)  d_in[0];
    const float* shares= (const float*)d_in[1];
    const float* emb   = (const float*)d_in[2];
    const float* ln1g  = (const float*)d_in[3];
    const float* ln1b  = (const float*)d_in[4];
    const float* ln2g  = (const float*)d_in[5];
    const float* ln2b  = (const float*)d_in[6];
    const float* Wr    = (const float*)d_in[7];
    const float* Wk    = (const float*)d_in[8];
    const float* Wv    = (const float*)d_in[9];
    const float* Wo    = (const float*)d_in[10];
    const float* W1    = (const float*)d_in[11];
    const float* W2    = (const float*)d_in[12];
    const float* wconf = (const float*)d_in[13];
    const float* Wl1   = (const float*)d_in[14];
    const float* Wl2   = (const float*)d_in[15];
    const float* Waff  = (const float*)d_in[17];
    const float* lnfg  = (const float*)d_in[18];
    const float* lnfb  = (const float*)d_in[19];
    const float* headW = (const float*)d_in[20];
    float* out = (float*)d_out;
    (void)in_sizes; (void)n_in; (void)out_size;

    float *X, *Hh, *SC, *HS;
    int *CNT, *LIST;
    float *Rb, *Kb, *Vb;
    __nv_bfloat16 *MX1,*MX2,*MX3, *HB1,*HB2,*HB3, *HZ1,*HZ2,*HZ3, *HD1,*HD2,*HD3, *WT1,*WT2,*WT3;
    cudaGetSymbolAddress((void**)&X,   g_X);
    cudaGetSymbolAddress((void**)&HS,  g_HS);
    cudaGetSymbolAddress((void**)&Rb,  g_R);
    cudaGetSymbolAddress((void**)&Kb,  g_K);
    cudaGetSymbolAddress((void**)&Vb,  g_V);
    cudaGetSymbolAddress((void**)&Hh,  g_H);
    cudaGetSymbolAddress((void**)&SC,  g_SC);
    cudaGetSymbolAddress((void**)&CNT, g_CNT);
    cudaGetSymbolAddress((void**)&LIST,g_LIST);
    cudaGetSymbolAddress((void**)&MX1, g_MX1); cudaGetSymbolAddress((void**)&MX2, g_MX2); cudaGetSymbolAddress((void**)&MX3, g_MX3);
    cudaGetSymbolAddress((void**)&HB1, g_HB1); cudaGetSymbolAddress((void**)&HB2, g_HB2); cudaGetSymbolAddress((void**)&HB3, g_HB3);
    cudaGetSymbolAddress((void**)&HZ1, g_HZ1); cudaGetSymbolAddress((void**)&HZ2, g_HZ2); cudaGetSymbolAddress((void**)&HZ3, g_HZ3);
    cudaGetSymbolAddress((void**)&HD1, g_HD1); cudaGetSymbolAddress((void**)&HD2, g_HD2); cudaGetSymbolAddress((void**)&HD3, g_HD3);
    cudaGetSymbolAddress((void**)&WT1, g_WT1); cudaGetSymbolAddress((void**)&WT2, g_WT2); cudaGetSymbolAddress((void**)&WT3, g_WT3);

    cudaFuncSetAttribute(gemm_mma<0,6>, cudaFuncAttributeMaxDynamicSharedMemorySize, SMEMB);
    cudaFuncSetAttribute(gemm_mma<1,6>, cudaFuncAttributeMaxDynamicSharedMemorySize, SMEMB);
    cudaFuncSetAttribute(gemm_mma<2,6>, cudaFuncAttributeMaxDynamicSharedMemorySize, SMEMB);
    cudaFuncSetAttribute(gemm_mma<3,6>, cudaFuncAttributeMaxDynamicSharedMemorySize, SMEMB);
    cudaFuncSetAttribute(gemm_mma<4,6>, cudaFuncAttributeMaxDynamicSharedMemorySize, SMEMB);
    cudaFuncSetAttribute(gemm_mma<0,3>, cudaFuncAttributeMaxDynamicSharedMemorySize, SMEMB);

    dim3 tb(32, 8);
    // weight arena layout per layer (elems): Wr@0 Wk@CC Wv@2CC Wo@3CC | W1e0@4CC W1e1@8CC |
    // W2e0@12CC W2e1@16CC | Wl1@20CC Wl2@28CC
    for (int l = 0; l < Ln; l++) {
        size_t LB = (size_t)l*WPL;
        tsplit_k<<<dim3(Cn/32, Cn/32), tb>>>(Wr + (size_t)l*CC, WT1+LB,        WT2+LB,        WT3+LB,        Cn, Cn);
        tsplit_k<<<dim3(Cn/32, Cn/32), tb>>>(Wk + (size_t)l*CC, WT1+LB+CC,     WT2+LB+CC,     WT3+LB+CC,     Cn, Cn);
        tsplit_k<<<dim3(Cn/32, Cn/32), tb>>>(Wv + (size_t)l*CC, WT1+LB+2*(size_t)CC, WT2+LB+2*(size_t)CC, WT3+LB+2*(size_t)CC, Cn, Cn);
        tsplit_k<<<dim3(Cn/32, Cn/32), tb>>>(Wo + (size_t)l*CC, WT1+LB+3*(size_t)CC, WT2+LB+3*(size_t)CC, WT3+LB+3*(size_t)CC, Cn, Cn);
        for (int e = 0; e < 2; e++) {
            size_t o1 = LB + (4 + 4*e)*(size_t)CC;
            tsplit_k<<<dim3(Hn/32, Cn/32), tb>>>(W1 + ((size_t)l*2 + e)*Cn*Hn, WT1+o1, WT2+o1, WT3+o1, Cn, Hn);
            size_t o2 = LB + (12 + 4*e)*(size_t)CC;
            tsplit_k<<<dim3(Cn/32, Hn/32), tb>>>(W2 + ((size_t)l*2 + e)*Hn*Cn, WT1+o2, WT2+o2, WT3+o2, Hn, Cn);
        }
        size_t ol1 = LB + 20*(size_t)CC;
        tsplit_k<<<dim3(Hn/32, 2*Cn/32), tb>>>(Wl1 + (size_t)l*2*Cn*Hn, WT1+ol1, WT2+ol1, WT3+ol1, 2*Cn, Hn);
        size_t ol2 = LB + 28*(size_t)CC;
        tsplit_k<<<dim3(Cn/32, Hn/32), tb>>>(Wl2 + (size_t)l*Hn*Cn, WT1+ol2, WT2+ol2, WT3+ol2, Hn, Cn);
    }
    tsplit_k<<<dim3(Vn/32, Cn/32), tb>>>(headW, WT1+WHEAD, WT2+WHEAD, WT3+WHEAD, Cn, Vn);

    embed_k<<<(BT*Cn)/256, 256>>>(idx, emb);

    dim3 gC(Cn/128, BT/128);
    dim3 gH(Hn/128, BT/128);

    for (int l = 0; l < Ln; l++) {
        size_t LB = (size_t)l*WPL;
        ln_k<false><<<BT, 256>>>(X, ln1g + (size_t)l*Cn, ln1b + (size_t)l*Cn, HS, nullptr, nullptr, nullptr);
        mix_k<<<(BT*Cn)/256, 256>>>();

        gemm_mma<1,6><<<gC, 256, SMEMB>>>(MX1,MX2,MX3, WT1+LB,WT2+LB,WT3+LB, Rb, nullptr,nullptr,nullptr, Cn, Cn, nullptr,nullptr,nullptr,0);
        gemm_mma<0,6><<<gC, 256, SMEMB>>>(MX1,MX2,MX3, WT1+LB+CC,WT2+LB+CC,WT3+LB+CC, Kb, nullptr,nullptr,nullptr, Cn, Cn, nullptr,nullptr,nullptr,0);
        gemm_mma<0,6><<<gC, 256, SMEMB>>>(MX1,MX2,MX3, WT1+LB+2*(size_t)CC,WT2+LB+2*(size_t)CC,WT3+LB+2*(size_t)CC, Vb, nullptr,nullptr,nullptr, Cn, Cn, nullptr,nullptr,nullptr,0);

        scan1_k<<<(Bsz*CH*Cn)/256, 256>>>();
        scan2_k<<<(Bsz*Cn)/256, 256>>>();
        scan3_k<<<(Bsz*CH*Cn)/256, 256>>>();

        gemm_mma<2,6><<<gC, 256, SMEMB>>>(MX1,MX2,MX3, WT1+LB+3*(size_t)CC,WT2+LB+3*(size_t)CC,WT3+LB+3*(size_t)CC, X, nullptr,nullptr,nullptr, Cn, Cn, nullptr,nullptr,nullptr,0);

        ln_k<true><<<BT, 256>>>(X, ln2g + (size_t)l*Cn, ln2b + (size_t)l*Cn, Hh, HB1, HB2, HB3);

        zcnt_k<<<1, 32>>>();
        route_k<<<BT, 128>>>(wconf + (size_t)l*En*Cn, Waff + (size_t)l*Cn*En, shares + (size_t)l*En);
        hz_k<<<(BT*2*Cn)/256, 256>>>();

        for (int e = 0; e < 2; e++) {
            size_t o1 = LB + (4 + 4*e)*(size_t)CC;
            size_t o2 = LB + (12 + 4*e)*(size_t)CC;
            gemm_mma<3,6><<<gH, 256, SMEMB>>>(HB1,HB2,HB3, WT1+o1,WT2+o1,WT3+o1, nullptr, HD1,HD2,HD3, Cn, Hn, LIST + e*BT, CNT + e, nullptr, 1);
            gemm_mma<4,6><<<gC, 256, SMEMB>>>(HD1,HD2,HD3, WT1+o2,WT2+o2,WT3+o2, X, nullptr,nullptr,nullptr, Hn, Cn, LIST + e*BT, CNT + e, SC, 0);
        }
        size_t ol1 = LB + 20*(size_t)CC, ol2 = LB + 28*(size_t)CC;
        gemm_mma<3,6><<<gH, 256, SMEMB>>>(HZ1,HZ2,HZ3, WT1+ol1,WT2+ol1,WT3+ol1, nullptr, HD1,HD2,HD3, 2*Cn, Hn, LIST + 2*BT, CNT + 2, nullptr, 1);
        gemm_mma<4,6><<<gC, 256, SMEMB>>>(HD1,HD2,HD3, WT1+ol2,WT2+ol2,WT3+ol2, X, nullptr,nullptr,nullptr, Hn, Cn, LIST + 2*BT, CNT + 2, SC, 0);
    }

    ln_k<true><<<BT, 256>>>(X, lnfg, lnfb, Hh, HB1, HB2, HB3);
    gemm_mma<0,3><<<dim3(Vn/128, BT/128), 256, SMEMB>>>(HB1,HB2,HB3, WT1+WHEAD,WT2+WHEAD,WT3+WHEAD, out, nullptr,nullptr,nullptr, Cn, Vn, nullptr,nullptr,nullptr,0);
}

// round 8
// speedup vs baseline: 2.6975x; 1.4627x over previous
#include <cuda_runtime.h>
#include <cuda_fp16.h>
#include <math.h>
#include <stdint.h>

// ---------------- dims ----------------
#define Bsz 2
#define Tn  2048
#define Cn  1024
#define Vn  32000
#define Ln  4
#define En  3
#define Hn  4096
#define BT  (Bsz*Tn)   // 4096 tokens
#define CH  16         // scan chunks
#define CL  (Tn/CH)
#define KC  32         // GEMM K-chunk (fp16 elems)

#define CC  (Cn*Cn)                     // 1,048,576
#define WPL (32*CC)                     // weights per layer (elems)
#define WHEAD ((size_t)4*WPL)           // head base
#define WTOT  ((size_t)4*WPL + (size_t)Cn*Vn)

// smem: 2 stages x 4 tiles x (128 x 32 fp16 = 8KB)  [A1 A2 B1 B2]
#define TILE_B 8192
#define STAGE_B (4*TILE_B)
#define SMEMB (2*STAGE_B)               // 65536 -> 2 CTAs/SM

// ---------------- scratch (__device__ globals; no allocs) ----------------
__device__ float g_X  [BT*Cn];
__device__ float g_HS [BT*Cn];
__device__ float g_R  [BT*Cn];
__device__ float g_K  [BT*Cn];
__device__ float g_V  [BT*Cn];
__device__ float g_ST [BT*Cn];
__device__ float g_H  [BT*Cn];
__device__ float g_SC [BT];
__device__ float g_PART[Bsz*CH*Cn];
__device__ int   g_CNT[En];
__device__ int   g_LIST[En*BT];

// fp16 pairs (2-way splits)
__device__ __half g_MX1[BT*Cn], g_MX2[BT*Cn];           // mix, then rs
__device__ __half g_HB1[BT*Cn], g_HB2[BT*Cn];           // h (ln2 / lnf)
__device__ __half g_HZ1[BT*2*Cn], g_HZ2[BT*2*Cn];
__device__ __half g_HD1[(size_t)BT*Hn], g_HD2[(size_t)BT*Hn];
__device__ __half g_WT1[WTOT], g_WT2[WTOT];             // transposed weight splits

// ---------------- helpers ----------------
__device__ __forceinline__ void split2(float v, __half& h1, __half& h2) {
    h1 = __float2half_rn(v);
    float r = v - __half2float(h1);
    h2 = __float2half_rn(r);
}

__device__ __forceinline__ uint32_t smem_u32(const void* p) {
    uint32_t a;
    asm("{ .reg .u64 t; cvta.to.shared.u64 t, %1; cvt.u32.u64 %0, t; }" : "=r"(a) : "l"(p));
    return a;
}

#define CP16(dst, src) asm volatile("cp.async.cg.shared.global [%0], [%1], 16;" :: "r"(dst), "l"(src) : "memory")
#define CP_COMMIT()    asm volatile("cp.async.commit_group;" ::: "memory")
#define CP_WAIT1()     asm volatile("cp.async.wait_group 1;" ::: "memory")
#define CP_WAIT0()     asm volatile("cp.async.wait_group 0;" ::: "memory")

#define LDSM4(r, a) \
    asm volatile("ldmatrix.sync.aligned.m8n8.x4.shared.b16 {%0,%1,%2,%3}, [%4];" \
        : "=r"((r)[0]), "=r"((r)[1]), "=r"((r)[2]), "=r"((r)[3]) : "r"(a))

#define MMA16816(d, a, b0v, b1v) \
    asm volatile("mma.sync.aligned.m16n8k16.row.col.f32.f16.f16.f32 " \
        "{%0,%1,%2,%3}, {%4,%5,%6,%7}, {%8,%9}, {%0,%1,%2,%3};" \
        : "+f"((d)[0]), "+f"((d)[1]), "+f"((d)[2]), "+f"((d)[3]) \
        : "r"((a)[0]), "r"((a)[1]), "r"((a)[2]), "r"((a)[3]), "r"(b0v), "r"(b1v))

// swizzle for 64B-pitch rows: XOR 16B-column bits [4:6) with row bits [6:8)
__device__ __forceinline__ uint32_t sw64(uint32_t o) { return o ^ ((o >> 2) & 0x30); }

// ---------------- embedding gather ----------------
__global__ void embed_k(const int* __restrict__ idx, const float* __restrict__ emb) {
    int i = blockIdx.x*blockDim.x + threadIdx.x;
    if (i >= BT*Cn) return;
    int row = i >> 10, c = i & 1023;
    g_X[i] = emb[(size_t)idx[row]*Cn + c];
}

// ---------------- LayerNorm; optional fp16 pair emission ----------------
template<bool TRIP>
__global__ void ln_k(const float* __restrict__ in, const float* __restrict__ g,
                     const float* __restrict__ b, float* __restrict__ out,
                     __half* o1, __half* o2) {
    int row = blockIdx.x;
    const float* p = in + (size_t)row*Cn;
    float v[4];
    float s = 0.f, ss = 0.f;
#pragma unroll
    for (int j = 0; j < 4; j++) {
        v[j] = p[threadIdx.x + j*256];
        s  += v[j];
        ss += v[j]*v[j];
    }
#pragma unroll
    for (int o = 16; o > 0; o >>= 1) {
        s  += __shfl_xor_sync(0xffffffffu, s,  o);
        ss += __shfl_xor_sync(0xffffffffu, ss, o);
    }
    __shared__ float sh[2][8];
    int w = threadIdx.x >> 5;
    if ((threadIdx.x & 31) == 0) { sh[0][w] = s; sh[1][w] = ss; }
    __syncthreads();
    s = 0.f; ss = 0.f;
#pragma unroll
    for (int j = 0; j < 8; j++) { s += sh[0][j]; ss += sh[1][j]; }
    float mean = s * (1.f/Cn);
    float var  = ss * (1.f/Cn) - mean*mean;
    float rstd = rsqrtf(var + 1e-5f);
    float* o = out + (size_t)row*Cn;
#pragma unroll
    for (int j = 0; j < 4; j++) {
        int c = threadIdx.x + j*256;
        float val = (v[j]-mean)*rstd*g[c] + b[c];
        o[c] = val;
        if (TRIP) {
            size_t id = (size_t)row*Cn + c;
            split2(val, o1[id], o2[id]);
        }
    }
}

// ---------------- token-shift mix -> MX pair ----------------
__global__ void mix_k() {
    int i = blockIdx.x*blockDim.x + threadIdx.x;
    if (i >= BT*Cn) return;
    int t = (i >> 10) & (Tn - 1);
    float prev = t ? g_HS[i - Cn] : 0.f;
    float mix = 0.5f*(g_HS[i] + prev);
    split2(mix, g_MX1[i], g_MX2[i]);
}

// ---------------- 3-phase rwkv scan ----------------
__global__ void scan1_k() {
    int i = blockIdx.x*blockDim.x + threadIdx.x;
    if (i >= Bsz*CH*Cn) return;
    int c  = i & 1023;
    int ch = (i >> 10) & (CH - 1);
    int b  = i >> 14;
    size_t base = (size_t)b*Tn*Cn + (size_t)ch*CL*Cn + c;
    float s = 0.f;
#pragma unroll 4
    for (int t = 0; t < CL; t++) {
        size_t id = base + (size_t)t*Cn;
        s += g_K[id]*g_V[id];
    }
    g_PART[i] = s;
}
__global__ void scan2_k() {
    int i = blockIdx.x*blockDim.x + threadIdx.x;
    if (i >= Bsz*Cn) return;
    int c = i & 1023, b = i >> 10;
    float run = 0.f;
#pragma unroll
    for (int ch = 0; ch < CH; ch++) {
        int id = ((b*CH + ch) << 10) | c;
        float p = g_PART[id];
        g_PART[id] = run;
        run += p;
    }
}
__global__ void scan3_k() {  // writes ST fp32 and RS pair into MX
    int i = blockIdx.x*blockDim.x + threadIdx.x;
    if (i >= Bsz*CH*Cn) return;
    int c  = i & 1023;
    int ch = (i >> 10) & (CH - 1);
    int b  = i >> 14;
    size_t base = (size_t)b*Tn*Cn + (size_t)ch*CL*Cn + c;
    float acc = g_PART[i];
    int t0 = ch*CL;
#pragma unroll 4
    for (int t = 0; t < CL; t++) {
        size_t id = base + (size_t)t*Cn;
        acc += g_K[id]*g_V[id];
        float st = acc / (float)(t0 + t + 1);
        g_ST[id] = st;
        float rs = g_R[id]*st;
        split2(rs, g_MX1[id], g_MX2[id]);
    }
}

// ---------------- routing (exact fp32) ----------------
__global__ void zcnt_k() { if (threadIdx.x < En) g_CNT[threadIdx.x] = 0; }

__global__ void route_k(const float* __restrict__ wc, const float* __restrict__ wa,
                        const float* __restrict__ shp) {
    int bt = blockIdx.x;
    const float* hp = g_H + (size_t)bt*Cn;
    float p[6] = {0,0,0,0,0,0};
    for (int c = threadIdx.x; c < Cn; c += 128) {
        float hv = hp[c];
        p[0] += hv*wc[c];
        p[1] += hv*wc[Cn + c];
        p[2] += hv*wc[2*Cn + c];
        p[3] += hv*wa[c*En + 0];
        p[4] += hv*wa[c*En + 1];
        p[5] += hv*wa[c*En + 2];
    }
#pragma unroll
    for (int o = 16; o > 0; o >>= 1)
#pragma unroll
        for (int q = 0; q < 6; q++) p[q] += __shfl_xor_sync(0xffffffffu, p[q], o);
    __shared__ float sm[4][6];
    int w = threadIdx.x >> 5;
    if ((threadIdx.x & 31) == 0)
#pragma unroll
        for (int q = 0; q < 6; q++) sm[w][q] = p[q];
    __syncthreads();
    if (threadIdx.x == 0) {
        float d[6];
#pragma unroll
        for (int q = 0; q < 6; q++) d[q] = sm[0][q] + sm[1][q] + sm[2][q] + sm[3][q];
        float best = -3.4e38f, wcf = 0.f;
        int wi = 0;
#pragma unroll
        for (int e = 0; e < En; e++) {
            float conf = 1.f/(1.f + expf(-d[e]));
            float bid  = conf*shp[e] + d[3+e];
            if (bid > best) { best = bid; wi = e; wcf = conf; }
        }
        g_SC[bt] = wcf / (wcf + 1e-6f);
        int pos = atomicAdd(&g_CNT[wi], 1);
        g_LIST[wi*BT + pos] = bt;
    }
}

// ---------------- hz = concat(h, state) -> pair ----------------
__global__ void hz_k() {
    int i = blockIdx.x*blockDim.x + threadIdx.x;
    if (i >= BT*2*Cn) return;
    int row = i >> 11;
    int c = i & (2*Cn - 1);
    float v = (c < Cn) ? g_H[(size_t)row*Cn + c] : g_ST[(size_t)row*Cn + c - Cn];
    split2(v, g_HZ1[i], g_HZ2[i]);
}

// ---------------- weight transpose + split: W[K,N] fp32 -> Wt[N,K] fp16 x2 ----------------
__global__ void tsplit_k(const float* __restrict__ W,
                         __half* __restrict__ o1, __half* __restrict__ o2,
                         int K, int N) {
    __shared__ __half s1[32][33], s2[32][33];
    int n0 = blockIdx.x*32, k0 = blockIdx.y*32;
    int tx = threadIdx.x, ty = threadIdx.y;
#pragma unroll
    for (int j = 0; j < 4; j++) {
        int k = k0 + ty + j*8;
        float v = W[(size_t)k*N + n0 + tx];
        split2(v, s1[ty+j*8][tx], s2[ty+j*8][tx]);
    }
    __syncthreads();
#pragma unroll
    for (int j = 0; j < 4; j++) {
        int n = n0 + ty + j*8;
        size_t o = (size_t)n*K + k0 + tx;
        o1[o] = s1[tx][ty+j*8];
        o2[o] = s2[tx][ty+j*8];
    }
}

// ---------------- HMMA fp16-split GEMM: 128x128 tile, 8 warps (4m x 2n), KC=32, 2 CTA/SM
// products {A1B1, A2B1, A1B2}  (omitted A2B2 ~ 2^-22)
// MODE 0: C=acc   1: C=sigmoid(acc)   2: C+=acc   3: relu->fp16 pair   4: scatter X[tok]+=acc*scal
template<int MODE>
__global__ void __launch_bounds__(256, 2) gemm_mma(
    const __half* __restrict__ A1, const __half* __restrict__ A2,
    const __half* __restrict__ B1, const __half* __restrict__ B2,
    float* __restrict__ Cf, __half* __restrict__ D1, __half* __restrict__ D2,
    int K, int N,
    const int* __restrict__ rows, const int* __restrict__ cntp,
    const float* __restrict__ scal, int gatherA)
{
    int Meff = cntp ? *cntp : BT;
    int m0 = blockIdx.y * 128;
    if (m0 >= Meff) return;

    extern __shared__ char smem[];
    uint32_t sbase = smem_u32(smem);

    int tid = threadIdx.x, lane = tid & 31, wid = tid >> 5;
    int wm = wid & 3, wn = wid >> 2;

    // ---- gmem -> smem assignment: 2 threads/row, 32B (2x16B) each ----
    int arow = tid >> 1, half_ = tid & 1;
    int am = m0 + arow;
    int amc = (am < Meff) ? am : (Meff - 1);
    long ga = gatherA ? rows[amc] : amc;
    const __half* asrc[2] = {A1 + (size_t)ga*K + half_*16,
                             A2 + (size_t)ga*K + half_*16};
    size_t bro = (size_t)(blockIdx.x*128 + arow)*K + half_*16;
    const __half* bsrc[2] = {B1 + bro, B2 + bro};

    uint32_t so[2];
#pragma unroll
    for (int q = 0; q < 2; q++)
        so[q] = sw64(arow*64 + half_*32 + q*16);

    float acc[2][8][4];
#pragma unroll
    for (int i = 0; i < 2; i++)
#pragma unroll
        for (int j = 0; j < 8; j++)
#pragma unroll
            for (int q = 0; q < 4; q++) acc[i][j][q] = 0.f;

    int nc = K / KC;

    // ---- pipeline: prefetch chunk 0 ----
    {
#pragma unroll
        for (int t = 0; t < 4; t++) {
            const __half* src = (t < 2) ? asrc[t] : bsrc[t-2];
#pragma unroll
            for (int q = 0; q < 2; q++)
                CP16(sbase + t*TILE_B + so[q], src + q*8);
        }
        CP_COMMIT();
    }

    for (int c = 0; c < nc; c++) {
        if (c + 1 < nc) {
            uint32_t sb = sbase + ((c+1) & 1)*STAGE_B;
            size_t kel = (size_t)(c+1)*KC;
#pragma unroll
            for (int t = 0; t < 4; t++) {
                const __half* src = ((t < 2) ? asrc[t] : bsrc[t-2]) + kel;
#pragma unroll
                for (int q = 0; q < 2; q++)
                    CP16(sb + t*TILE_B + so[q], src + q*8);
            }
            CP_COMMIT();
            CP_WAIT1();
        } else {
            CP_WAIT0();
        }
        __syncthreads();

        uint32_t stg = sbase + (c & 1)*STAGE_B;
#pragma unroll
        for (int ks = 0; ks < 2; ks++) {
#pragma unroll
            for (int bs = 0; bs < 2; bs++) {
                int na = 2 - bs;     // B1: {A1,A2}; B2: {A1}
                uint32_t bbase = stg + (2 + bs)*TILE_B;
                uint32_t bfr[4][4];
#pragma unroll
                for (int nq = 0; nq < 4; nq++) {
                    // B fragment: matrices ordered {n0-7 k0-7, n0-7 k8-15, n8-15 k0-7, n8-15 k8-15}
                    // -> row select uses lane&16, k-offset uses lane&8 (DIFFERENT from A!)
                    uint32_t r  = wn*64 + nq*16 + (lane & 7) + ((lane & 16) ? 8 : 0);
                    uint32_t of = ks*32 + ((lane & 8) ? 16 : 0);
                    LDSM4(bfr[nq], bbase + sw64(r*64 + of));
                }
#pragma unroll
                for (int as_ = 0; as_ < 2; as_++) {
                    if (as_ >= na) break;
                    uint32_t abase = stg + as_*TILE_B;
                    uint32_t afr[2][4];
#pragma unroll
                    for (int mf = 0; mf < 2; mf++) {
                        uint32_t r  = wm*32 + mf*16 + (lane & 7) + ((lane & 8) ? 8 : 0);
                        uint32_t of = ks*32 + ((lane & 16) ? 16 : 0);
                        LDSM4(afr[mf], abase + sw64(r*64 + of));
                    }
#pragma unroll
                    for (int mf = 0; mf < 2; mf++)
#pragma unroll
                        for (int nf = 0; nf < 8; nf++)
                            MMA16816(acc[mf][nf], afr[mf], bfr[nf>>1][(nf&1)*2], bfr[nf>>1][(nf&1)*2 + 1]);
                }
            }
        }
        __syncthreads();
    }

    // ---- epilogue ----
    int cbase = blockIdx.x*128 + wn*64;
#pragma unroll
    for (int mf = 0; mf < 2; mf++) {
        int r0 = m0 + wm*32 + mf*16 + (lane >> 2);
#pragma unroll
        for (int nf = 0; nf < 8; nf++) {
            int cc = cbase + nf*8 + (lane & 3)*2;
#pragma unroll
            for (int h = 0; h < 2; h++) {
                int r = r0 + h*8;
                if (r >= Meff) continue;
                float v0 = acc[mf][nf][h*2], v1 = acc[mf][nf][h*2 + 1];
                if (MODE == 4) {
                    int tok = rows[r];
                    float sc = scal[tok];
                    float* xr = Cf + (size_t)tok*N + cc;
                    xr[0] += v0*sc;
                    xr[1] += v1*sc;
                } else if (MODE == 3) {
                    size_t o = (size_t)r*N + cc;
                    v0 = fmaxf(v0, 0.f);
                    v1 = fmaxf(v1, 0.f);
                    split2(v0, D1[o],   D2[o]);
                    split2(v1, D1[o+1], D2[o+1]);
                } else {
                    float* cr = Cf + (size_t)r*N + cc;
                    if (MODE == 1) {
                        cr[0] = 1.f/(1.f + expf(-v0));
                        cr[1] = 1.f/(1.f + expf(-v1));
                    } else if (MODE == 2) {
                        cr[0] += v0;
                        cr[1] += v1;
                    } else {
                        cr[0] = v0;
                        cr[1] = v1;
                    }
                }
            }
        }
    }
}

// ---------------- launch ----------------
extern "C" void kernel_launch(void* const* d_in, const int* in_sizes, int n_in,
                              void* d_out, int out_size)
{
    const int*   idx   = (const int*)  d_in[0];
    const float* shares= (const float*)d_in[1];
    const float* emb   = (const float*)d_in[2];
    const float* ln1g  = (const float*)d_in[3];
    const float* ln1b  = (const float*)d_in[4];
    const float* ln2g  = (const float*)d_in[5];
    const float* ln2b  = (const float*)d_in[6];
    const float* Wr    = (const float*)d_in[7];
    const float* Wk    = (const float*)d_in[8];
    const float* Wv    = (const float*)d_in[9];
    const float* Wo    = (const float*)d_in[10];
    const float* W1    = (const float*)d_in[11];
    const float* W2    = (const float*)d_in[12];
    const float* wconf = (const float*)d_in[13];
    const float* Wl1   = (const float*)d_in[14];
    const float* Wl2   = (const float*)d_in[15];
    const float* Waff  = (const float*)d_in[17];
    const float* lnfg  = (const float*)d_in[18];
    const float* lnfb  = (const float*)d_in[19];
    const float* headW = (const float*)d_in[20];
    float* out = (float*)d_out;
    (void)in_sizes; (void)n_in; (void)out_size;

    float *X, *Hh, *SC, *HS;
    int *CNT, *LIST;
    float *Rb, *Kb, *Vb;
    __half *MX1,*MX2, *HB1,*HB2, *HZ1,*HZ2, *HD1,*HD2, *WT1,*WT2;
    cudaGetSymbolAddress((void**)&X,   g_X);
    cudaGetSymbolAddress((void**)&HS,  g_HS);
    cudaGetSymbolAddress((void**)&Rb,  g_R);
    cudaGetSymbolAddress((void**)&Kb,  g_K);
    cudaGetSymbolAddress((void**)&Vb,  g_V);
    cudaGetSymbolAddress((void**)&Hh,  g_H);
    cudaGetSymbolAddress((void**)&SC,  g_SC);
    cudaGetSymbolAddress((void**)&CNT, g_CNT);
    cudaGetSymbolAddress((void**)&LIST,g_LIST);
    cudaGetSymbolAddress((void**)&MX1, g_MX1); cudaGetSymbolAddress((void**)&MX2, g_MX2);
    cudaGetSymbolAddress((void**)&HB1, g_HB1); cudaGetSymbolAddress((void**)&HB2, g_HB2);
    cudaGetSymbolAddress((void**)&HZ1, g_HZ1); cudaGetSymbolAddress((void**)&HZ2, g_HZ2);
    cudaGetSymbolAddress((void**)&HD1, g_HD1); cudaGetSymbolAddress((void**)&HD2, g_HD2);
    cudaGetSymbolAddress((void**)&WT1, g_WT1); cudaGetSymbolAddress((void**)&WT2, g_WT2);

    cudaFuncSetAttribute(gemm_mma<0>, cudaFuncAttributeMaxDynamicSharedMemorySize, SMEMB);
    cudaFuncSetAttribute(gemm_mma<1>, cudaFuncAttributeMaxDynamicSharedMemorySize, SMEMB);
    cudaFuncSetAttribute(gemm_mma<2>, cudaFuncAttributeMaxDynamicSharedMemorySize, SMEMB);
    cudaFuncSetAttribute(gemm_mma<3>, cudaFuncAttributeMaxDynamicSharedMemorySize, SMEMB);
    cudaFuncSetAttribute(gemm_mma<4>, cudaFuncAttributeMaxDynamicSharedMemorySize, SMEMB);

    dim3 tb(32, 8);
    // weight arena layout per layer (elems): Wr@0 Wk@CC Wv@2CC Wo@3CC | W1e0@4CC W1e1@8CC |
    // W2e0@12CC W2e1@16CC | Wl1@20CC Wl2@28CC
    for (int l = 0; l < Ln; l++) {
        size_t LB = (size_t)l*WPL;
        tsplit_k<<<dim3(Cn/32, Cn/32), tb>>>(Wr + (size_t)l*CC, WT1+LB,        WT2+LB,        Cn, Cn);
        tsplit_k<<<dim3(Cn/32, Cn/32), tb>>>(Wk + (size_t)l*CC, WT1+LB+CC,     WT2+LB+CC,     Cn, Cn);
        tsplit_k<<<dim3(Cn/32, Cn/32), tb>>>(Wv + (size_t)l*CC, WT1+LB+2*(size_t)CC, WT2+LB+2*(size_t)CC, Cn, Cn);
        tsplit_k<<<dim3(Cn/32, Cn/32), tb>>>(Wo + (size_t)l*CC, WT1+LB+3*(size_t)CC, WT2+LB+3*(size_t)CC, Cn, Cn);
        for (int e = 0; e < 2; e++) {
            size_t o1 = LB + (4 + 4*e)*(size_t)CC;
            tsplit_k<<<dim3(Hn/32, Cn/32), tb>>>(W1 + ((size_t)l*2 + e)*Cn*Hn, WT1+o1, WT2+o1, Cn, Hn);
            size_t o2 = LB + (12 + 4*e)*(size_t)CC;
            tsplit_k<<<dim3(Cn/32, Hn/32), tb>>>(W2 + ((size_t)l*2 + e)*Hn*Cn, WT1+o2, WT2+o2, Hn, Cn);
        }
        size_t ol1 = LB + 20*(size_t)CC;
        tsplit_k<<<dim3(Hn/32, 2*Cn/32), tb>>>(Wl1 + (size_t)l*2*Cn*Hn, WT1+ol1, WT2+ol1, 2*Cn, Hn);
        size_t ol2 = LB + 28*(size_t)CC;
        tsplit_k<<<dim3(Cn/32, Hn/32), tb>>>(Wl2 + (size_t)l*Hn*Cn, WT1+ol2, WT2+ol2, Hn, Cn);
    }
    tsplit_k<<<dim3(Vn/32, Cn/32), tb>>>(headW, WT1+WHEAD, WT2+WHEAD, Cn, Vn);

    embed_k<<<(BT*Cn)/256, 256>>>(idx, emb);

    dim3 gC(Cn/128, BT/128);
    dim3 gH(Hn/128, BT/128);

    for (int l = 0; l < Ln; l++) {
        size_t LB = (size_t)l*WPL;
        ln_k<false><<<BT, 256>>>(X, ln1g + (size_t)l*Cn, ln1b + (size_t)l*Cn, HS, nullptr, nullptr);
        mix_k<<<(BT*Cn)/256, 256>>>();

        gemm_mma<1><<<gC, 256, SMEMB>>>(MX1,MX2, WT1+LB,WT2+LB, Rb, nullptr,nullptr, Cn, Cn, nullptr,nullptr,nullptr,0);
        gemm_mma<0><<<gC, 256, SMEMB>>>(MX1,MX2, WT1+LB+CC,WT2+LB+CC, Kb, nullptr,nullptr, Cn, Cn, nullptr,nullptr,nullptr,0);
        gemm_mma<0><<<gC, 256, SMEMB>>>(MX1,MX2, WT1+LB+2*(size_t)CC,WT2+LB+2*(size_t)CC, Vb, nullptr,nullptr, Cn, Cn, nullptr,nullptr,nullptr,0);

        scan1_k<<<(Bsz*CH*Cn)/256, 256>>>();
        scan2_k<<<(Bsz*Cn)/256, 256>>>();
        scan3_k<<<(Bsz*CH*Cn)/256, 256>>>();

        gemm_mma<2><<<gC, 256, SMEMB>>>(MX1,MX2, WT1+LB+3*(size_t)CC,WT2+LB+3*(size_t)CC, X, nullptr,nullptr, Cn, Cn, nullptr,nullptr,nullptr,0);

        ln_k<true><<<BT, 256>>>(X, ln2g + (size_t)l*Cn, ln2b + (size_t)l*Cn, Hh, HB1, HB2);

        zcnt_k<<<1, 32>>>();
        route_k<<<BT, 128>>>(wconf + (size_t)l*En*Cn, Waff + (size_t)l*Cn*En, shares + (size_t)l*En);
        hz_k<<<(BT*2*Cn)/256, 256>>>();

        for (int e = 0; e < 2; e++) {
            size_t o1 = LB + (4 + 4*e)*(size_t)CC;
            size_t o2 = LB + (12 + 4*e)*(size_t)CC;
            gemm_mma<3><<<gH, 256, SMEMB>>>(HB1,HB2, WT1+o1,WT2+o1, nullptr, HD1,HD2, Cn, Hn, LIST + e*BT, CNT + e, nullptr, 1);
            gemm_mma<4><<<gC, 256, SMEMB>>>(HD1,HD2, WT1+o2,WT2+o2, X, nullptr,nullptr, Hn, Cn, LIST + e*BT, CNT + e, SC, 0);
        }
        size_t ol1 = LB + 20*(size_t)CC, ol2 = LB + 28*(size_t)CC;
        gemm_mma<3><<<gH, 256, SMEMB>>>(HZ1,HZ2, WT1+ol1,WT2+ol1, nullptr, HD1,HD2, 2*Cn, Hn, LIST + 2*BT, CNT + 2, nullptr, 1);
        gemm_mma<4><<<gC, 256, SMEMB>>>(HD1,HD2, WT1+ol2,WT2+ol2, X, nullptr,nullptr, Hn, Cn, LIST + 2*BT, CNT + 2, SC, 0);
    }

    ln_k<true><<<BT, 256>>>(X, lnfg, lnfb, Hh, HB1, HB2);
    gemm_mma<0><<<dim3(Vn/128, BT/128), 256, SMEMB>>>(HB1,HB2, WT1+WHEAD,WT2+WHEAD, out, nullptr,nullptr, Cn, Vn, nullptr,nullptr,nullptr,0);
}

// round 9
// speedup vs baseline: 3.4083x; 1.2635x over previous
#include <cuda_runtime.h>
#include <cuda_fp16.h>
#include <math.h>
#include <stdint.h>

// ---------------- dims ----------------
#define Bsz 2
#define Tn  2048
#define Cn  1024
#define Vn  32000
#define Ln  4
#define En  3
#define Hn  4096
#define BT  (Bsz*Tn)
#define CH  16
#define CL  (Tn/CH)
#define KC  32

#define CC  (Cn*Cn)
#define WPL (32*CC)
#define WHEAD ((size_t)4*WPL)
#define WTOT  ((size_t)4*WPL + (size_t)Cn*Vn)

#define TILE_B 8192
#define STAGE_B (4*TILE_B)
#define SMEMB (2*STAGE_B)               // 64KB -> 2 CTAs/SM

// ---------------- scratch ----------------
__device__ float g_X  [BT*Cn];
__device__ float g_HS [BT*Cn];
__device__ float g_R  [BT*Cn];
__device__ float g_K  [BT*Cn];
__device__ float g_V  [BT*Cn];
__device__ float g_ST [BT*Cn];
__device__ float g_H  [BT*Cn];
__device__ float g_SC [BT];
__device__ float g_PART[Bsz*CH*Cn];
__device__ int   g_CNT[En];
__device__ int   g_LIST[En*BT];

__device__ __half g_MX1[BT*Cn], g_MX2[BT*Cn];
__device__ __half g_HB1[BT*Cn], g_HB2[BT*Cn];
__device__ __half g_HZ1[BT*2*Cn], g_HZ2[BT*2*Cn];
__device__ __half g_HD1[(size_t)BT*Hn], g_HD2[(size_t)BT*Hn];
__device__ __half g_WT1[WTOT], g_WT2[WTOT];

// ---------------- helpers ----------------
__device__ __forceinline__ void split2(float v, __half& h1, __half& h2) {
    h1 = __float2half_rn(v);
    float r = v - __half2float(h1);
    h2 = __float2half_rn(r);
}
__device__ __forceinline__ uint32_t smem_u32(const void* p) {
    uint32_t a;
    asm("{ .reg .u64 t; cvta.to.shared.u64 t, %1; cvt.u32.u64 %0, t; }" : "=r"(a) : "l"(p));
    return a;
}
#define CP16(dst, src) asm volatile("cp.async.cg.shared.global [%0], [%1], 16;" :: "r"(dst), "l"(src) : "memory")
#define CP_COMMIT()    asm volatile("cp.async.commit_group;" ::: "memory")
#define CP_WAIT1()     asm volatile("cp.async.wait_group 1;" ::: "memory")
#define CP_WAIT0()     asm volatile("cp.async.wait_group 0;" ::: "memory")
#define LDSM4(r, a) \
    asm volatile("ldmatrix.sync.aligned.m8n8.x4.shared.b16 {%0,%1,%2,%3}, [%4];" \
        : "=r"((r)[0]), "=r"((r)[1]), "=r"((r)[2]), "=r"((r)[3]) : "r"(a))
#define MMA16816(d, a, b0v, b1v) \
    asm volatile("mma.sync.aligned.m16n8k16.row.col.f32.f16.f16.f32 " \
        "{%0,%1,%2,%3}, {%4,%5,%6,%7}, {%8,%9}, {%0,%1,%2,%3};" \
        : "+f"((d)[0]), "+f"((d)[1]), "+f"((d)[2]), "+f"((d)[3]) \
        : "r"((a)[0]), "r"((a)[1]), "r"((a)[2]), "r"((a)[3]), "r"(b0v), "r"(b1v))
__device__ __forceinline__ uint32_t sw64(uint32_t o) { return o ^ ((o >> 2) & 0x30); }

// ---------------- GEMM core: products {A1B1,A2B1,A1B2} (NP=3) or {A1B1,A2B1} (NP=2)
// a1/a2/b1/b2: this thread's row base ptrs (incl. +half*16). acc: 128x128 tile frags.
template<int NP>
__device__ __forceinline__ void mma_core(
    uint32_t sbase,
    const __half* a1, const __half* a2, const __half* b1, const __half* b2,
    int K, int tid, int lane, int wm, int wn, float acc[2][8][4])
{
    int arow = tid >> 1, half_ = tid & 1;
    uint32_t so[2];
#pragma unroll
    for (int q = 0; q < 2; q++)
        so[q] = sw64(arow*64 + half_*32 + q*16);

    const int NT = (NP == 3) ? 4 : 3;
    const __half* srcs[4] = {a1, a2, b1, b2};
    int nc = K / KC;

    {
#pragma unroll
        for (int t = 0; t < 4; t++) {
            if (t >= NT) break;
#pragma unroll
            for (int q = 0; q < 2; q++)
                CP16(sbase + t*TILE_B + so[q], srcs[t] + q*8);
        }
        CP_COMMIT();
    }

    for (int c = 0; c < nc; c++) {
        if (c + 1 < nc) {
            uint32_t sb = sbase + ((c+1) & 1)*STAGE_B;
            size_t kel = (size_t)(c+1)*KC;
#pragma unroll
            for (int t = 0; t < 4; t++) {
                if (t >= NT) break;
#pragma unroll
                for (int q = 0; q < 2; q++)
                    CP16(sb + t*TILE_B + so[q], srcs[t] + kel + q*8);
            }
            CP_COMMIT();
            CP_WAIT1();
        } else {
            CP_WAIT0();
        }
        __syncthreads();

        uint32_t stg = sbase + (c & 1)*STAGE_B;
#pragma unroll
        for (int ks = 0; ks < 2; ks++) {
#pragma unroll
            for (int bs = 0; bs < 2; bs++) {
                if (NP == 2 && bs == 1) break;
                int na = 2 - bs;
                uint32_t bbase = stg + (2 + bs)*TILE_B;
                uint32_t bfr[4][4];
#pragma unroll
                for (int nq = 0; nq < 4; nq++) {
                    // B frag: row select lane&16, k-offset lane&8 (different from A!)
                    uint32_t r  = wn*64 + nq*16 + (lane & 7) + ((lane & 16) ? 8 : 0);
                    uint32_t of = ks*32 + ((lane & 8) ? 16 : 0);
                    LDSM4(bfr[nq], bbase + sw64(r*64 + of));
                }
#pragma unroll
                for (int as_ = 0; as_ < 2; as_++) {
                    if (as_ >= na) break;
                    uint32_t abase = stg + as_*TILE_B;
                    uint32_t afr[2][4];
#pragma unroll
                    for (int mf = 0; mf < 2; mf++) {
                        uint32_t r  = wm*32 + mf*16 + (lane & 7) + ((lane & 8) ? 8 : 0);
                        uint32_t of = ks*32 + ((lane & 16) ? 16 : 0);
                        LDSM4(afr[mf], abase + sw64(r*64 + of));
                    }
#pragma unroll
                    for (int mf = 0; mf < 2; mf++)
#pragma unroll
                        for (int nf = 0; nf < 8; nf++)
                            MMA16816(acc[mf][nf], afr[mf], bfr[nf>>1][(nf&1)*2], bfr[nf>>1][(nf&1)*2 + 1]);
                }
            }
        }
        __syncthreads();
    }
}

#define MMA_PROLOG() \
    extern __shared__ char smem[]; \
    uint32_t sbase = smem_u32(smem); \
    int tid = threadIdx.x, lane = tid & 31, wid = tid >> 5; \
    int wm = wid & 3, wn = wid >> 2; \
    int arow = tid >> 1, half_ = tid & 1; \
    float acc[2][8][4]; \
    _Pragma("unroll") for (int i = 0; i < 2; i++) \
    _Pragma("unroll") for (int j = 0; j < 8; j++) \
    _Pragma("unroll") for (int q = 0; q < 4; q++) acc[i][j][q] = 0.f;

// ---------------- fused r/k/v GEMM: grid(24, 32); B spans 3 contiguous [Cn,Cn] weights
__global__ void __launch_bounds__(256, 2) rkv_mma(
    const __half* __restrict__ A1, const __half* __restrict__ A2,
    const __half* __restrict__ B1, const __half* __restrict__ B2)
{
    MMA_PROLOG();
    int m0 = blockIdx.y * 128;
    size_t aro = (size_t)(m0 + arow)*Cn + half_*16;
    size_t bro = (size_t)(blockIdx.x*128 + arow)*Cn + half_*16;
    mma_core<3>(sbase, A1 + aro, A2 + aro, B1 + bro, B2 + bro, Cn, tid, lane, wm, wn, acc);

    int mat = blockIdx.x >> 3;
    float* outp = (mat == 0) ? g_R : ((mat == 1) ? g_K : g_V);
    int cbase = (blockIdx.x & 7)*128 + wn*64;
#pragma unroll
    for (int mf = 0; mf < 2; mf++) {
        int r0 = m0 + wm*32 + mf*16 + (lane >> 2);
#pragma unroll
        for (int nf = 0; nf < 8; nf++) {
            int cc = cbase + nf*8 + (lane & 3)*2;
#pragma unroll
            for (int h = 0; h < 2; h++) {
                int r = r0 + h*8;
                float v0 = acc[mf][nf][h*2], v1 = acc[mf][nf][h*2 + 1];
                if (mat == 0) {
                    v0 = 1.f/(1.f + expf(-v0));
                    v1 = 1.f/(1.f + expf(-v1));
                }
                float* cr = outp + (size_t)r*Cn + cc;
                cr[0] = v0; cr[1] = v1;
            }
        }
    }
}

// ---------------- generic dense GEMM: MODE 0: C=acc  2: C+=acc
template<int MODE, int NP>
__global__ void __launch_bounds__(256, 2) gemm_mma(
    const __half* __restrict__ A1, const __half* __restrict__ A2,
    const __half* __restrict__ B1, const __half* __restrict__ B2,
    float* __restrict__ Cf, int K, int N)
{
    MMA_PROLOG();
    int m0 = blockIdx.y * 128;
    size_t aro = (size_t)(m0 + arow)*K + half_*16;
    size_t bro = (size_t)(blockIdx.x*128 + arow)*K + half_*16;
    mma_core<NP>(sbase, A1 + aro, A2 + aro, B1 + bro, B2 + bro, K, tid, lane, wm, wn, acc);

    int cbase = blockIdx.x*128 + wn*64;
#pragma unroll
    for (int mf = 0; mf < 2; mf++) {
        int r0 = m0 + wm*32 + mf*16 + (lane >> 2);
#pragma unroll
        for (int nf = 0; nf < 8; nf++) {
            int cc = cbase + nf*8 + (lane & 3)*2;
#pragma unroll
            for (int h = 0; h < 2; h++) {
                int r = r0 + h*8;
                float v0 = acc[mf][nf][h*2], v1 = acc[mf][nf][h*2 + 1];
                float* cr = Cf + (size_t)r*N + cc;
                if (MODE == 2) { cr[0] += v0; cr[1] += v1; }
                else           { cr[0] = v0;  cr[1] = v1; }
            }
        }
    }
}

// ---------------- fused expert up-proj: grid(32, 32, 3); relu -> HD pair at TOKEN rows
struct UpArgs {
    const __half* A1[3]; const __half* A2[3];
    const __half* B1[3]; const __half* B2[3];
    int K[3];
};
__global__ void __launch_bounds__(256, 2) up3_mma(UpArgs ua) {
    int z = blockIdx.z;
    int Meff = g_CNT[z];
    int m0 = blockIdx.y * 128;
    if (m0 >= Meff) return;
    const int* rows = g_LIST + z*BT;
    int K = ua.K[z];

    MMA_PROLOG();
    int am = m0 + arow;
    int amc = (am < Meff) ? am : (Meff - 1);
    size_t aro = (size_t)rows[amc]*K + half_*16;
    size_t bro = (size_t)(blockIdx.x*128 + arow)*K + half_*16;
    mma_core<3>(sbase, ua.A1[z] + aro, ua.A2[z] + aro, ua.B1[z] + bro, ua.B2[z] + bro,
                K, tid, lane, wm, wn, acc);

    int cbase = blockIdx.x*128 + wn*64;
#pragma unroll
    for (int mf = 0; mf < 2; mf++) {
        int r0 = m0 + wm*32 + mf*16 + (lane >> 2);
#pragma unroll
        for (int nf = 0; nf < 8; nf++) {
            int cc = cbase + nf*8 + (lane & 3)*2;
#pragma unroll
            for (int h = 0; h < 2; h++) {
                int r = r0 + h*8;
                if (r >= Meff) continue;
                size_t o = (size_t)rows[r]*Hn + cc;
                float v0 = fmaxf(acc[mf][nf][h*2],     0.f);
                float v1 = fmaxf(acc[mf][nf][h*2 + 1], 0.f);
                split2(v0, g_HD1[o],   g_HD2[o]);
                split2(v1, g_HD1[o+1], g_HD2[o+1]);
            }
        }
    }
}

// ---------------- fused expert down-proj: grid(8, 32, 3); scatter X[tok] += acc*SC[tok]
struct DnArgs { const __half* B1[3]; const __half* B2[3]; };
__global__ void __launch_bounds__(256, 2) dn3_mma(DnArgs da) {
    int z = blockIdx.z;
    int Meff = g_CNT[z];
    int m0 = blockIdx.y * 128;
    if (m0 >= Meff) return;
    const int* rows = g_LIST + z*BT;

    MMA_PROLOG();
    int am = m0 + arow;
    int amc = (am < Meff) ? am : (Meff - 1);
    size_t aro = (size_t)rows[amc]*Hn + half_*16;
    size_t bro = (size_t)(blockIdx.x*128 + arow)*Hn + half_*16;
    mma_core<3>(sbase, g_HD1 + aro, g_HD2 + aro, da.B1[z] + bro, da.B2[z] + bro,
                Hn, tid, lane, wm, wn, acc);

    int cbase = blockIdx.x*128 + wn*64;
#pragma unroll
    for (int mf = 0; mf < 2; mf++) {
        int r0 = m0 + wm*32 + mf*16 + (lane >> 2);
#pragma unroll
        for (int nf = 0; nf < 8; nf++) {
            int cc = cbase + nf*8 + (lane & 3)*2;
#pragma unroll
            for (int h = 0; h < 2; h++) {
                int r = r0 + h*8;
                if (r >= Meff) continue;
                int tok = rows[r];
                float sc = g_SC[tok];
                float* xr = g_X + (size_t)tok*Cn + cc;
                xr[0] += acc[mf][nf][h*2]*sc;
                xr[1] += acc[mf][nf][h*2 + 1]*sc;
            }
        }
    }
}

// ---------------- embedding gather ----------------
__global__ void embed_k(const int* __restrict__ idx, const float* __restrict__ emb) {
    int i = blockIdx.x*blockDim.x + threadIdx.x;
    if (i >= BT*Cn) return;
    int row = i >> 10, c = i & 1023;
    g_X[i] = emb[(size_t)idx[row]*Cn + c];
}

// ---------------- LayerNorm; TRIP: emit fp16 pair + zero CNT ----------------
template<bool TRIP>
__global__ void ln_k(const float* __restrict__ in, const float* __restrict__ g,
                     const float* __restrict__ b, float* __restrict__ out,
                     __half* o1, __half* o2) {
    int row = blockIdx.x;
    if (TRIP && row == 0 && threadIdx.x < En) g_CNT[threadIdx.x] = 0;
    const float* p = in + (size_t)row*Cn;
    float v[4];
    float s = 0.f, ss = 0.f;
#pragma unroll
    for (int j = 0; j < 4; j++) {
        v[j] = p[threadIdx.x + j*256];
        s  += v[j];
        ss += v[j]*v[j];
    }
#pragma unroll
    for (int o = 16; o > 0; o >>= 1) {
        s  += __shfl_xor_sync(0xffffffffu, s,  o);
        ss += __shfl_xor_sync(0xffffffffu, ss, o);
    }
    __shared__ float sh[2][8];
    int w = threadIdx.x >> 5;
    if ((threadIdx.x & 31) == 0) { sh[0][w] = s; sh[1][w] = ss; }
    __syncthreads();
    s = 0.f; ss = 0.f;
#pragma unroll
    for (int j = 0; j < 8; j++) { s += sh[0][j]; ss += sh[1][j]; }
    float mean = s * (1.f/Cn);
    float var  = ss * (1.f/Cn) - mean*mean;
    float rstd = rsqrtf(var + 1e-5f);
    float* o = out + (size_t)row*Cn;
#pragma unroll
    for (int j = 0; j < 4; j++) {
        int c = threadIdx.x + j*256;
        float val = (v[j]-mean)*rstd*g[c] + b[c];
        o[c] = val;
        if (TRIP) {
            size_t id = (size_t)row*Cn + c;
            split2(val, o1[id], o2[id]);
        }
    }
}

// ---------------- token-shift mix -> MX pair ----------------
__global__ void mix_k() {
    int i = blockIdx.x*blockDim.x + threadIdx.x;
    if (i >= BT*Cn) return;
    int t = (i >> 10) & (Tn - 1);
    float prev = t ? g_HS[i - Cn] : 0.f;
    float mix = 0.5f*(g_HS[i] + prev);
    split2(mix, g_MX1[i], g_MX2[i]);
}

// ---------------- 3-phase rwkv scan ----------------
__global__ void scan1_k() {
    int i = blockIdx.x*blockDim.x + threadIdx.x;
    if (i >= Bsz*CH*Cn) return;
    int c  = i & 1023;
    int ch = (i >> 10) & (CH - 1);
    int b  = i >> 14;
    size_t base = (size_t)b*Tn*Cn + (size_t)ch*CL*Cn + c;
    float s = 0.f;
#pragma unroll 4
    for (int t = 0; t < CL; t++) {
        size_t id = base + (size_t)t*Cn;
        s += g_K[id]*g_V[id];
    }
    g_PART[i] = s;
}
__global__ void scan2_k() {
    int i = blockIdx.x*blockDim.x + threadIdx.x;
    if (i >= Bsz*Cn) return;
    int c = i & 1023, b = i >> 10;
    float run = 0.f;
#pragma unroll
    for (int ch = 0; ch < CH; ch++) {
        int id = ((b*CH + ch) << 10) | c;
        float p = g_PART[id];
        g_PART[id] = run;
        run += p;
    }
}
__global__ void scan3_k() {
    int i = blockIdx.x*blockDim.x + threadIdx.x;
    if (i >= Bsz*CH*Cn) return;
    int c  = i & 1023;
    int ch = (i >> 10) & (CH - 1);
    int b  = i >> 14;
    size_t base = (size_t)b*Tn*Cn + (size_t)ch*CL*Cn + c;
    float acc = g_PART[i];
    int t0 = ch*CL;
#pragma unroll 4
    for (int t = 0; t < CL; t++) {
        size_t id = base + (size_t)t*Cn;
        acc += g_K[id]*g_V[id];
        float st = acc / (float)(t0 + t + 1);
        g_ST[id] = st;
        float rs = g_R[id]*st;
        split2(rs, g_MX1[id], g_MX2[id]);
    }
}

// ---------------- routing (exact fp32) ----------------
__global__ void route_k(const float* __restrict__ wc, const float* __restrict__ wa,
                        const float* __restrict__ shp) {
    int bt = blockIdx.x;
    const float* hp = g_H + (size_t)bt*Cn;
    float p[6] = {0,0,0,0,0,0};
    for (int c = threadIdx.x; c < Cn; c += 128) {
        float hv = hp[c];
        p[0] += hv*wc[c];
        p[1] += hv*wc[Cn + c];
        p[2] += hv*wc[2*Cn + c];
        p[3] += hv*wa[c*En + 0];
        p[4] += hv*wa[c*En + 1];
        p[5] += hv*wa[c*En + 2];
    }
#pragma unroll
    for (int o = 16; o > 0; o >>= 1)
#pragma unroll
        for (int q = 0; q < 6; q++) p[q] += __shfl_xor_sync(0xffffffffu, p[q], o);
    __shared__ float sm[4][6];
    int w = threadIdx.x >> 5;
    if ((threadIdx.x & 31) == 0)
#pragma unroll
        for (int q = 0; q < 6; q++) sm[w][q] = p[q];
    __syncthreads();
    if (threadIdx.x == 0) {
        float d[6];
#pragma unroll
        for (int q = 0; q < 6; q++) d[q] = sm[0][q] + sm[1][q] + sm[2][q] + sm[3][q];
        float best = -3.4e38f, wcf = 0.f;
        int wi = 0;
#pragma unroll
        for (int e = 0; e < En; e++) {
            float conf = 1.f/(1.f + expf(-d[e]));
            float bid  = conf*shp[e] + d[3+e];
            if (bid > best) { best = bid; wi = e; wcf = conf; }
        }
        g_SC[bt] = wcf / (wcf + 1e-6f);
        int pos = atomicAdd(&g_CNT[wi], 1);
        g_LIST[wi*BT + pos] = bt;
    }
}

// ---------------- hz = concat(h, state) -> pair ----------------
__global__ void hz_k() {
    int i = blockIdx.x*blockDim.x + threadIdx.x;
    if (i >= BT*2*Cn) return;
    int row = i >> 11;
    int c = i & (2*Cn - 1);
    float v = (c < Cn) ? g_H[(size_t)row*Cn + c] : g_ST[(size_t)row*Cn + c - Cn];
    split2(v, g_HZ1[i], g_HZ2[i]);
}

// ---------------- batched weight transpose+split: z-indexed src/dst ----------------
__global__ void tsplit_k(const float* __restrict__ W,
                         __half* __restrict__ o1, __half* __restrict__ o2,
                         int K, int N, size_t srcStride, size_t dstStride) {
    __shared__ __half s1[32][33], s2[32][33];
    int z = blockIdx.z;
    W  += (size_t)z*srcStride;
    o1 += (size_t)z*dstStride;
    o2 += (size_t)z*dstStride;
    int n0 = blockIdx.x*32, k0 = blockIdx.y*32;
    int tx = threadIdx.x, ty = threadIdx.y;
#pragma unroll
    for (int j = 0; j < 4; j++) {
        int k = k0 + ty + j*8;
        float v = W[(size_t)k*N + n0 + tx];
        split2(v, s1[ty+j*8][tx], s2[ty+j*8][tx]);
    }
    __syncthreads();
#pragma unroll
    for (int j = 0; j < 4; j++) {
        int n = n0 + ty + j*8;
        size_t o = (size_t)n*K + k0 + tx;
        o1[o] = s1[tx][ty+j*8];
        o2[o] = s2[tx][ty+j*8];
    }
}

// ---------------- launch ----------------
extern "C" void kernel_launch(void* const* d_in, const int* in_sizes, int n_in,
                              void* d_out, int out_size)
{
    const int*   idx   = (const int*)  d_in[0];
    const float* shares= (const float*)d_in[1];
    const float* emb   = (const float*)d_in[2];
    const float* ln1g  = (const float*)d_in[3];
    const float* ln1b  = (const float*)d_in[4];
    const float* ln2g  = (const float*)d_in[5];
    const float* ln2b  = (const float*)d_in[6];
    const float* Wr    = (const float*)d_in[7];
    const float* Wk    = (const float*)d_in[8];
    const float* Wv    = (const float*)d_in[9];
    const float* Wo    = (const float*)d_in[10];
    const float* W1    = (const float*)d_in[11];
    const float* W2    = (const float*)d_in[12];
    const float* wconf = (const float*)d_in[13];
    const float* Wl1   = (const float*)d_in[14];
    const float* Wl2   = (const float*)d_in[15];
    const float* Waff  = (const float*)d_in[17];
    const float* lnfg  = (const float*)d_in[18];
    const float* lnfb  = (const float*)d_in[19];
    const float* headW = (const float*)d_in[20];
    float* out = (float*)d_out;
    (void)in_sizes; (void)n_in; (void)out_size;

    float *X, *Hh, *HS;
    __half *MX1,*MX2, *HB1,*HB2, *HZ1,*HZ2, *WT1,*WT2;
    cudaGetSymbolAddress((void**)&X,   g_X);
    cudaGetSymbolAddress((void**)&HS,  g_HS);
    cudaGetSymbolAddress((void**)&Hh,  g_H);
    cudaGetSymbolAddress((void**)&MX1, g_MX1); cudaGetSymbolAddress((void**)&MX2, g_MX2);
    cudaGetSymbolAddress((void**)&HB1, g_HB1); cudaGetSymbolAddress((void**)&HB2, g_HB2);
    cudaGetSymbolAddress((void**)&HZ1, g_HZ1); cudaGetSymbolAddress((void**)&HZ2, g_HZ2);
    cudaGetSymbolAddress((void**)&WT1, g_WT1); cudaGetSymbolAddress((void**)&WT2, g_WT2);

    cudaFuncSetAttribute(rkv_mma,        cudaFuncAttributeMaxDynamicSharedMemorySize, SMEMB);
    cudaFuncSetAttribute(gemm_mma<2,3>,  cudaFuncAttributeMaxDynamicSharedMemorySize, SMEMB);
    cudaFuncSetAttribute(gemm_mma<0,2>,  cudaFuncAttributeMaxDynamicSharedMemorySize, SMEMB);
    cudaFuncSetAttribute(up3_mma,        cudaFuncAttributeMaxDynamicSharedMemorySize, SMEMB);
    cudaFuncSetAttribute(dn3_mma,        cudaFuncAttributeMaxDynamicSharedMemorySize, SMEMB);

    dim3 tb(32, 8);
    // batched tsplit: 11 launches total
    // arena per layer: Wr@0 Wk@CC Wv@2CC Wo@3CC | W1e0@4CC W1e1@8CC | W2e0@12CC W2e1@16CC | Wl1@20CC Wl2@28CC
    tsplit_k<<<dim3(Cn/32, Cn/32, Ln), tb>>>(Wr, WT1,                 WT2,                 Cn, Cn, CC, WPL);
    tsplit_k<<<dim3(Cn/32, Cn/32, Ln), tb>>>(Wk, WT1+CC,              WT2+CC,              Cn, Cn, CC, WPL);
    tsplit_k<<<dim3(Cn/32, Cn/32, Ln), tb>>>(Wv, WT1+2*(size_t)CC,    WT2+2*(size_t)CC,    Cn, Cn, CC, WPL);
    tsplit_k<<<dim3(Cn/32, Cn/32, Ln), tb>>>(Wo, WT1+3*(size_t)CC,    WT2+3*(size_t)CC,    Cn, Cn, CC, WPL);
    tsplit_k<<<dim3(Hn/32, Cn/32, Ln), tb>>>(W1,               WT1+4*(size_t)CC,  WT2+4*(size_t)CC,  Cn, Hn, 2*(size_t)Cn*Hn, WPL);
    tsplit_k<<<dim3(Hn/32, Cn/32, Ln), tb>>>(W1 + (size_t)Cn*Hn, WT1+8*(size_t)CC, WT2+8*(size_t)CC, Cn, Hn, 2*(size_t)Cn*Hn, WPL);
    tsplit_k<<<dim3(Cn/32, Hn/32, Ln), tb>>>(W2,               WT1+12*(size_t)CC, WT2+12*(size_t)CC, Hn, Cn, 2*(size_t)Hn*Cn, WPL);
    tsplit_k<<<dim3(Cn/32, Hn/32, Ln), tb>>>(W2 + (size_t)Hn*Cn, WT1+16*(size_t)CC, WT2+16*(size_t)CC, Hn, Cn, 2*(size_t)Hn*Cn, WPL);
    tsplit_k<<<dim3(Hn/32, 2*Cn/32, Ln), tb>>>(Wl1, WT1+20*(size_t)CC, WT2+20*(size_t)CC, 2*Cn, Hn, 2*(size_t)Cn*Hn, WPL);
    tsplit_k<<<dim3(Cn/32, Hn/32, Ln), tb>>>(Wl2, WT1+28*(size_t)CC, WT2+28*(size_t)CC, Hn, Cn, (size_t)Hn*Cn, WPL);
    tsplit_k<<<dim3(Vn/32, Cn/32, 1), tb>>>(headW, WT1+WHEAD, WT2+WHEAD, Cn, Vn, 0, 0);

    embed_k<<<(BT*Cn)/256, 256>>>(idx, emb);

    for (int l = 0; l < Ln; l++) {
        size_t LB = (size_t)l*WPL;
        ln_k<false><<<BT, 256>>>(X, ln1g + (size_t)l*Cn, ln1b + (size_t)l*Cn, HS, nullptr, nullptr);
        mix_k<<<(BT*Cn)/256, 256>>>();

        rkv_mma<<<dim3(24, 32), 256, SMEMB>>>(MX1, MX2, WT1+LB, WT2+LB);

        scan1_k<<<(Bsz*CH*Cn)/256, 256>>>();
        scan2_k<<<(Bsz*Cn)/256, 256>>>();
        scan3_k<<<(Bsz*CH*Cn)/256, 256>>>();

        gemm_mma<2,3><<<dim3(8, 32), 256, SMEMB>>>(MX1, MX2, WT1+LB+3*(size_t)CC, WT2+LB+3*(size_t)CC, X, Cn, Cn);

        ln_k<true><<<BT, 256>>>(X, ln2g + (size_t)l*Cn, ln2b + (size_t)l*Cn, Hh, HB1, HB2);
        route_k<<<BT, 128>>>(wconf + (size_t)l*En*Cn, Waff + (size_t)l*Cn*En, shares + (size_t)l*En);
        hz_k<<<(BT*2*Cn)/256, 256>>>();

        UpArgs ua;
        DnArgs da;
        for (int e = 0; e < 2; e++) {
            size_t o1 = LB + (4 + 4*e)*(size_t)CC;
            size_t o2 = LB + (12 + 4*e)*(size_t)CC;
            ua.A1[e] = HB1; ua.A2[e] = HB2;
            ua.B1[e] = WT1 + o1; ua.B2[e] = WT2 + o1;
            ua.K[e] = Cn;
            da.B1[e] = WT1 + o2; da.B2[e] = WT2 + o2;
        }
        ua.A1[2] = HZ1; ua.A2[2] = HZ2;
        ua.B1[2] = WT1 + LB + 20*(size_t)CC; ua.B2[2] = WT2 + LB + 20*(size_t)CC;
        ua.K[2] = 2*Cn;
        da.B1[2] = WT1 + LB + 28*(size_t)CC; da.B2[2] = WT2 + LB + 28*(size_t)CC;

        up3_mma<<<dim3(32, 32, 3), 256, SMEMB>>>(ua);
        dn3_mma<<<dim3(8, 32, 3), 256, SMEMB>>>(da);
    }

    ln_k<true><<<BT, 256>>>(X, lnfg, lnfb, Hh, HB1, HB2);
    gemm_mma<0,2><<<dim3(Vn/128, BT/128), 256, SMEMB>>>(HB1, HB2, WT1+WHEAD, WT2+WHEAD, out, Cn, Vn);
}

// round 10
// speedup vs baseline: 3.4389x; 1.0090x over previous
#include <cuda_runtime.h>
#include <cuda_fp16.h>
#include <math.h>
#include <stdint.h>

// ---------------- dims ----------------
#define Bsz 2
#define Tn  2048
#define Cn  1024
#define Vn  32000
#define Ln  4
#define En  3
#define Hn  4096
#define BT  (Bsz*Tn)
#define CH  16
#define CL  (Tn/CH)
#define KC  32

#define CC  (Cn*Cn)
#define WPL (32*CC)
#define WHEAD ((size_t)4*WPL)
#define WTOT  ((size_t)4*WPL + (size_t)Cn*Vn)

#define TILE_B 8192
#define STAGE_B (4*TILE_B)
#define SMEMB (2*STAGE_B)               // 64KB -> 2 CTAs/SM

// ---------------- scratch ----------------
__device__ float g_X  [BT*Cn];
__device__ float g_R  [BT*Cn];
__device__ float g_K  [BT*Cn];
__device__ float g_V  [BT*Cn];
__device__ float g_SC [BT];
__device__ float g_PART[Bsz*CH*Cn];
__device__ int   g_CNT[En];
__device__ int   g_LIST[En*BT];

__device__ __half g_MX1[BT*Cn], g_MX2[BT*Cn];           // mix, then rs
__device__ __half g_SP1[BT*Cn], g_SP2[BT*Cn];           // rwkv state pair
__device__ __half g_HB1[BT*Cn], g_HB2[BT*Cn];           // h pair
__device__ __half g_HD1[(size_t)BT*Hn], g_HD2[(size_t)BT*Hn];
__device__ __half g_WT1[WTOT], g_WT2[WTOT];

// ---------------- helpers ----------------
__device__ __forceinline__ void split2(float v, __half& h1, __half& h2) {
    h1 = __float2half_rn(v);
    float r = v - __half2float(h1);
    h2 = __float2half_rn(r);
}
__device__ __forceinline__ uint32_t smem_u32(const void* p) {
    uint32_t a;
    asm("{ .reg .u64 t; cvta.to.shared.u64 t, %1; cvt.u32.u64 %0, t; }" : "=r"(a) : "l"(p));
    return a;
}
#define CP16(dst, src) asm volatile("cp.async.cg.shared.global [%0], [%1], 16;" :: "r"(dst), "l"(src) : "memory")
#define CP_COMMIT()    asm volatile("cp.async.commit_group;" ::: "memory")
#define CP_WAIT1()     asm volatile("cp.async.wait_group 1;" ::: "memory")
#define CP_WAIT0()     asm volatile("cp.async.wait_group 0;" ::: "memory")
#define LDSM4(r, a) \
    asm volatile("ldmatrix.sync.aligned.m8n8.x4.shared.b16 {%0,%1,%2,%3}, [%4];" \
        : "=r"((r)[0]), "=r"((r)[1]), "=r"((r)[2]), "=r"((r)[3]) : "r"(a))
#define MMA16816(d, a, b0v, b1v) \
    asm volatile("mma.sync.aligned.m16n8k16.row.col.f32.f16.f16.f32 " \
        "{%0,%1,%2,%3}, {%4,%5,%6,%7}, {%8,%9}, {%0,%1,%2,%3};" \
        : "+f"((d)[0]), "+f"((d)[1]), "+f"((d)[2]), "+f"((d)[3]) \
        : "r"((a)[0]), "r"((a)[1]), "r"((a)[2]), "r"((a)[3]), "r"(b0v), "r"(b1v))
__device__ __forceinline__ uint32_t sw64(uint32_t o) { return o ^ ((o >> 2) & 0x30); }

// ---------------- GEMM core: products {A1B1,A2B1,A1B2} (NP=3) or {A1B1,A2B1} (NP=2)
// A source switches to (a1b,a2b) for k >= ksw (chunk-aligned). Pointers include row+half offsets.
template<int NP>
__device__ __forceinline__ void mma_core(
    uint32_t sbase,
    const __half* a1, const __half* a2, const __half* a1b, const __half* a2b, int ksw,
    const __half* b1, const __half* b2,
    int K, int tid, int lane, int wm, int wn, float acc[2][8][4])
{
    int arow = tid >> 1, half_ = tid & 1;
    uint32_t so[2];
#pragma unroll
    for (int q = 0; q < 2; q++)
        so[q] = sw64(arow*64 + half_*32 + q*16);

    const int NT = (NP == 3) ? 4 : 3;
    int nc = K / KC;

    {
        const __half* s0 = a1;
        const __half* s1 = a2;
        const __half* srcs[4] = {s0, s1, b1, b2};
#pragma unroll
        for (int t = 0; t < 4; t++) {
            if (t >= NT) break;
#pragma unroll
            for (int q = 0; q < 2; q++)
                CP16(sbase + t*TILE_B + so[q], srcs[t] + q*8);
        }
        CP_COMMIT();
    }

    for (int c = 0; c < nc; c++) {
        if (c + 1 < nc) {
            uint32_t sb = sbase + ((c+1) & 1)*STAGE_B;
            int k0 = (c+1)*KC;
            const __half* s0 = (k0 < ksw) ? a1 + k0 : a1b + (k0 - ksw);
            const __half* s1 = (k0 < ksw) ? a2 + k0 : a2b + (k0 - ksw);
            const __half* srcs[4] = {s0, s1, b1 + k0, b2 + k0};
#pragma unroll
            for (int t = 0; t < 4; t++) {
                if (t >= NT) break;
#pragma unroll
                for (int q = 0; q < 2; q++)
                    CP16(sb + t*TILE_B + so[q], srcs[t] + q*8);
            }
            CP_COMMIT();
            CP_WAIT1();
        } else {
            CP_WAIT0();
        }
        __syncthreads();

        uint32_t stg = sbase + (c & 1)*STAGE_B;
#pragma unroll
        for (int ks = 0; ks < 2; ks++) {
#pragma unroll
            for (int bs = 0; bs < 2; bs++) {
                if (NP == 2 && bs == 1) break;
                int na = 2 - bs;
                uint32_t bbase = stg + (2 + bs)*TILE_B;
                uint32_t bfr[4][4];
#pragma unroll
                for (int nq = 0; nq < 4; nq++) {
                    // B frag: row select lane&16, k-offset lane&8 (different from A!)
                    uint32_t r  = wn*64 + nq*16 + (lane & 7) + ((lane & 16) ? 8 : 0);
                    uint32_t of = ks*32 + ((lane & 8) ? 16 : 0);
                    LDSM4(bfr[nq], bbase + sw64(r*64 + of));
                }
#pragma unroll
                for (int as_ = 0; as_ < 2; as_++) {
                    if (as_ >= na) break;
                    uint32_t abase = stg + as_*TILE_B;
                    uint32_t afr[2][4];
#pragma unroll
                    for (int mf = 0; mf < 2; mf++) {
                        uint32_t r  = wm*32 + mf*16 + (lane & 7) + ((lane & 8) ? 8 : 0);
                        uint32_t of = ks*32 + ((lane & 16) ? 16 : 0);
                        LDSM4(afr[mf], abase + sw64(r*64 + of));
                    }
#pragma unroll
                    for (int mf = 0; mf < 2; mf++)
#pragma unroll
                        for (int nf = 0; nf < 8; nf++)
                            MMA16816(acc[mf][nf], afr[mf], bfr[nf>>1][(nf&1)*2], bfr[nf>>1][(nf&1)*2 + 1]);
                }
            }
        }
        __syncthreads();
    }
}

#define MMA_PROLOG() \
    extern __shared__ char smem[]; \
    uint32_t sbase = smem_u32(smem); \
    int tid = threadIdx.x, lane = tid & 31, wid = tid >> 5; \
    int wm = wid & 3, wn = wid >> 2; \
    int arow = tid >> 1, half_ = tid & 1; \
    float acc[2][8][4]; \
    _Pragma("unroll") for (int i = 0; i < 2; i++) \
    _Pragma("unroll") for (int j = 0; j < 8; j++) \
    _Pragma("unroll") for (int q = 0; q < 4; q++) acc[i][j][q] = 0.f;

// ---------------- fused r/k/v GEMM: grid(24, 32) ----------------
__global__ void __launch_bounds__(256, 2) rkv_mma(
    const __half* __restrict__ A1, const __half* __restrict__ A2,
    const __half* __restrict__ B1, const __half* __restrict__ B2)
{
    MMA_PROLOG();
    int m0 = blockIdx.y * 128;
    size_t aro = (size_t)(m0 + arow)*Cn + half_*16;
    size_t bro = (size_t)(blockIdx.x*128 + arow)*Cn + half_*16;
    mma_core<3>(sbase, A1 + aro, A2 + aro, A1 + aro, A2 + aro, Cn,
                B1 + bro, B2 + bro, Cn, tid, lane, wm, wn, acc);

    int mat = blockIdx.x >> 3;
    float* outp = (mat == 0) ? g_R : ((mat == 1) ? g_K : g_V);
    int cbase = (blockIdx.x & 7)*128 + wn*64;
#pragma unroll
    for (int mf = 0; mf < 2; mf++) {
        int r0 = m0 + wm*32 + mf*16 + (lane >> 2);
#pragma unroll
        for (int nf = 0; nf < 8; nf++) {
            int cc = cbase + nf*8 + (lane & 3)*2;
#pragma unroll
            for (int h = 0; h < 2; h++) {
                int r = r0 + h*8;
                float v0 = acc[mf][nf][h*2], v1 = acc[mf][nf][h*2 + 1];
                if (mat == 0) {
                    v0 = 1.f/(1.f + expf(-v0));
                    v1 = 1.f/(1.f + expf(-v1));
                }
                float* cr = outp + (size_t)r*Cn + cc;
                cr[0] = v0; cr[1] = v1;
            }
        }
    }
}

// ---------------- generic dense GEMM: MODE 0: C=acc  2: C+=acc ----------------
template<int MODE, int NP>
__global__ void __launch_bounds__(256, 2) gemm_mma(
    const __half* __restrict__ A1, const __half* __restrict__ A2,
    const __half* __restrict__ B1, const __half* __restrict__ B2,
    float* __restrict__ Cf, int K, int N)
{
    MMA_PROLOG();
    int m0 = blockIdx.y * 128;
    size_t aro = (size_t)(m0 + arow)*K + half_*16;
    size_t bro = (size_t)(blockIdx.x*128 + arow)*K + half_*16;
    mma_core<NP>(sbase, A1 + aro, A2 + aro, A1 + aro, A2 + aro, K,
                 B1 + bro, B2 + bro, K, tid, lane, wm, wn, acc);

    int cbase = blockIdx.x*128 + wn*64;
#pragma unroll
    for (int mf = 0; mf < 2; mf++) {
        int r0 = m0 + wm*32 + mf*16 + (lane >> 2);
#pragma unroll
        for (int nf = 0; nf < 8; nf++) {
            int cc = cbase + nf*8 + (lane & 3)*2;
#pragma unroll
            for (int h = 0; h < 2; h++) {
                int r = r0 + h*8;
                float v0 = acc[mf][nf][h*2], v1 = acc[mf][nf][h*2 + 1];
                float* cr = Cf + (size_t)r*N + cc;
                if (MODE == 2) { cr[0] += v0; cr[1] += v1; }
                else           { cr[0] = v0;  cr[1] = v1; }
            }
        }
    }
}

// ---------------- fused expert up-proj: grid(32, 32, 3); A row stride Cn, switch at ksw=Cn
struct UpArgs {
    const __half* A1[3]; const __half* A2[3];    // first-half A (stride Cn)
    const __half* A1b[3]; const __half* A2b[3];  // second-half A (stride Cn, k>=Cn)
    const __half* B1[3]; const __half* B2[3];
    int K[3];
};
__global__ void __launch_bounds__(256, 2) up3_mma(UpArgs ua) {
    int z = blockIdx.z;
    int Meff = g_CNT[z];
    int m0 = blockIdx.y * 128;
    if (m0 >= Meff) return;
    const int* rows = g_LIST + z*BT;
    int K = ua.K[z];

    MMA_PROLOG();
    int am = m0 + arow;
    int amc = (am < Meff) ? am : (Meff - 1);
    size_t aro = (size_t)rows[amc]*Cn + half_*16;
    size_t bro = (size_t)(blockIdx.x*128 + arow)*K + half_*16;
    mma_core<3>(sbase, ua.A1[z] + aro, ua.A2[z] + aro, ua.A1b[z] + aro, ua.A2b[z] + aro, Cn,
                ua.B1[z] + bro, ua.B2[z] + bro, K, tid, lane, wm, wn, acc);

    int cbase = blockIdx.x*128 + wn*64;
#pragma unroll
    for (int mf = 0; mf < 2; mf++) {
        int r0 = m0 + wm*32 + mf*16 + (lane >> 2);
#pragma unroll
        for (int nf = 0; nf < 8; nf++) {
            int cc = cbase + nf*8 + (lane & 3)*2;
#pragma unroll
            for (int h = 0; h < 2; h++) {
                int r = r0 + h*8;
                if (r >= Meff) continue;
                size_t o = (size_t)rows[r]*Hn + cc;
                float v0 = fmaxf(acc[mf][nf][h*2],     0.f);
                float v1 = fmaxf(acc[mf][nf][h*2 + 1], 0.f);
                split2(v0, g_HD1[o],   g_HD2[o]);
                split2(v1, g_HD1[o+1], g_HD2[o+1]);
            }
        }
    }
}

// ---------------- fused expert down-proj: grid(8, 32, 3) ----------------
struct DnArgs { const __half* B1[3]; const __half* B2[3]; };
__global__ void __launch_bounds__(256, 2) dn3_mma(DnArgs da) {
    int z = blockIdx.z;
    int Meff = g_CNT[z];
    int m0 = blockIdx.y * 128;
    if (m0 >= Meff) return;
    const int* rows = g_LIST + z*BT;

    MMA_PROLOG();
    int am = m0 + arow;
    int amc = (am < Meff) ? am : (Meff - 1);
    size_t aro = (size_t)rows[amc]*Hn + half_*16;
    size_t bro = (size_t)(blockIdx.x*128 + arow)*Hn + half_*16;
    mma_core<3>(sbase, g_HD1 + aro, g_HD2 + aro, g_HD1 + aro, g_HD2 + aro, Hn,
                da.B1[z] + bro, da.B2[z] + bro, Hn, tid, lane, wm, wn, acc);

    int cbase = blockIdx.x*128 + wn*64;
#pragma unroll
    for (int mf = 0; mf < 2; mf++) {
        int r0 = m0 + wm*32 + mf*16 + (lane >> 2);
#pragma unroll
        for (int nf = 0; nf < 8; nf++) {
            int cc = cbase + nf*8 + (lane & 3)*2;
#pragma unroll
            for (int h = 0; h < 2; h++) {
                int r = r0 + h*8;
                if (r >= Meff) continue;
                int tok = rows[r];
                float sc = g_SC[tok];
                float* xr = g_X + (size_t)tok*Cn + cc;
                xr[0] += acc[mf][nf][h*2]*sc;
                xr[1] += acc[mf][nf][h*2 + 1]*sc;
            }
        }
    }
}

// ---------------- embedding gather ----------------
__global__ void embed_k(const int* __restrict__ idx, const float* __restrict__ emb) {
    int i = blockIdx.x*blockDim.x + threadIdx.x;
    if (i >= BT*Cn) return;
    int row = i >> 10, c = i & 1023;
    g_X[i] = emb[(size_t)idx[row]*Cn + c];
}

// ---------------- fused ln1 + token-shift mix -> MX pair ----------------
__global__ void ln1mix_k(const float* __restrict__ in, const float* __restrict__ g,
                         const float* __restrict__ b) {
    int row = blockIdx.x;
    int t = row & (Tn - 1);
    const float* p = in + (size_t)row*Cn;
    const float* pp = in + (size_t)(row-1)*Cn;
    float v[4], u[4];
    float s = 0.f, ss = 0.f, su = 0.f, ssu = 0.f;
#pragma unroll
    for (int j = 0; j < 4; j++) {
        int c = threadIdx.x + j*256;
        v[j] = p[c];
        s += v[j]; ss += v[j]*v[j];
        u[j] = (t > 0) ? pp[c] : 0.f;
        su += u[j]; ssu += u[j]*u[j];
    }
#pragma unroll
    for (int o = 16; o > 0; o >>= 1) {
        s   += __shfl_xor_sync(0xffffffffu, s,   o);
        ss  += __shfl_xor_sync(0xffffffffu, ss,  o);
        su  += __shfl_xor_sync(0xffffffffu, su,  o);
        ssu += __shfl_xor_sync(0xffffffffu, ssu, o);
    }
    __shared__ float sh[4][8];
    int w = threadIdx.x >> 5;
    if ((threadIdx.x & 31) == 0) { sh[0][w] = s; sh[1][w] = ss; sh[2][w] = su; sh[3][w] = ssu; }
    __syncthreads();
    s = 0.f; ss = 0.f; su = 0.f; ssu = 0.f;
#pragma unroll
    for (int j = 0; j < 8; j++) { s += sh[0][j]; ss += sh[1][j]; su += sh[2][j]; ssu += sh[3][j]; }
    float mv = s*(1.f/Cn),  rv = rsqrtf(ss*(1.f/Cn) - mv*mv + 1e-5f);
    float mu = su*(1.f/Cn), ru = rsqrtf(ssu*(1.f/Cn) - mu*mu + 1e-5f);
#pragma unroll
    for (int j = 0; j < 4; j++) {
        int c = threadIdx.x + j*256;
        float hv = (v[j]-mv)*rv*g[c] + b[c];
        float hu = (t > 0) ? ((u[j]-mu)*ru*g[c] + b[c]) : 0.f;
        float mix = 0.5f*(hv + hu);
        size_t id = (size_t)row*Cn + c;
        split2(mix, g_MX1[id], g_MX2[id]);
    }
}

// ---------------- fused ln2 + route (or plain lnf) -> HB pair ----------------
template<bool ROUTE>
__global__ void ln2r_k(const float* __restrict__ in, const float* __restrict__ g,
                       const float* __restrict__ b,
                       __half* __restrict__ o1, __half* __restrict__ o2,
                       const float* __restrict__ wc, const float* __restrict__ wa,
                       const float* __restrict__ shp) {
    int row = blockIdx.x;
    const float* p = in + (size_t)row*Cn;
    float v[4];
    float s = 0.f, ss = 0.f;
#pragma unroll
    for (int j = 0; j < 4; j++) {
        v[j] = p[threadIdx.x + j*256];
        s += v[j]; ss += v[j]*v[j];
    }
#pragma unroll
    for (int o = 16; o > 0; o >>= 1) {
        s  += __shfl_xor_sync(0xffffffffu, s,  o);
        ss += __shfl_xor_sync(0xffffffffu, ss, o);
    }
    __shared__ float sh[2][8];
    int w = threadIdx.x >> 5;
    if ((threadIdx.x & 31) == 0) { sh[0][w] = s; sh[1][w] = ss; }
    __syncthreads();
    s = 0.f; ss = 0.f;
#pragma unroll
    for (int j = 0; j < 8; j++) { s += sh[0][j]; ss += sh[1][j]; }
    float mean = s * (1.f/Cn);
    float rstd = rsqrtf(ss*(1.f/Cn) - mean*mean + 1e-5f);

    float pq[6] = {0,0,0,0,0,0};
#pragma unroll
    for (int j = 0; j < 4; j++) {
        int c = threadIdx.x + j*256;
        float val = (v[j]-mean)*rstd*g[c] + b[c];
        size_t id = (size_t)row*Cn + c;
        split2(val, o1[id], o2[id]);
        if (ROUTE) {
            pq[0] += val*wc[c];
            pq[1] += val*wc[Cn + c];
            pq[2] += val*wc[2*Cn + c];
            pq[3] += val*wa[c*En + 0];
            pq[4] += val*wa[c*En + 1];
            pq[5] += val*wa[c*En + 2];
        }
    }
    if (ROUTE) {
#pragma unroll
        for (int o = 16; o > 0; o >>= 1)
#pragma unroll
            for (int q = 0; q < 6; q++) pq[q] += __shfl_xor_sync(0xffffffffu, pq[q], o);
        __shared__ float sm[8][6];
        if ((threadIdx.x & 31) == 0)
#pragma unroll
            for (int q = 0; q < 6; q++) sm[w][q] = pq[q];
        __syncthreads();
        if (threadIdx.x == 0) {
            float d[6];
#pragma unroll
            for (int q = 0; q < 6; q++) {
                d[q] = 0.f;
#pragma unroll
                for (int ww = 0; ww < 8; ww++) d[q] += sm[ww][q];
            }
            float best = -3.4e38f, wcf = 0.f;
            int wi = 0;
#pragma unroll
            for (int e = 0; e < En; e++) {
                float conf = 1.f/(1.f + expf(-d[e]));
                float bid  = conf*shp[e] + d[3+e];
                if (bid > best) { best = bid; wi = e; wcf = conf; }
            }
            g_SC[row] = wcf / (wcf + 1e-6f);
            int pos = atomicAdd(&g_CNT[wi], 1);
            g_LIST[wi*BT + pos] = row;
        }
    }
}

// ---------------- scan phase 1 (+ CNT zeroing for this layer's routing) ----------------
__global__ void scan1_k() {
    if (blockIdx.x == 0 && threadIdx.x < En) g_CNT[threadIdx.x] = 0;
    int i = blockIdx.x*blockDim.x + threadIdx.x;
    if (i >= Bsz*CH*Cn) return;
    int c  = i & 1023;
    int ch = (i >> 10) & (CH - 1);
    int b  = i >> 14;
    size_t base = (size_t)b*Tn*Cn + (size_t)ch*CL*Cn + c;
    float s = 0.f;
#pragma unroll 4
    for (int t = 0; t < CL; t++) {
        size_t id = base + (size_t)t*Cn;
        s += g_K[id]*g_V[id];
    }
    g_PART[i] = s;
}
// ---------------- scan phase 2+3 fused: inline chunk prefix, write SP pair + RS pair
__global__ void scan3_k() {
    int i = blockIdx.x*blockDim.x + threadIdx.x;
    if (i >= Bsz*CH*Cn) return;
    int c  = i & 1023;
    int ch = (i >> 10) & (CH - 1);
    int b  = i >> 14;
    float acc = 0.f;
    for (int j = 0; j < CH; j++)
        if (j < ch) acc += g_PART[((b*CH + j) << 10) | c];
    size_t base = (size_t)b*Tn*Cn + (size_t)ch*CL*Cn + c;
    int t0 = ch*CL;
#pragma unroll 4
    for (int t = 0; t < CL; t++) {
        size_t id = base + (size_t)t*Cn;
        acc += g_K[id]*g_V[id];
        float st = acc / (float)(t0 + t + 1);
        split2(st, g_SP1[id], g_SP2[id]);
        float rs = g_R[id]*st;
        split2(rs, g_MX1[id], g_MX2[id]);
    }
}

// ---------------- batched weight transpose+split ----------------
__global__ void tsplit_k(const float* __restrict__ W,
                         __half* __restrict__ o1, __half* __restrict__ o2,
                         int K, int N, size_t srcStride, size_t dstStride) {
    __shared__ __half s1[32][33], s2[32][33];
    int z = blockIdx.z;
    W  += (size_t)z*srcStride;
    o1 += (size_t)z*dstStride;
    o2 += (size_t)z*dstStride;
    int n0 = blockIdx.x*32, k0 = blockIdx.y*32;
    int tx = threadIdx.x, ty = threadIdx.y;
#pragma unroll
    for (int j = 0; j < 4; j++) {
        int k = k0 + ty + j*8;
        float v = W[(size_t)k*N + n0 + tx];
        split2(v, s1[ty+j*8][tx], s2[ty+j*8][tx]);
    }
    __syncthreads();
#pragma unroll
    for (int j = 0; j < 4; j++) {
        int n = n0 + ty + j*8;
        size_t o = (size_t)n*K + k0 + tx;
        o1[o] = s1[tx][ty+j*8];
        o2[o] = s2[tx][ty+j*8];
    }
}

// ---------------- launch ----------------
extern "C" void kernel_launch(void* const* d_in, const int* in_sizes, int n_in,
                              void* d_out, int out_size)
{
    const int*   idx   = (const int*)  d_in[0];
    const float* shares= (const float*)d_in[1];
    const float* emb   = (const float*)d_in[2];
    const float* ln1g  = (const float*)d_in[3];
    const float* ln1b  = (const float*)d_in[4];
    const float* ln2g  = (const float*)d_in[5];
    const float* ln2b  = (const float*)d_in[6];
    const float* Wr    = (const float*)d_in[7];
    const float* Wk    = (const float*)d_in[8];
    const float* Wv    = (const float*)d_in[9];
    const float* Wo    = (const float*)d_in[10];
    const float* W1    = (const float*)d_in[11];
    const float* W2    = (const float*)d_in[12];
    const float* wconf = (const float*)d_in[13];
    const float* Wl1   = (const float*)d_in[14];
    const float* Wl2   = (const float*)d_in[15];
    const float* Waff  = (const float*)d_in[17];
    const float* lnfg  = (const float*)d_in[18];
    const float* lnfb  = (const float*)d_in[19];
    const float* headW = (const float*)d_in[20];
    float* out = (float*)d_out;
    (void)in_sizes; (void)n_in; (void)out_size;

    float *X;
    __half *MX1,*MX2, *SP1,*SP2, *HB1,*HB2, *WT1,*WT2;
    cudaGetSymbolAddress((void**)&X,   g_X);
    cudaGetSymbolAddress((void**)&MX1, g_MX1); cudaGetSymbolAddress((void**)&MX2, g_MX2);
    cudaGetSymbolAddress((void**)&SP1, g_SP1); cudaGetSymbolAddress((void**)&SP2, g_SP2);
    cudaGetSymbolAddress((void**)&HB1, g_HB1); cudaGetSymbolAddress((void**)&HB2, g_HB2);
    cudaGetSymbolAddress((void**)&WT1, g_WT1); cudaGetSymbolAddress((void**)&WT2, g_WT2);

    cudaFuncSetAttribute(rkv_mma,        cudaFuncAttributeMaxDynamicSharedMemorySize, SMEMB);
    cudaFuncSetAttribute(gemm_mma<2,3>,  cudaFuncAttributeMaxDynamicSharedMemorySize, SMEMB);
    cudaFuncSetAttribute(gemm_mma<0,2>,  cudaFuncAttributeMaxDynamicSharedMemorySize, SMEMB);
    cudaFuncSetAttribute(up3_mma,        cudaFuncAttributeMaxDynamicSharedMemorySize, SMEMB);
    cudaFuncSetAttribute(dn3_mma,        cudaFuncAttributeMaxDynamicSharedMemorySize, SMEMB);

    dim3 tb(32, 8);
    // arena per layer: Wr@0 Wk@CC Wv@2CC Wo@3CC | W1e0@4CC W1e1@8CC | W2e0@12CC W2e1@16CC | Wl1@20CC Wl2@28CC
    tsplit_k<<<dim3(Cn/32, Cn/32, Ln), tb>>>(Wr, WT1,              WT2,              Cn, Cn, CC, WPL);
    tsplit_k<<<dim3(Cn/32, Cn/32, Ln), tb>>>(Wk, WT1+CC,           WT2+CC,           Cn, Cn, CC, WPL);
    tsplit_k<<<dim3(Cn/32, Cn/32, Ln), tb>>>(Wv, WT1+2*(size_t)CC, WT2+2*(size_t)CC, Cn, Cn, CC, WPL);
    tsplit_k<<<dim3(Cn/32, Cn/32, Ln), tb>>>(Wo, WT1+3*(size_t)CC, WT2+3*(size_t)CC, Cn, Cn, CC, WPL);
    tsplit_k<<<dim3(Hn/32, Cn/32, Ln), tb>>>(W1,                 WT1+4*(size_t)CC,  WT2+4*(size_t)CC,  Cn, Hn, 2*(size_t)Cn*Hn, WPL);
    tsplit_k<<<dim3(Hn/32, Cn/32, Ln), tb>>>(W1 + (size_t)Cn*Hn, WT1+8*(size_t)CC,  WT2+8*(size_t)CC,  Cn, Hn, 2*(size_t)Cn*Hn, WPL);
    tsplit_k<<<dim3(Cn/32, Hn/32, Ln), tb>>>(W2,                 WT1+12*(size_t)CC, WT2+12*(size_t)CC, Hn, Cn, 2*(size_t)Hn*Cn, WPL);
    tsplit_k<<<dim3(Cn/32, Hn/32, Ln), tb>>>(W2 + (size_t)Hn*Cn, WT1+16*(size_t)CC, WT2+16*(size_t)CC, Hn, Cn, 2*(size_t)Hn*Cn, WPL);
    tsplit_k<<<dim3(Hn/32, 2*Cn/32, Ln), tb>>>(Wl1, WT1+20*(size_t)CC, WT2+20*(size_t)CC, 2*Cn, Hn, 2*(size_t)Cn*Hn, WPL);
    tsplit_k<<<dim3(Cn/32, Hn/32, Ln), tb>>>(Wl2, WT1+28*(size_t)CC, WT2+28*(size_t)CC, Hn, Cn, (size_t)Hn*Cn, WPL);
    tsplit_k<<<dim3(Vn/32, Cn/32, 1), tb>>>(headW, WT1+WHEAD, WT2+WHEAD, Cn, Vn, 0, 0);

    embed_k<<<(BT*Cn)/256, 256>>>(idx, emb);

    for (int l = 0; l < Ln; l++) {
        size_t LB = (size_t)l*WPL;
        ln1mix_k<<<BT, 256>>>(X, ln1g + (size_t)l*Cn, ln1b + (size_t)l*Cn);

        rkv_mma<<<dim3(24, 32), 256, SMEMB>>>(MX1, MX2, WT1+LB, WT2+LB);

        scan1_k<<<(Bsz*CH*Cn)/256, 256>>>();   // also zeroes CNT for this layer
        scan3_k<<<(Bsz*CH*Cn)/256, 256>>>();

        gemm_mma<2,3><<<dim3(8, 32), 256, SMEMB>>>(MX1, MX2, WT1+LB+3*(size_t)CC, WT2+LB+3*(size_t)CC, X, Cn, Cn);

        ln2r_k<true><<<BT, 256>>>(X, ln2g + (size_t)l*Cn, ln2b + (size_t)l*Cn, HB1, HB2,
                                  wconf + (size_t)l*En*Cn, Waff + (size_t)l*Cn*En,
                                  shares + (size_t)l*En);

        UpArgs ua;
        DnArgs da;
        for (int e = 0; e < 2; e++) {
            size_t o1 = LB + (4 + 4*e)*(size_t)CC;
            size_t o2 = LB + (12 + 4*e)*(size_t)CC;
            ua.A1[e] = HB1; ua.A2[e] = HB2;
            ua.A1b[e] = HB1; ua.A2b[e] = HB2;   // unused (K=Cn)
            ua.B1[e] = WT1 + o1; ua.B2[e] = WT2 + o1;
            ua.K[e] = Cn;
            da.B1[e] = WT1 + o2; da.B2[e] = WT2 + o2;
        }
        ua.A1[2] = HB1; ua.A2[2] = HB2;
        ua.A1b[2] = SP1; ua.A2b[2] = SP2;       // second half of hz = state pair
        ua.B1[2] = WT1 + LB + 20*(size_t)CC; ua.B2[2] = WT2 + LB + 20*(size_t)CC;
        ua.K[2] = 2*Cn;
        da.B1[2] = WT1 + LB + 28*(size_t)CC; da.B2[2] = WT2 + LB + 28*(size_t)CC;

        up3_mma<<<dim3(32, 32, 3), 256, SMEMB>>>(ua);
        dn3_mma<<<dim3(8, 32, 3), 256, SMEMB>>>(da);
    }

    ln2r_k<false><<<BT, 256>>>(X, lnfg, lnfb, HB1, HB2, nullptr, nullptr, nullptr);
    gemm_mma<0,2><<<dim3(Vn/128, BT/128), 256, SMEMB>>>(HB1, HB2, WT1+WHEAD, WT2+WHEAD, out, Cn, Vn);
}

// round 11
// speedup vs baseline: 3.8595x; 1.1223x over previous
#include <cuda_runtime.h>
#include <cuda_fp16.h>
#include <math.h>
#include <stdint.h>

// ---------------- dims ----------------
#define Bsz 2
#define Tn  2048
#define Cn  1024
#define Vn  32000
#define Ln  4
#define En  3
#define Hn  4096
#define BT  (Bsz*Tn)
#define CH  16
#define CL  (Tn/CH)
#define KC  32

#define CC  (Cn*Cn)
#define WPL (32*CC)
#define WHEAD ((size_t)4*WPL)
#define WTOT  ((size_t)4*WPL + (size_t)Cn*Vn)

#define TILE_B 8192
#define STAGE_B (4*TILE_B)
#define SMEMB (3*STAGE_B)               // 96KB, 3-stage -> 2 CTAs/SM

// ---------------- scratch ----------------
__device__ float g_X  [BT*Cn];
__device__ float g_R  [BT*Cn];
__device__ float g_K  [BT*Cn];
__device__ float g_V  [BT*Cn];
__device__ float g_SC [BT];
__device__ float g_PART[Bsz*CH*Cn];
__device__ int   g_CNT[En];
__device__ int   g_LIST[En*BT];

__device__ __half g_MX1[BT*Cn], g_MX2[BT*Cn];           // mix, then rs
__device__ __half g_SP1[BT*Cn], g_SP2[BT*Cn];           // rwkv state pair
__device__ __half g_HB1[BT*Cn], g_HB2[BT*Cn];           // h pair
__device__ __half g_HD1[(size_t)BT*Hn], g_HD2[(size_t)BT*Hn];
__device__ __half g_WT1[WTOT], g_WT2[WTOT];

// ---------------- helpers ----------------
__device__ __forceinline__ void split2(float v, __half& h1, __half& h2) {
    h1 = __float2half_rn(v);
    float r = v - __half2float(h1);
    h2 = __float2half_rn(r);
}
__device__ __forceinline__ uint32_t smem_u32(const void* p) {
    uint32_t a;
    asm("{ .reg .u64 t; cvta.to.shared.u64 t, %1; cvt.u32.u64 %0, t; }" : "=r"(a) : "l"(p));
    return a;
}
#define CP16(dst, src) asm volatile("cp.async.cg.shared.global [%0], [%1], 16;" :: "r"(dst), "l"(src) : "memory")
#define CP_COMMIT()    asm volatile("cp.async.commit_group;" ::: "memory")
#define CP_WAIT1()     asm volatile("cp.async.wait_group 1;" ::: "memory")
#define CP_WAIT0()     asm volatile("cp.async.wait_group 0;" ::: "memory")
#define LDSM4(r, a) \
    asm volatile("ldmatrix.sync.aligned.m8n8.x4.shared.b16 {%0,%1,%2,%3}, [%4];" \
        : "=r"((r)[0]), "=r"((r)[1]), "=r"((r)[2]), "=r"((r)[3]) : "r"(a))
#define MMA16816(d, a, b0v, b1v) \
    asm volatile("mma.sync.aligned.m16n8k16.row.col.f32.f16.f16.f32 " \
        "{%0,%1,%2,%3}, {%4,%5,%6,%7}, {%8,%9}, {%0,%1,%2,%3};" \
        : "+f"((d)[0]), "+f"((d)[1]), "+f"((d)[2]), "+f"((d)[3]) \
        : "r"((a)[0]), "r"((a)[1]), "r"((a)[2]), "r"((a)[3]), "r"(b0v), "r"(b1v))
__device__ __forceinline__ uint32_t sw64(uint32_t o) { return o ^ ((o >> 2) & 0x30); }

// ---------------- GEMM core: products {A1B1,A2B1,A1B2} (NP=3) or {A1B1,A2B1} (NP=2)
// 3-stage cp.async pipeline, ONE barrier per chunk. A source switches to (a1b,a2b)
// at k >= ksw (chunk-aligned). Pointers include row+half offsets.
template<int NP>
__device__ __forceinline__ void mma_core(
    uint32_t sbase,
    const __half* a1, const __half* a2, const __half* a1b, const __half* a2b, int ksw,
    const __half* b1, const __half* b2,
    int K, int tid, int lane, int wm, int wn, float acc[2][8][4])
{
    int arow = tid >> 1, half_ = tid & 1;
    uint32_t so[2];
#pragma unroll
    for (int q = 0; q < 2; q++)
        so[q] = sw64(arow*64 + half_*32 + q*16);

    const int NT = (NP == 3) ? 4 : 3;
    int nc = K / KC;

    auto issue = [&](int c, uint32_t sb) {
        int k0 = c*KC;
        const __half* s0 = (k0 < ksw) ? a1 + k0 : a1b + (k0 - ksw);
        const __half* s1 = (k0 < ksw) ? a2 + k0 : a2b + (k0 - ksw);
        const __half* srcs[4] = {s0, s1, b1 + k0, b2 + k0};
#pragma unroll
        for (int t = 0; t < 4; t++) {
            if (t >= NT) break;
#pragma unroll
            for (int q = 0; q < 2; q++)
                CP16(sb + t*TILE_B + so[q], srcs[t] + q*8);
        }
        CP_COMMIT();
    };

    issue(0, sbase);
    if (nc > 1) issue(1, sbase + STAGE_B);

    for (int c = 0; c < nc; c++) {
        if (c + 1 < nc) CP_WAIT1();
        else            CP_WAIT0();
        __syncthreads();   // single barrier per chunk (3-stage makes trailing sync redundant)

        uint32_t stg = sbase + (uint32_t)(c % 3)*STAGE_B;
#pragma unroll
        for (int ks = 0; ks < 2; ks++) {
            // hoist ALL A fragments for this k16-slab: A1,A2 x mf0,1
            uint32_t afr[2][2][4];
#pragma unroll
            for (int as_ = 0; as_ < 2; as_++)
#pragma unroll
                for (int mf = 0; mf < 2; mf++) {
                    uint32_t r  = wm*32 + mf*16 + (lane & 7) + ((lane & 8) ? 8 : 0);
                    uint32_t of = ks*32 + ((lane & 16) ? 16 : 0);
                    LDSM4(afr[as_][mf], stg + as_*TILE_B + sw64(r*64 + of));
                }
            // B1 fragments; B frag mapping: row select lane&16, k-offset lane&8 (differs from A!)
            uint32_t bfr[4][4];
#pragma unroll
            for (int nq = 0; nq < 4; nq++) {
                uint32_t r  = wn*64 + nq*16 + (lane & 7) + ((lane & 16) ? 8 : 0);
                uint32_t of = ks*32 + ((lane & 8) ? 16 : 0);
                LDSM4(bfr[nq], stg + 2*TILE_B + sw64(r*64 + of));
            }
            // A1*B1 then A2*B1 (same order as before)
#pragma unroll
            for (int as_ = 0; as_ < 2; as_++)
#pragma unroll
                for (int mf = 0; mf < 2; mf++)
#pragma unroll
                    for (int nf = 0; nf < 8; nf++)
                        MMA16816(acc[mf][nf], afr[as_][mf], bfr[nf>>1][(nf&1)*2], bfr[nf>>1][(nf&1)*2 + 1]);
            if (NP == 3) {
                // B2 fragments, A1*B2
#pragma unroll
                for (int nq = 0; nq < 4; nq++) {
                    uint32_t r  = wn*64 + nq*16 + (lane & 7) + ((lane & 16) ? 8 : 0);
                    uint32_t of = ks*32 + ((lane & 8) ? 16 : 0);
                    LDSM4(bfr[nq], stg + 3*TILE_B + sw64(r*64 + of));
                }
#pragma unroll
                for (int mf = 0; mf < 2; mf++)
#pragma unroll
                    for (int nf = 0; nf < 8; nf++)
                        MMA16816(acc[mf][nf], afr[0][mf], bfr[nf>>1][(nf&1)*2], bfr[nf>>1][(nf&1)*2 + 1]);
            }
        }
        if (c + 2 < nc) issue(c + 2, sbase + (uint32_t)((c + 2) % 3)*STAGE_B);
    }
}

#define MMA_PROLOG() \
    extern __shared__ char smem[]; \
    uint32_t sbase = smem_u32(smem); \
    int tid = threadIdx.x, lane = tid & 31, wid = tid >> 5; \
    int wm = wid & 3, wn = wid >> 2; \
    int arow = tid >> 1, half_ = tid & 1; \
    float acc[2][8][4]; \
    _Pragma("unroll") for (int i = 0; i < 2; i++) \
    _Pragma("unroll") for (int j = 0; j < 8; j++) \
    _Pragma("unroll") for (int q = 0; q < 4; q++) acc[i][j][q] = 0.f;

// ---------------- fused r/k/v GEMM: grid(24, 32) ----------------
__global__ void __launch_bounds__(256, 2) rkv_mma(
    const __half* __restrict__ A1, const __half* __restrict__ A2,
    const __half* __restrict__ B1, const __half* __restrict__ B2)
{
    MMA_PROLOG();
    int m0 = blockIdx.y * 128;
    size_t aro = (size_t)(m0 + arow)*Cn + half_*16;
    size_t bro = (size_t)(blockIdx.x*128 + arow)*Cn + half_*16;
    mma_core<3>(sbase, A1 + aro, A2 + aro, A1 + aro, A2 + aro, Cn,
                B1 + bro, B2 + bro, Cn, tid, lane, wm, wn, acc);

    int mat = blockIdx.x >> 3;
    float* outp = (mat == 0) ? g_R : ((mat == 1) ? g_K : g_V);
    int cbase = (blockIdx.x & 7)*128 + wn*64;
#pragma unroll
    for (int mf = 0; mf < 2; mf++) {
        int r0 = m0 + wm*32 + mf*16 + (lane >> 2);
#pragma unroll
        for (int nf = 0; nf < 8; nf++) {
            int cc = cbase + nf*8 + (lane & 3)*2;
#pragma unroll
            for (int h = 0; h < 2; h++) {
                int r = r0 + h*8;
                float v0 = acc[mf][nf][h*2], v1 = acc[mf][nf][h*2 + 1];
                if (mat == 0) {
                    v0 = 1.f/(1.f + expf(-v0));
                    v1 = 1.f/(1.f + expf(-v1));
                }
                float* cr = outp + (size_t)r*Cn + cc;
                cr[0] = v0; cr[1] = v1;
            }
        }
    }
}

// ---------------- generic dense GEMM: MODE 0: C=acc  2: C+=acc ----------------
template<int MODE, int NP>
__global__ void __launch_bounds__(256, 2) gemm_mma(
    const __half* __restrict__ A1, const __half* __restrict__ A2,
    const __half* __restrict__ B1, const __half* __restrict__ B2,
    float* __restrict__ Cf, int K, int N)
{
    MMA_PROLOG();
    int m0 = blockIdx.y * 128;
    size_t aro = (size_t)(m0 + arow)*K + half_*16;
    size_t bro = (size_t)(blockIdx.x*128 + arow)*K + half_*16;
    mma_core<NP>(sbase, A1 + aro, A2 + aro, A1 + aro, A2 + aro, K,
                 B1 + bro, B2 + bro, K, tid, lane, wm, wn, acc);

    int cbase = blockIdx.x*128 + wn*64;
#pragma unroll
    for (int mf = 0; mf < 2; mf++) {
        int r0 = m0 + wm*32 + mf*16 + (lane >> 2);
#pragma unroll
        for (int nf = 0; nf < 8; nf++) {
            int cc = cbase + nf*8 + (lane & 3)*2;
#pragma unroll
            for (int h = 0; h < 2; h++) {
                int r = r0 + h*8;
                float v0 = acc[mf][nf][h*2], v1 = acc[mf][nf][h*2 + 1];
                float* cr = Cf + (size_t)r*N + cc;
                if (MODE == 2) { cr[0] += v0; cr[1] += v1; }
                else           { cr[0] = v0;  cr[1] = v1; }
            }
        }
    }
}

// ---------------- fused expert up-proj: grid(32, 32, 3); A row stride Cn, switch at ksw=Cn
struct UpArgs {
    const __half* A1[3]; const __half* A2[3];
    const __half* A1b[3]; const __half* A2b[3];
    const __half* B1[3]; const __half* B2[3];
    int K[3];
};
__global__ void __launch_bounds__(256, 2) up3_mma(UpArgs ua) {
    int z = blockIdx.z;
    int Meff = g_CNT[z];
    int m0 = blockIdx.y * 128;
    if (m0 >= Meff) return;
    const int* rows = g_LIST + z*BT;
    int K = ua.K[z];

    MMA_PROLOG();
    int am = m0 + arow;
    int amc = (am < Meff) ? am : (Meff - 1);
    size_t aro = (size_t)rows[amc]*Cn + half_*16;
    size_t bro = (size_t)(blockIdx.x*128 + arow)*K + half_*16;
    mma_core<3>(sbase, ua.A1[z] + aro, ua.A2[z] + aro, ua.A1b[z] + aro, ua.A2b[z] + aro, Cn,
                ua.B1[z] + bro, ua.B2[z] + bro, K, tid, lane, wm, wn, acc);

    int cbase = blockIdx.x*128 + wn*64;
#pragma unroll
    for (int mf = 0; mf < 2; mf++) {
        int r0 = m0 + wm*32 + mf*16 + (lane >> 2);
#pragma unroll
        for (int nf = 0; nf < 8; nf++) {
            int cc = cbase + nf*8 + (lane & 3)*2;
#pragma unroll
            for (int h = 0; h < 2; h++) {
                int r = r0 + h*8;
                if (r >= Meff) continue;
                size_t o = (size_t)rows[r]*Hn + cc;
                float v0 = fmaxf(acc[mf][nf][h*2],     0.f);
                float v1 = fmaxf(acc[mf][nf][h*2 + 1], 0.f);
                split2(v0, g_HD1[o],   g_HD2[o]);
                split2(v1, g_HD1[o+1], g_HD2[o+1]);
            }
        }
    }
}

// ---------------- fused expert down-proj: grid(8, 32, 3) ----------------
struct DnArgs { const __half* B1[3]; const __half* B2[3]; };
__global__ void __launch_bounds__(256, 2) dn3_mma(DnArgs da) {
    int z = blockIdx.z;
    int Meff = g_CNT[z];
    int m0 = blockIdx.y * 128;
    if (m0 >= Meff) return;
    const int* rows = g_LIST + z*BT;

    MMA_PROLOG();
    int am = m0 + arow;
    int amc = (am < Meff) ? am : (Meff - 1);
    size_t aro = (size_t)rows[amc]*Hn + half_*16;
    size_t bro = (size_t)(blockIdx.x*128 + arow)*Hn + half_*16;
    mma_core<3>(sbase, g_HD1 + aro, g_HD2 + aro, g_HD1 + aro, g_HD2 + aro, Hn,
                da.B1[z] + bro, da.B2[z] + bro, Hn, tid, lane, wm, wn, acc);

    int cbase = blockIdx.x*128 + wn*64;
#pragma unroll
    for (int mf = 0; mf < 2; mf++) {
        int r0 = m0 + wm*32 + mf*16 + (lane >> 2);
#pragma unroll
        for (int nf = 0; nf < 8; nf++) {
            int cc = cbase + nf*8 + (lane & 3)*2;
#pragma unroll
            for (int h = 0; h < 2; h++) {
                int r = r0 + h*8;
                if (r >= Meff) continue;
                int tok = rows[r];
                float sc = g_SC[tok];
                float* xr = g_X + (size_t)tok*Cn + cc;
                xr[0] += acc[mf][nf][h*2]*sc;
                xr[1] += acc[mf][nf][h*2 + 1]*sc;
            }
        }
    }
}

// ---------------- embedding gather ----------------
__global__ void embed_k(const int* __restrict__ idx, const float* __restrict__ emb) {
    int i = blockIdx.x*blockDim.x + threadIdx.x;
    if (i >= BT*Cn) return;
    int row = i >> 10, c = i & 1023;
    g_X[i] = emb[(size_t)idx[row]*Cn + c];
}

// ---------------- fused ln1 + token-shift mix -> MX pair ----------------
__global__ void ln1mix_k(const float* __restrict__ in, const float* __restrict__ g,
                         const float* __restrict__ b) {
    int row = blockIdx.x;
    int t = row & (Tn - 1);
    const float* p = in + (size_t)row*Cn;
    const float* pp = in + (size_t)(row-1)*Cn;
    float v[4], u[4];
    float s = 0.f, ss = 0.f, su = 0.f, ssu = 0.f;
#pragma unroll
    for (int j = 0; j < 4; j++) {
        int c = threadIdx.x + j*256;
        v[j] = p[c];
        s += v[j]; ss += v[j]*v[j];
        u[j] = (t > 0) ? pp[c] : 0.f;
        su += u[j]; ssu += u[j]*u[j];
    }
#pragma unroll
    for (int o = 16; o > 0; o >>= 1) {
        s   += __shfl_xor_sync(0xffffffffu, s,   o);
        ss  += __shfl_xor_sync(0xffffffffu, ss,  o);
        su  += __shfl_xor_sync(0xffffffffu, su,  o);
        ssu += __shfl_xor_sync(0xffffffffu, ssu, o);
    }
    __shared__ float sh[4][8];
    int w = threadIdx.x >> 5;
    if ((threadIdx.x & 31) == 0) { sh[0][w] = s; sh[1][w] = ss; sh[2][w] = su; sh[3][w] = ssu; }
    __syncthreads();
    s = 0.f; ss = 0.f; su = 0.f; ssu = 0.f;
#pragma unroll
    for (int j = 0; j < 8; j++) { s += sh[0][j]; ss += sh[1][j]; su += sh[2][j]; ssu += sh[3][j]; }
    float mv = s*(1.f/Cn),  rv = rsqrtf(ss*(1.f/Cn) - mv*mv + 1e-5f);
    float mu = su*(1.f/Cn), ru = rsqrtf(ssu*(1.f/Cn) - mu*mu + 1e-5f);
#pragma unroll
    for (int j = 0; j < 4; j++) {
        int c = threadIdx.x + j*256;
        float hv = (v[j]-mv)*rv*g[c] + b[c];
        float hu = (t > 0) ? ((u[j]-mu)*ru*g[c] + b[c]) : 0.f;
        float mix = 0.5f*(hv + hu);
        size_t id = (size_t)row*Cn + c;
        split2(mix, g_MX1[id], g_MX2[id]);
    }
}

// ---------------- fused ln2 + route (or plain lnf) -> HB pair ----------------
template<bool ROUTE>
__global__ void ln2r_k(const float* __restrict__ in, const float* __restrict__ g,
                       const float* __restrict__ b,
                       __half* __restrict__ o1, __half* __restrict__ o2,
                       const float* __restrict__ wc, const float* __restrict__ wa,
                       const float* __restrict__ shp) {
    int row = blockIdx.x;
    const float* p = in + (size_t)row*Cn;
    float v[4];
    float s = 0.f, ss = 0.f;
#pragma unroll
    for (int j = 0; j < 4; j++) {
        v[j] = p[threadIdx.x + j*256];
        s += v[j]; ss += v[j]*v[j];
    }
#pragma unroll
    for (int o = 16; o > 0; o >>= 1) {
        s  += __shfl_xor_sync(0xffffffffu, s,  o);
        ss += __shfl_xor_sync(0xffffffffu, ss, o);
    }
    __shared__ float sh[2][8];
    int w = threadIdx.x >> 5;
    if ((threadIdx.x & 31) == 0) { sh[0][w] = s; sh[1][w] = ss; }
    __syncthreads();
    s = 0.f; ss = 0.f;
#pragma unroll
    for (int j = 0; j < 8; j++) { s += sh[0][j]; ss += sh[1][j]; }
    float mean = s * (1.f/Cn);
    float rstd = rsqrtf(ss*(1.f/Cn) - mean*mean + 1e-5f);

    float pq[6] = {0,0,0,0,0,0};
#pragma unroll
    for (int j = 0; j < 4; j++) {
        int c = threadIdx.x + j*256;
        float val = (v[j]-mean)*rstd*g[c] + b[c];
        size_t id = (size_t)row*Cn + c;
        split2(val, o1[id], o2[id]);
        if (ROUTE) {
            pq[0] += val*wc[c];
            pq[1] += val*wc[Cn + c];
            pq[2] += val*wc[2*Cn + c];
            pq[3] += val*wa[c*En + 0];
            pq[4] += val*wa[c*En + 1];
            pq[5] += val*wa[c*En + 2];
        }
    }
    if (ROUTE) {
#pragma unroll
        for (int o = 16; o > 0; o >>= 1)
#pragma unroll
            for (int q = 0; q < 6; q++) pq[q] += __shfl_xor_sync(0xffffffffu, pq[q], o);
        __shared__ float sm[8][6];
        if ((threadIdx.x & 31) == 0)
#pragma unroll
            for (int q = 0; q < 6; q++) sm[w][q] = pq[q];
        __syncthreads();
        if (threadIdx.x == 0) {
            float d[6];
#pragma unroll
            for (int q = 0; q < 6; q++) {
                d[q] = 0.f;
#pragma unroll
                for (int ww = 0; ww < 8; ww++) d[q] += sm[ww][q];
            }
            float best = -3.4e38f, wcf = 0.f;
            int wi = 0;
#pragma unroll
            for (int e = 0; e < En; e++) {
                float conf = 1.f/(1.f + expf(-d[e]));
                float bid  = conf*shp[e] + d[3+e];
                if (bid > best) { best = bid; wi = e; wcf = conf; }
            }
            g_SC[row] = wcf / (wcf + 1e-6f);
            int pos = atomicAdd(&g_CNT[wi], 1);
            g_LIST[wi*BT + pos] = row;
        }
    }
}

// ---------------- scan phase 1 (+ CNT zeroing for this layer's routing) ----------------
__global__ void scan1_k() {
    if (blockIdx.x == 0 && threadIdx.x < En) g_CNT[threadIdx.x] = 0;
    int i = blockIdx.x*blockDim.x + threadIdx.x;
    if (i >= Bsz*CH*Cn) return;
    int c  = i & 1023;
    int ch = (i >> 10) & (CH - 1);
    int b  = i >> 14;
    size_t base = (size_t)b*Tn*Cn + (size_t)ch*CL*Cn + c;
    float s = 0.f;
#pragma unroll 4
    for (int t = 0; t < CL; t++) {
        size_t id = base + (size_t)t*Cn;
        s += g_K[id]*g_V[id];
    }
    g_PART[i] = s;
}
// ---------------- scan phase 2+3 fused ----------------
__global__ void scan3_k() {
    int i = blockIdx.x*blockDim.x + threadIdx.x;
    if (i >= Bsz*CH*Cn) return;
    int c  = i & 1023;
    int ch = (i >> 10) & (CH - 1);
    int b  = i >> 14;
    float acc = 0.f;
    for (int j = 0; j < CH; j++)
        if (j < ch) acc += g_PART[((b*CH + j) << 10) | c];
    size_t base = (size_t)b*Tn*Cn + (size_t)ch*CL*Cn + c;
    int t0 = ch*CL;
#pragma unroll 4
    for (int t = 0; t < CL; t++) {
        size_t id = base + (size_t)t*Cn;
        acc += g_K[id]*g_V[id];
        float st = acc / (float)(t0 + t + 1);
        split2(st, g_SP1[id], g_SP2[id]);
        float rs = g_R[id]*st;
        split2(rs, g_MX1[id], g_MX2[id]);
    }
}

// ---------------- batched weight transpose+split ----------------
__global__ void tsplit_k(const float* __restrict__ W,
                         __half* __restrict__ o1, __half* __restrict__ o2,
                         int K, int N, size_t srcStride, size_t dstStride) {
    __shared__ __half s1[32][33], s2[32][33];
    int z = blockIdx.z;
    W  += (size_t)z*srcStride;
    o1 += (size_t)z*dstStride;
    o2 += (size_t)z*dstStride;
    int n0 = blockIdx.x*32, k0 = blockIdx.y*32;
    int tx = threadIdx.x, ty = threadIdx.y;
#pragma unroll
    for (int j = 0; j < 4; j++) {
        int k = k0 + ty + j*8;
        float v = W[(size_t)k*N + n0 + tx];
        split2(v, s1[ty+j*8][tx], s2[ty+j*8][tx]);
    }
    __syncthreads();
#pragma unroll
    for (int j = 0; j < 4; j++) {
        int n = n0 + ty + j*8;
        size_t o = (size_t)n*K + k0 + tx;
        o1[o] = s1[tx][ty+j*8];
        o2[o] = s2[tx][ty+j*8];
    }
}

// ---------------- launch ----------------
extern "C" void kernel_launch(void* const* d_in, const int* in_sizes, int n_in,
                              void* d_out, int out_size)
{
    const int*   idx   = (const int*)  d_in[0];
    const float* shares= (const float*)d_in[1];
    const float* emb   = (const float*)d_in[2];
    const float* ln1g  = (const float*)d_in[3];
    const float* ln1b  = (const float*)d_in[4];
    const float* ln2g  = (const float*)d_in[5];
    const float* ln2b  = (const float*)d_in[6];
    const float* Wr    = (const float*)d_in[7];
    const float* Wk    = (const float*)d_in[8];
    const float* Wv    = (const float*)d_in[9];
    const float* Wo    = (const float*)d_in[10];
    const float* W1    = (const float*)d_in[11];
    const float* W2    = (const float*)d_in[12];
    const float* wconf = (const float*)d_in[13];
    const float* Wl1   = (const float*)d_in[14];
    const float* Wl2   = (const float*)d_in[15];
    const float* Waff  = (const float*)d_in[17];
    const float* lnfg  = (const float*)d_in[18];
    const float* lnfb  = (const float*)d_in[19];
    const float* headW = (const float*)d_in[20];
    float* out = (float*)d_out;
    (void)in_sizes; (void)n_in; (void)out_size;

    float *X;
    __half *MX1,*MX2, *SP1,*SP2, *HB1,*HB2, *WT1,*WT2;
    cudaGetSymbolAddress((void**)&X,   g_X);
    cudaGetSymbolAddress((void**)&MX1, g_MX1); cudaGetSymbolAddress((void**)&MX2, g_MX2);
    cudaGetSymbolAddress((void**)&SP1, g_SP1); cudaGetSymbolAddress((void**)&SP2, g_SP2);
    cudaGetSymbolAddress((void**)&HB1, g_HB1); cudaGetSymbolAddress((void**)&HB2, g_HB2);
    cudaGetSymbolAddress((void**)&WT1, g_WT1); cudaGetSymbolAddress((void**)&WT2, g_WT2);

    cudaFuncSetAttribute(rkv_mma,        cudaFuncAttributeMaxDynamicSharedMemorySize, SMEMB);
    cudaFuncSetAttribute(gemm_mma<2,3>,  cudaFuncAttributeMaxDynamicSharedMemorySize, SMEMB);
    cudaFuncSetAttribute(gemm_mma<0,2>,  cudaFuncAttributeMaxDynamicSharedMemorySize, SMEMB);
    cudaFuncSetAttribute(up3_mma,        cudaFuncAttributeMaxDynamicSharedMemorySize, SMEMB);
    cudaFuncSetAttribute(dn3_mma,        cudaFuncAttributeMaxDynamicSharedMemorySize, SMEMB);

    dim3 tb(32, 8);
    // arena per layer: Wr@0 Wk@CC Wv@2CC Wo@3CC | W1e0@4CC W1e1@8CC | W2e0@12CC W2e1@16CC | Wl1@20CC Wl2@28CC
    tsplit_k<<<dim3(Cn/32, Cn/32, Ln), tb>>>(Wr, WT1,              WT2,              Cn, Cn, CC, WPL);
    tsplit_k<<<dim3(Cn/32, Cn/32, Ln), tb>>>(Wk, WT1+CC,           WT2+CC,           Cn, Cn, CC, WPL);
    tsplit_k<<<dim3(Cn/32, Cn/32, Ln), tb>>>(Wv, WT1+2*(size_t)CC, WT2+2*(size_t)CC, Cn, Cn, CC, WPL);
    tsplit_k<<<dim3(Cn/32, Cn/32, Ln), tb>>>(Wo, WT1+3*(size_t)CC, WT2+3*(size_t)CC, Cn, Cn, CC, WPL);
    tsplit_k<<<dim3(Hn/32, Cn/32, Ln), tb>>>(W1,                 WT1+4*(size_t)CC,  WT2+4*(size_t)CC,  Cn, Hn, 2*(size_t)Cn*Hn, WPL);
    tsplit_k<<<dim3(Hn/32, Cn/32, Ln), tb>>>(W1 + (size_t)Cn*Hn, WT1+8*(size_t)CC,  WT2+8*(size_t)CC,  Cn, Hn, 2*(size_t)Cn*Hn, WPL);
    tsplit_k<<<dim3(Cn/32, Hn/32, Ln), tb>>>(W2,                 WT1+12*(size_t)CC, WT2+12*(size_t)CC, Hn, Cn, 2*(size_t)Hn*Cn, WPL);
    tsplit_k<<<dim3(Cn/32, Hn/32, Ln), tb>>>(W2 + (size_t)Hn*Cn, WT1+16*(size_t)CC, WT2+16*(size_t)CC, Hn, Cn, 2*(size_t)Hn*Cn, WPL);
    tsplit_k<<<dim3(Hn/32, 2*Cn/32, Ln), tb>>>(Wl1, WT1+20*(size_t)CC, WT2+20*(size_t)CC, 2*Cn, Hn, 2*(size_t)Cn*Hn, WPL);
    tsplit_k<<<dim3(Cn/32, Hn/32, Ln), tb>>>(Wl2, WT1+28*(size_t)CC, WT2+28*(size_t)CC, Hn, Cn, (size_t)Hn*Cn, WPL);
    tsplit_k<<<dim3(Vn/32, Cn/32, 1), tb>>>(headW, WT1+WHEAD, WT2+WHEAD, Cn, Vn, 0, 0);

    embed_k<<<(BT*Cn)/256, 256>>>(idx, emb);

    for (int l = 0; l < Ln; l++) {
        size_t LB = (size_t)l*WPL;
        ln1mix_k<<<BT, 256>>>(X, ln1g + (size_t)l*Cn, ln1b + (size_t)l*Cn);

        rkv_mma<<<dim3(24, 32), 256, SMEMB>>>(MX1, MX2, WT1+LB, WT2+LB);

        scan1_k<<<(Bsz*CH*Cn)/256, 256>>>();   // also zeroes CNT for this layer
        scan3_k<<<(Bsz*CH*Cn)/256, 256>>>();

        gemm_mma<2,3><<<dim3(8, 32), 256, SMEMB>>>(MX1, MX2, WT1+LB+3*(size_t)CC, WT2+LB+3*(size_t)CC, X, Cn, Cn);

        ln2r_k<true><<<BT, 256>>>(X, ln2g + (size_t)l*Cn, ln2b + (size_t)l*Cn, HB1, HB2,
                                  wconf + (size_t)l*En*Cn, Waff + (size_t)l*Cn*En,
                                  shares + (size_t)l*En);

        UpArgs ua;
        DnArgs da;
        for (int e = 0; e < 2; e++) {
            size_t o1 = LB + (4 + 4*e)*(size_t)CC;
            size_t o2 = LB + (12 + 4*e)*(size_t)CC;
            ua.A1[e] = HB1; ua.A2[e] = HB2;
            ua.A1b[e] = HB1; ua.A2b[e] = HB2;   // unused (K=Cn)
            ua.B1[e] = WT1 + o1; ua.B2[e] = WT2 + o1;
            ua.K[e] = Cn;
            da.B1[e] = WT1 + o2; da.B2[e] = WT2 + o2;
        }
        ua.A1[2] = HB1; ua.A2[2] = HB2;
        ua.A1b[2] = SP1; ua.A2b[2] = SP2;       // second half of hz = state pair
        ua.B1[2] = WT1 + LB + 20*(size_t)CC; ua.B2[2] = WT2 + LB + 20*(size_t)CC;
        ua.K[2] = 2*Cn;
        da.B1[2] = WT1 + LB + 28*(size_t)CC; da.B2[2] = WT2 + LB + 28*(size_t)CC;

        up3_mma<<<dim3(32, 32, 3), 256, SMEMB>>>(ua);
        dn3_mma<<<dim3(8, 32, 3), 256, SMEMB>>>(da);
    }

    ln2r_k<false><<<BT, 256>>>(X, lnfg, lnfb, HB1, HB2, nullptr, nullptr, nullptr);
    gemm_mma<0,2><<<dim3(Vn/128, BT/128), 256, SMEMB>>>(HB1, HB2, WT1+WHEAD, WT2+WHEAD, out, Cn, Vn);
}

// round 12
// speedup vs baseline: 4.0588x; 1.0516x over previous
#include <cuda_runtime.h>
#include <cuda_fp16.h>
#include <math.h>
#include <stdint.h>

// ---------------- dims ----------------
#define Bsz 2
#define Tn  2048
#define Cn  1024
#define Vn  32000
#define Ln  4
#define En  3
#define Hn  4096
#define BT  (Bsz*Tn)
#define CH  16
#define CL  (Tn/CH)
#define KC  32

#define CC  (Cn*Cn)
#define WPL (32*CC)
#define WHEAD ((size_t)4*WPL)
#define WTOT  ((size_t)4*WPL + (size_t)Cn*Vn)

#define TILE_B 8192
#define STAGE_B (4*TILE_B)
#define SMEMB (3*STAGE_B)               // 96KB, 3-stage -> 2 CTAs/SM

// ---------------- scratch ----------------
__device__ float g_X  [BT*Cn];
__device__ float g_R  [BT*Cn];
__device__ float g_K  [BT*Cn];
__device__ float g_V  [BT*Cn];
__device__ float g_SC [BT];
__device__ float g_PART[Bsz*CH*Cn];
__device__ int   g_CNT[En];
__device__ int   g_LIST[En*BT];

__device__ __half g_MX1[BT*Cn], g_MX2[BT*Cn];           // mix, then rs
__device__ __half g_SP1[BT*Cn], g_SP2[BT*Cn];           // rwkv state pair
__device__ __half g_HB1[BT*Cn], g_HB2[BT*Cn];           // h pair
__device__ __half g_HD1[(size_t)BT*Hn], g_HD2[(size_t)BT*Hn];
__device__ __half g_WT1[WTOT], g_WT2[WTOT];

// ---------------- helpers ----------------
__device__ __forceinline__ void split2(float v, __half& h1, __half& h2) {
    h1 = __float2half_rn(v);
    float r = v - __half2float(h1);
    h2 = __float2half_rn(r);
}
__device__ __forceinline__ uint32_t smem_u32(const void* p) {
    uint32_t a;
    asm("{ .reg .u64 t; cvta.to.shared.u64 t, %1; cvt.u32.u64 %0, t; }" : "=r"(a) : "l"(p));
    return a;
}
#define CP16(dst, src) asm volatile("cp.async.cg.shared.global [%0], [%1], 16;" :: "r"(dst), "l"(src) : "memory")
#define CP_COMMIT()    asm volatile("cp.async.commit_group;" ::: "memory")
#define CP_WAIT1()     asm volatile("cp.async.wait_group 1;" ::: "memory")
#define CP_WAIT0()     asm volatile("cp.async.wait_group 0;" ::: "memory")
#define LDSM4(r, a) \
    asm volatile("ldmatrix.sync.aligned.m8n8.x4.shared.b16 {%0,%1,%2,%3}, [%4];" \
        : "=r"((r)[0]), "=r"((r)[1]), "=r"((r)[2]), "=r"((r)[3]) : "r"(a))
#define MMA16816(d, a, b0v, b1v) \
    asm volatile("mma.sync.aligned.m16n8k16.row.col.f32.f16.f16.f32 " \
        "{%0,%1,%2,%3}, {%4,%5,%6,%7}, {%8,%9}, {%0,%1,%2,%3};" \
        : "+f"((d)[0]), "+f"((d)[1]), "+f"((d)[2]), "+f"((d)[3]) \
        : "r"((a)[0]), "r"((a)[1]), "r"((a)[2]), "r"((a)[3]), "r"(b0v), "r"(b1v))
__device__ __forceinline__ uint32_t sw64(uint32_t o) { return o ^ ((o >> 2) & 0x30); }

// ---------------- GEMM core ----------------
// NP=3: {A1B1,A2B1,A1B2}   NP=2: {A1B1,A2B1}   NP=1: {A1B1} (pure fp16)
// 3-stage cp.async pipeline, ONE barrier per chunk. A source switches to (a1b,a2b)
// at k >= ksw (chunk-aligned). Pointers include row+half offsets.
template<int NP>
__device__ __forceinline__ void mma_core(
    uint32_t sbase,
    const __half* a1, const __half* a2, const __half* a1b, const __half* a2b, int ksw,
    const __half* b1, const __half* b2,
    int K, int tid, int lane, int wm, int wn, float acc[2][8][4])
{
    int arow = tid >> 1, half_ = tid & 1;
    uint32_t so[2];
#pragma unroll
    for (int q = 0; q < 2; q++)
        so[q] = sw64(arow*64 + half_*32 + q*16);

    // tile slots: 0=A1 1=A2 2=B1 3=B2
    const bool useT[4] = {true, NP >= 2, true, NP == 3};
    const int  nA = (NP >= 2) ? 2 : 1;
    int nc = K / KC;

    auto issue = [&](int c, uint32_t sb) {
        int k0 = c*KC;
        const __half* s0 = (k0 < ksw) ? a1 + k0 : a1b + (k0 - ksw);
        const __half* s1 = (k0 < ksw) ? a2 + k0 : a2b + (k0 - ksw);
        const __half* srcs[4] = {s0, s1, b1 + k0, b2 + k0};
#pragma unroll
        for (int t = 0; t < 4; t++) {
            if (!useT[t]) continue;
#pragma unroll
            for (int q = 0; q < 2; q++)
                CP16(sb + t*TILE_B + so[q], srcs[t] + q*8);
        }
        CP_COMMIT();
    };

    issue(0, sbase);
    if (nc > 1) issue(1, sbase + STAGE_B);

    for (int c = 0; c < nc; c++) {
        if (c + 1 < nc) CP_WAIT1();
        else            CP_WAIT0();
        __syncthreads();   // single barrier per chunk (3-stage makes trailing sync redundant)

        uint32_t stg = sbase + (uint32_t)(c % 3)*STAGE_B;
#pragma unroll
        for (int ks = 0; ks < 2; ks++) {
            // hoist A fragments for this k16-slab
            uint32_t afr[2][2][4];
#pragma unroll
            for (int as_ = 0; as_ < 2; as_++) {
                if (as_ >= nA) break;
#pragma unroll
                for (int mf = 0; mf < 2; mf++) {
                    uint32_t r  = wm*32 + mf*16 + (lane & 7) + ((lane & 8) ? 8 : 0);
                    uint32_t of = ks*32 + ((lane & 16) ? 16 : 0);
                    LDSM4(afr[as_][mf], stg + as_*TILE_B + sw64(r*64 + of));
                }
            }
            // B1 fragments; B frag mapping: row select lane&16, k-offset lane&8 (differs from A!)
            uint32_t bfr[4][4];
#pragma unroll
            for (int nq = 0; nq < 4; nq++) {
                uint32_t r  = wn*64 + nq*16 + (lane & 7) + ((lane & 16) ? 8 : 0);
                uint32_t of = ks*32 + ((lane & 8) ? 16 : 0);
                LDSM4(bfr[nq], stg + 2*TILE_B + sw64(r*64 + of));
            }
#pragma unroll
            for (int as_ = 0; as_ < 2; as_++) {
                if (as_ >= nA) break;
#pragma unroll
                for (int mf = 0; mf < 2; mf++)
#pragma unroll
                    for (int nf = 0; nf < 8; nf++)
                        MMA16816(acc[mf][nf], afr[as_][mf], bfr[nf>>1][(nf&1)*2], bfr[nf>>1][(nf&1)*2 + 1]);
            }
            if (NP == 3) {
                // B2 fragments, A1*B2
#pragma unroll
                for (int nq = 0; nq < 4; nq++) {
                    uint32_t r  = wn*64 + nq*16 + (lane & 7) + ((lane & 16) ? 8 : 0);
                    uint32_t of = ks*32 + ((lane & 8) ? 16 : 0);
                    LDSM4(bfr[nq], stg + 3*TILE_B + sw64(r*64 + of));
                }
#pragma unroll
                for (int mf = 0; mf < 2; mf++)
#pragma unroll
                    for (int nf = 0; nf < 8; nf++)
                        MMA16816(acc[mf][nf], afr[0][mf], bfr[nf>>1][(nf&1)*2], bfr[nf>>1][(nf&1)*2 + 1]);
            }
        }
        if (c + 2 < nc) issue(c + 2, sbase + (uint32_t)((c + 2) % 3)*STAGE_B);
    }
}

#define MMA_PROLOG() \
    extern __shared__ char smem[]; \
    uint32_t sbase = smem_u32(smem); \
    int tid = threadIdx.x, lane = tid & 31, wid = tid >> 5; \
    int wm = wid & 3, wn = wid >> 2; \
    int arow = tid >> 1, half_ = tid & 1; \
    float acc[2][8][4]; \
    _Pragma("unroll") for (int i = 0; i < 2; i++) \
    _Pragma("unroll") for (int j = 0; j < 8; j++) \
    _Pragma("unroll") for (int q = 0; q < 4; q++) acc[i][j][q] = 0.f;

// ---------------- fused r/k/v GEMM: grid(24, 32) ----------------
__global__ void __launch_bounds__(256, 2) rkv_mma(
    const __half* __restrict__ A1, const __half* __restrict__ A2,
    const __half* __restrict__ B1, const __half* __restrict__ B2)
{
    MMA_PROLOG();
    int m0 = blockIdx.y * 128;
    size_t aro = (size_t)(m0 + arow)*Cn + half_*16;
    size_t bro = (size_t)(blockIdx.x*128 + arow)*Cn + half_*16;
    mma_core<3>(sbase, A1 + aro, A2 + aro, A1 + aro, A2 + aro, Cn,
                B1 + bro, B2 + bro, Cn, tid, lane, wm, wn, acc);

    int mat = blockIdx.x >> 3;
    float* outp = (mat == 0) ? g_R : ((mat == 1) ? g_K : g_V);
    int cbase = (blockIdx.x & 7)*128 + wn*64;
#pragma unroll
    for (int mf = 0; mf < 2; mf++) {
        int r0 = m0 + wm*32 + mf*16 + (lane >> 2);
#pragma unroll
        for (int nf = 0; nf < 8; nf++) {
            int cc = cbase + nf*8 + (lane & 3)*2;
#pragma unroll
            for (int h = 0; h < 2; h++) {
                int r = r0 + h*8;
                float v0 = acc[mf][nf][h*2], v1 = acc[mf][nf][h*2 + 1];
                if (mat == 0) {
                    v0 = 1.f/(1.f + expf(-v0));
                    v1 = 1.f/(1.f + expf(-v1));
                }
                float* cr = outp + (size_t)r*Cn + cc;
                cr[0] = v0; cr[1] = v1;
            }
        }
    }
}

// ---------------- generic dense GEMM: MODE 0: C=acc  2: C+=acc ----------------
template<int MODE, int NP>
__global__ void __launch_bounds__(256, 2) gemm_mma(
    const __half* __restrict__ A1, const __half* __restrict__ A2,
    const __half* __restrict__ B1, const __half* __restrict__ B2,
    float* __restrict__ Cf, int K, int N)
{
    MMA_PROLOG();
    int m0 = blockIdx.y * 128;
    size_t aro = (size_t)(m0 + arow)*K + half_*16;
    size_t bro = (size_t)(blockIdx.x*128 + arow)*K + half_*16;
    mma_core<NP>(sbase, A1 + aro, A2 + aro, A1 + aro, A2 + aro, K,
                 B1 + bro, B2 + bro, K, tid, lane, wm, wn, acc);

    int cbase = blockIdx.x*128 + wn*64;
#pragma unroll
    for (int mf = 0; mf < 2; mf++) {
        int r0 = m0 + wm*32 + mf*16 + (lane >> 2);
#pragma unroll
        for (int nf = 0; nf < 8; nf++) {
            int cc = cbase + nf*8 + (lane & 3)*2;
#pragma unroll
            for (int h = 0; h < 2; h++) {
                int r = r0 + h*8;
                float v0 = acc[mf][nf][h*2], v1 = acc[mf][nf][h*2 + 1];
                float* cr = Cf + (size_t)r*N + cc;
                if (MODE == 2) { cr[0] += v0; cr[1] += v1; }
                else           { cr[0] = v0;  cr[1] = v1; }
            }
        }
    }
}

// ---------------- fused expert up-proj: grid(32, 32, 3); A row stride Cn, switch at ksw=Cn
struct UpArgs {
    const __half* A1[3]; const __half* A2[3];
    const __half* A1b[3]; const __half* A2b[3];
    const __half* B1[3]; const __half* B2[3];
    int K[3];
};
__global__ void __launch_bounds__(256, 2) up3_mma(UpArgs ua) {
    int z = blockIdx.z;
    int Meff = g_CNT[z];
    int m0 = blockIdx.y * 128;
    if (m0 >= Meff) return;
    const int* rows = g_LIST + z*BT;
    int K = ua.K[z];

    MMA_PROLOG();
    int am = m0 + arow;
    int amc = (am < Meff) ? am : (Meff - 1);
    size_t aro = (size_t)rows[amc]*Cn + half_*16;
    size_t bro = (size_t)(blockIdx.x*128 + arow)*K + half_*16;
    mma_core<3>(sbase, ua.A1[z] + aro, ua.A2[z] + aro, ua.A1b[z] + aro, ua.A2b[z] + aro, Cn,
                ua.B1[z] + bro, ua.B2[z] + bro, K, tid, lane, wm, wn, acc);

    int cbase = blockIdx.x*128 + wn*64;
#pragma unroll
    for (int mf = 0; mf < 2; mf++) {
        int r0 = m0 + wm*32 + mf*16 + (lane >> 2);
#pragma unroll
        for (int nf = 0; nf < 8; nf++) {
            int cc = cbase + nf*8 + (lane & 3)*2;
#pragma unroll
            for (int h = 0; h < 2; h++) {
                int r = r0 + h*8;
                if (r >= Meff) continue;
                size_t o = (size_t)rows[r]*Hn + cc;
                float v0 = fmaxf(acc[mf][nf][h*2],     0.f);
                float v1 = fmaxf(acc[mf][nf][h*2 + 1], 0.f);
                split2(v0, g_HD1[o],   g_HD2[o]);
                split2(v1, g_HD1[o+1], g_HD2[o+1]);
            }
        }
    }
}

// ---------------- fused expert down-proj: grid(8, 32, 3) ----------------
struct DnArgs { const __half* B1[3]; const __half* B2[3]; };
__global__ void __launch_bounds__(256, 2) dn3_mma(DnArgs da) {
    int z = blockIdx.z;
    int Meff = g_CNT[z];
    int m0 = blockIdx.y * 128;
    if (m0 >= Meff) return;
    const int* rows = g_LIST + z*BT;

    MMA_PROLOG();
    int am = m0 + arow;
    int amc = (am < Meff) ? am : (Meff - 1);
    size_t aro = (size_t)rows[amc]*Hn + half_*16;
    size_t bro = (size_t)(blockIdx.x*128 + arow)*Hn + half_*16;
    mma_core<3>(sbase, g_HD1 + aro, g_HD2 + aro, g_HD1 + aro, g_HD2 + aro, Hn,
                da.B1[z] + bro, da.B2[z] + bro, Hn, tid, lane, wm, wn, acc);

    int cbase = blockIdx.x*128 + wn*64;
#pragma unroll
    for (int mf = 0; mf < 2; mf++) {
        int r0 = m0 + wm*32 + mf*16 + (lane >> 2);
#pragma unroll
        for (int nf = 0; nf < 8; nf++) {
            int cc = cbase + nf*8 + (lane & 3)*2;
#pragma unroll
            for (int h = 0; h < 2; h++) {
                int r = r0 + h*8;
                if (r >= Meff) continue;
                int tok = rows[r];
                float sc = g_SC[tok];
                float* xr = g_X + (size_t)tok*Cn + cc;
                xr[0] += acc[mf][nf][h*2]*sc;
                xr[1] += acc[mf][nf][h*2 + 1]*sc;
            }
        }
    }
}

// ---------------- embedding gather ----------------
__global__ void embed_k(const int* __restrict__ idx, const float* __restrict__ emb) {
    int i = blockIdx.x*blockDim.x + threadIdx.x;
    if (i >= BT*Cn) return;
    int row = i >> 10, c = i & 1023;
    g_X[i] = emb[(size_t)idx[row]*Cn + c];
}

// ---------------- fused ln1 + token-shift mix -> MX pair ----------------
__global__ void ln1mix_k(const float* __restrict__ in, const float* __restrict__ g,
                         const float* __restrict__ b) {
    int row = blockIdx.x;
    int t = row & (Tn - 1);
    const float* p = in + (size_t)row*Cn;
    const float* pp = in + (size_t)(row-1)*Cn;
    float v[4], u[4];
    float s = 0.f, ss = 0.f, su = 0.f, ssu = 0.f;
#pragma unroll
    for (int j = 0; j < 4; j++) {
        int c = threadIdx.x + j*256;
        v[j] = p[c];
        s += v[j]; ss += v[j]*v[j];
        u[j] = (t > 0) ? pp[c] : 0.f;
        su += u[j]; ssu += u[j]*u[j];
    }
#pragma unroll
    for (int o = 16; o > 0; o >>= 1) {
        s   += __shfl_xor_sync(0xffffffffu, s,   o);
        ss  += __shfl_xor_sync(0xffffffffu, ss,  o);
        su  += __shfl_xor_sync(0xffffffffu, su,  o);
        ssu += __shfl_xor_sync(0xffffffffu, ssu, o);
    }
    __shared__ float sh[4][8];
    int w = threadIdx.x >> 5;
    if ((threadIdx.x & 31) == 0) { sh[0][w] = s; sh[1][w] = ss; sh[2][w] = su; sh[3][w] = ssu; }
    __syncthreads();
    s = 0.f; ss = 0.f; su = 0.f; ssu = 0.f;
#pragma unroll
    for (int j = 0; j < 8; j++) { s += sh[0][j]; ss += sh[1][j]; su += sh[2][j]; ssu += sh[3][j]; }
    float mv = s*(1.f/Cn),  rv = rsqrtf(ss*(1.f/Cn) - mv*mv + 1e-5f);
    float mu = su*(1.f/Cn), ru = rsqrtf(ssu*(1.f/Cn) - mu*mu + 1e-5f);
#pragma unroll
    for (int j = 0; j < 4; j++) {
        int c = threadIdx.x + j*256;
        float hv = (v[j]-mv)*rv*g[c] + b[c];
        float hu = (t > 0) ? ((u[j]-mu)*ru*g[c] + b[c]) : 0.f;
        float mix = 0.5f*(hv + hu);
        size_t id = (size_t)row*Cn + c;
        split2(mix, g_MX1[id], g_MX2[id]);
    }
}

// ---------------- fused ln2 + route (or plain lnf) -> HB pair ----------------
template<bool ROUTE>
__global__ void ln2r_k(const float* __restrict__ in, const float* __restrict__ g,
                       const float* __restrict__ b,
                       __half* __restrict__ o1, __half* __restrict__ o2,
                       const float* __restrict__ wc, const float* __restrict__ wa,
                       const float* __restrict__ shp) {
    int row = blockIdx.x;
    const float* p = in + (size_t)row*Cn;
    float v[4];
    float s = 0.f, ss = 0.f;
#pragma unroll
    for (int j = 0; j < 4; j++) {
        v[j] = p[threadIdx.x + j*256];
        s += v[j]; ss += v[j]*v[j];
    }
#pragma unroll
    for (int o = 16; o > 0; o >>= 1) {
        s  += __shfl_xor_sync(0xffffffffu, s,  o);
        ss += __shfl_xor_sync(0xffffffffu, ss, o);
    }
    __shared__ float sh[2][8];
    int w = threadIdx.x >> 5;
    if ((threadIdx.x & 31) == 0) { sh[0][w] = s; sh[1][w] = ss; }
    __syncthreads();
    s = 0.f; ss = 0.f;
#pragma unroll
    for (int j = 0; j < 8; j++) { s += sh[0][j]; ss += sh[1][j]; }
    float mean = s * (1.f/Cn);
    float rstd = rsqrtf(ss*(1.f/Cn) - mean*mean + 1e-5f);

    float pq[6] = {0,0,0,0,0,0};
#pragma unroll
    for (int j = 0; j < 4; j++) {
        int c = threadIdx.x + j*256;
        float val = (v[j]-mean)*rstd*g[c] + b[c];
        size_t id = (size_t)row*Cn + c;
        split2(val, o1[id], o2[id]);
        if (ROUTE) {
            pq[0] += val*wc[c];
            pq[1] += val*wc[Cn + c];
            pq[2] += val*wc[2*Cn + c];
            pq[3] += val*wa[c*En + 0];
            pq[4] += val*wa[c*En + 1];
            pq[5] += val*wa[c*En + 2];
        }
    }
    if (ROUTE) {
#pragma unroll
        for (int o = 16; o > 0; o >>= 1)
#pragma unroll
            for (int q = 0; q < 6; q++) pq[q] += __shfl_xor_sync(0xffffffffu, pq[q], o);
        __shared__ float sm[8][6];
        if ((threadIdx.x & 31) == 0)
#pragma unroll
            for (int q = 0; q < 6; q++) sm[w][q] = pq[q];
        __syncthreads();
        if (threadIdx.x == 0) {
            float d[6];
#pragma unroll
            for (int q = 0; q < 6; q++) {
                d[q] = 0.f;
#pragma unroll
                for (int ww = 0; ww < 8; ww++) d[q] += sm[ww][q];
            }
            float best = -3.4e38f, wcf = 0.f;
            int wi = 0;
#pragma unroll
            for (int e = 0; e < En; e++) {
                float conf = 1.f/(1.f + expf(-d[e]));
                float bid  = conf*shp[e] + d[3+e];
                if (bid > best) { best = bid; wi = e; wcf = conf; }
            }
            g_SC[row] = wcf / (wcf + 1e-6f);
            int pos = atomicAdd(&g_CNT[wi], 1);
            g_LIST[wi*BT + pos] = row;
        }
    }
}

// ---------------- scan phase 1 (+ CNT zeroing for this layer's routing) ----------------
__global__ void scan1_k() {
    if (blockIdx.x == 0 && threadIdx.x < En) g_CNT[threadIdx.x] = 0;
    int i = blockIdx.x*blockDim.x + threadIdx.x;
    if (i >= Bsz*CH*Cn) return;
    int c  = i & 1023;
    int ch = (i >> 10) & (CH - 1);
    int b  = i >> 14;
    size_t base = (size_t)b*Tn*Cn + (size_t)ch*CL*Cn + c;
    float s = 0.f;
#pragma unroll 4
    for (int t = 0; t < CL; t++) {
        size_t id = base + (size_t)t*Cn;
        s += g_K[id]*g_V[id];
    }
    g_PART[i] = s;
}
// ---------------- scan phase 2+3 fused ----------------
__global__ void scan3_k() {
    int i = blockIdx.x*blockDim.x + threadIdx.x;
    if (i >= Bsz*CH*Cn) return;
    int c  = i & 1023;
    int ch = (i >> 10) & (CH - 1);
    int b  = i >> 14;
    float acc = 0.f;
    for (int j = 0; j < CH; j++)
        if (j < ch) acc += g_PART[((b*CH + j) << 10) | c];
    size_t base = (size_t)b*Tn*Cn + (size_t)ch*CL*Cn + c;
    int t0 = ch*CL;
#pragma unroll 4
    for (int t = 0; t < CL; t++) {
        size_t id = base + (size_t)t*Cn;
        acc += g_K[id]*g_V[id];
        float st = acc / (float)(t0 + t + 1);
        split2(st, g_SP1[id], g_SP2[id]);
        float rs = g_R[id]*st;
        split2(rs, g_MX1[id], g_MX2[id]);
    }
}

// ---------------- batched weight transpose+split ----------------
__global__ void tsplit_k(const float* __restrict__ W,
                         __half* __restrict__ o1, __half* __restrict__ o2,
                         int K, int N, size_t srcStride, size_t dstStride) {
    __shared__ __half s1[32][33], s2[32][33];
    int z = blockIdx.z;
    W  += (size_t)z*srcStride;
    o1 += (size_t)z*dstStride;
    o2 += (size_t)z*dstStride;
    int n0 = blockIdx.x*32, k0 = blockIdx.y*32;
    int tx = threadIdx.x, ty = threadIdx.y;
#pragma unroll
    for (int j = 0; j < 4; j++) {
        int k = k0 + ty + j*8;
        float v = W[(size_t)k*N + n0 + tx];
        split2(v, s1[ty+j*8][tx], s2[ty+j*8][tx]);
    }
    __syncthreads();
#pragma unroll
    for (int j = 0; j < 4; j++) {
        int n = n0 + ty + j*8;
        size_t o = (size_t)n*K + k0 + tx;
        o1[o] = s1[tx][ty+j*8];
        o2[o] = s2[tx][ty+j*8];
    }
}

// ---------------- launch ----------------
extern "C" void kernel_launch(void* const* d_in, const int* in_sizes, int n_in,
                              void* d_out, int out_size)
{
    const int*   idx   = (const int*)  d_in[0];
    const float* shares= (const float*)d_in[1];
    const float* emb   = (const float*)d_in[2];
    const float* ln1g  = (const float*)d_in[3];
    const float* ln1b  = (const float*)d_in[4];
    const float* ln2g  = (const float*)d_in[5];
    const float* ln2b  = (const float*)d_in[6];
    const float* Wr    = (const float*)d_in[7];
    const float* Wk    = (const float*)d_in[8];
    const float* Wv    = (const float*)d_in[9];
    const float* Wo    = (const float*)d_in[10];
    const float* W1    = (const float*)d_in[11];
    const float* W2    = (const float*)d_in[12];
    const float* wconf = (const float*)d_in[13];
    const float* Wl1   = (const float*)d_in[14];
    const float* Wl2   = (const float*)d_in[15];
    const float* Waff  = (const float*)d_in[17];
    const float* lnfg  = (const float*)d_in[18];
    const float* lnfb  = (const float*)d_in[19];
    const float* headW = (const float*)d_in[20];
    float* out = (float*)d_out;
    (void)in_sizes; (void)n_in; (void)out_size;

    float *X;
    __half *MX1,*MX2, *SP1,*SP2, *HB1,*HB2, *WT1,*WT2;
    cudaGetSymbolAddress((void**)&X,   g_X);
    cudaGetSymbolAddress((void**)&MX1, g_MX1); cudaGetSymbolAddress((void**)&MX2, g_MX2);
    cudaGetSymbolAddress((void**)&SP1, g_SP1); cudaGetSymbolAddress((void**)&SP2, g_SP2);
    cudaGetSymbolAddress((void**)&HB1, g_HB1); cudaGetSymbolAddress((void**)&HB2, g_HB2);
    cudaGetSymbolAddress((void**)&WT1, g_WT1); cudaGetSymbolAddress((void**)&WT2, g_WT2);

    cudaFuncSetAttribute(rkv_mma,        cudaFuncAttributeMaxDynamicSharedMemorySize, SMEMB);
    cudaFuncSetAttribute(gemm_mma<2,3>,  cudaFuncAttributeMaxDynamicSharedMemorySize, SMEMB);
    cudaFuncSetAttribute(gemm_mma<0,1>,  cudaFuncAttributeMaxDynamicSharedMemorySize, SMEMB);
    cudaFuncSetAttribute(up3_mma,        cudaFuncAttributeMaxDynamicSharedMemorySize, SMEMB);
    cudaFuncSetAttribute(dn3_mma,        cudaFuncAttributeMaxDynamicSharedMemorySize, SMEMB);

    dim3 tb(32, 8);
    // arena per layer: Wr@0 Wk@CC Wv@2CC Wo@3CC | W1e0@4CC W1e1@8CC | W2e0@12CC W2e1@16CC | Wl1@20CC Wl2@28CC
    tsplit_k<<<dim3(Cn/32, Cn/32, Ln), tb>>>(Wr, WT1,              WT2,              Cn, Cn, CC, WPL);
    tsplit_k<<<dim3(Cn/32, Cn/32, Ln), tb>>>(Wk, WT1+CC,           WT2+CC,           Cn, Cn, CC, WPL);
    tsplit_k<<<dim3(Cn/32, Cn/32, Ln), tb>>>(Wv, WT1+2*(size_t)CC, WT2+2*(size_t)CC, Cn, Cn, CC, WPL);
    tsplit_k<<<dim3(Cn/32, Cn/32, Ln), tb>>>(Wo, WT1+3*(size_t)CC, WT2+3*(size_t)CC, Cn, Cn, CC, WPL);
    tsplit_k<<<dim3(Hn/32, Cn/32, Ln), tb>>>(W1,                 WT1+4*(size_t)CC,  WT2+4*(size_t)CC,  Cn, Hn, 2*(size_t)Cn*Hn, WPL);
    tsplit_k<<<dim3(Hn/32, Cn/32, Ln), tb>>>(W1 + (size_t)Cn*Hn, WT1+8*(size_t)CC,  WT2+8*(size_t)CC,  Cn, Hn, 2*(size_t)Cn*Hn, WPL);
    tsplit_k<<<dim3(Cn/32, Hn/32, Ln), tb>>>(W2,                 WT1+12*(size_t)CC, WT2+12*(size_t)CC, Hn, Cn, 2*(size_t)Hn*Cn, WPL);
    tsplit_k<<<dim3(Cn/32, Hn/32, Ln), tb>>>(W2 + (size_t)Hn*Cn, WT1+16*(size_t)CC, WT2+16*(size_t)CC, Hn, Cn, 2*(size_t)Hn*Cn, WPL);
    tsplit_k<<<dim3(Hn/32, 2*Cn/32, Ln), tb>>>(Wl1, WT1+20*(size_t)CC, WT2+20*(size_t)CC, 2*Cn, Hn, 2*(size_t)Cn*Hn, WPL);
    tsplit_k<<<dim3(Cn/32, Hn/32, Ln), tb>>>(Wl2, WT1+28*(size_t)CC, WT2+28*(size_t)CC, Hn, Cn, (size_t)Hn*Cn, WPL);
    tsplit_k<<<dim3(Vn/32, Cn/32, 1), tb>>>(headW, WT1+WHEAD, WT2+WHEAD, Cn, Vn, 0, 0);

    embed_k<<<(BT*Cn)/256, 256>>>(idx, emb);

    for (int l = 0; l < Ln; l++) {
        size_t LB = (size_t)l*WPL;
        ln1mix_k<<<BT, 256>>>(X, ln1g + (size_t)l*Cn, ln1b + (size_t)l*Cn);

        rkv_mma<<<dim3(24, 32), 256, SMEMB>>>(MX1, MX2, WT1+LB, WT2+LB);

        scan1_k<<<(Bsz*CH*Cn)/256, 256>>>();   // also zeroes CNT for this layer
        scan3_k<<<(Bsz*CH*Cn)/256, 256>>>();

        gemm_mma<2,3><<<dim3(8, 32), 256, SMEMB>>>(MX1, MX2, WT1+LB+3*(size_t)CC, WT2+LB+3*(size_t)CC, X, Cn, Cn);

        ln2r_k<true><<<BT, 256>>>(X, ln2g + (size_t)l*Cn, ln2b + (size_t)l*Cn, HB1, HB2,
                                  wconf + (size_t)l*En*Cn, Waff + (size_t)l*Cn*En,
                                  shares + (size_t)l*En);

        UpArgs ua;
        DnArgs da;
        for (int e = 0; e < 2; e++) {
            size_t o1 = LB + (4 + 4*e)*(size_t)CC;
            size_t o2 = LB + (12 + 4*e)*(size_t)CC;
            ua.A1[e] = HB1; ua.A2[e] = HB2;
            ua.A1b[e] = HB1; ua.A2b[e] = HB2;   // unused (K=Cn)
            ua.B1[e] = WT1 + o1; ua.B2[e] = WT2 + o1;
            ua.K[e] = Cn;
            da.B1[e] = WT1 + o2; da.B2[e] = WT2 + o2;
        }
        ua.A1[2] = HB1; ua.A2[2] = HB2;
        ua.A1b[2] = SP1; ua.A2b[2] = SP2;       // second half of hz = state pair
        ua.B1[2] = WT1 + LB + 20*(size_t)CC; ua.B2[2] = WT2 + LB + 20*(size_t)CC;
        ua.K[2] = 2*Cn;
        da.B1[2] = WT1 + LB + 28*(size_t)CC; da.B2[2] = WT2 + LB + 28*(size_t)CC;

        up3_mma<<<dim3(32, 32, 3), 256, SMEMB>>>(ua);
        dn3_mma<<<dim3(8, 32, 3), 256, SMEMB>>>(da);
    }

    ln2r_k<false><<<BT, 256>>>(X, lnfg, lnfb, HB1, HB2, nullptr, nullptr, nullptr);
    // head: pure fp16 single product (error model: ~2.9e-4, validated margin under 1e-3)
    gemm_mma<0,1><<<dim3(Vn/128, BT/128), 256, SMEMB>>>(HB1, HB2, WT1+WHEAD, WT2+WHEAD, out, Cn, Vn);
}

// round 15
// speedup vs baseline: 4.1949x; 1.0335x over previous
#include <cuda_runtime.h>
#include <cuda_fp16.h>
#include <math.h>
#include <stdint.h>

// ---------------- dims ----------------
#define Bsz 2
#define Tn  2048
#define Cn  1024
#define Vn  32000
#define Ln  4
#define En  3
#define Hn  4096
#define BT  (Bsz*Tn)
#define CH  16
#define CL  (Tn/CH)
#define KC  32

#define CC  (Cn*Cn)
#define WPL (32*CC)
#define WHEAD ((size_t)4*WPL)
#define WTOT  ((size_t)4*WPL + (size_t)Cn*Vn)

#define TILE_B 8192
#define STAGE_B (4*TILE_B)
#define SMEMB (3*STAGE_B)               // 96KB, 3-stage -> 2 CTAs/SM

// ---------------- scratch ----------------
__device__ float g_X  [BT*Cn];
__device__ float g_R  [BT*Cn];
__device__ float g_K  [BT*Cn];
__device__ float g_V  [BT*Cn];
__device__ float g_SC [BT];
__device__ float g_PART[Bsz*CH*Cn];
__device__ int   g_CNT[En];
__device__ int   g_LIST[En*BT];

__device__ __half g_MX1[BT*Cn], g_MX2[BT*Cn];           // mix, then rs
__device__ __half g_SP1[BT*Cn], g_SP2[BT*Cn];           // rwkv state pair
__device__ __half g_HB1[BT*Cn], g_HB2[BT*Cn];           // h pair
__device__ __half g_HD1[(size_t)BT*Hn], g_HD2[(size_t)BT*Hn];
__device__ __half g_WT1[WTOT], g_WT2[WTOT];

// ---------------- helpers ----------------
__device__ __forceinline__ void split2(float v, __half& h1, __half& h2) {
    h1 = __float2half_rn(v);
    float r = v - __half2float(h1);
    h2 = __float2half_rn(r);
}
__device__ __forceinline__ uint32_t smem_u32(const void* p) {
    uint32_t a;
    asm("{ .reg .u64 t; cvta.to.shared.u64 t, %1; cvt.u32.u64 %0, t; }" : "=r"(a) : "l"(p));
    return a;
}
#define CP16(dst, src) asm volatile("cp.async.cg.shared.global [%0], [%1], 16;" :: "r"(dst), "l"(src) : "memory")
#define CP_COMMIT()    asm volatile("cp.async.commit_group;" ::: "memory")
#define CP_WAIT1()     asm volatile("cp.async.wait_group 1;" ::: "memory")
#define CP_WAIT0()     asm volatile("cp.async.wait_group 0;" ::: "memory")
#define LDSM4(r, a) \
    asm volatile("ldmatrix.sync.aligned.m8n8.x4.shared.b16 {%0,%1,%2,%3}, [%4];" \
        : "=r"((r)[0]), "=r"((r)[1]), "=r"((r)[2]), "=r"((r)[3]) : "r"(a))
#define MMA16816(d, a, b0v, b1v) \
    asm volatile("mma.sync.aligned.m16n8k16.row.col.f32.f16.f16.f32 " \
        "{%0,%1,%2,%3}, {%4,%5,%6,%7}, {%8,%9}, {%0,%1,%2,%3};" \
        : "+f"((d)[0]), "+f"((d)[1]), "+f"((d)[2]), "+f"((d)[3]) \
        : "r"((a)[0]), "r"((a)[1]), "r"((a)[2]), "r"((a)[3]), "r"(b0v), "r"(b1v))
__device__ __forceinline__ uint32_t sw64(uint32_t o) { return o ^ ((o >> 2) & 0x30); }

// ---------------- GEMM core ----------------
// NP=3: {A1B1,A2B1,A1B2}   NP=2: {A1B1,A2B1}   NP=1: {A1B1} (pure fp16)
// 3-stage cp.async pipeline, ONE barrier per chunk. A source switches to (a1b,a2b)
// at k >= ksw (chunk-aligned). Pointers include row+half offsets.
template<int NP>
__device__ __forceinline__ void mma_core(
    uint32_t sbase,
    const __half* a1, const __half* a2, const __half* a1b, const __half* a2b, int ksw,
    const __half* b1, const __half* b2,
    int K, int tid, int lane, int wm, int wn, float acc[2][8][4])
{
    int arow = tid >> 1, half_ = tid & 1;
    uint32_t so[2];
#pragma unroll
    for (int q = 0; q < 2; q++)
        so[q] = sw64(arow*64 + half_*32 + q*16);

    // tile slots: 0=A1 1=A2 2=B1 3=B2
    const bool useT[4] = {true, NP >= 2, true, NP == 3};
    const int  nA = (NP >= 2) ? 2 : 1;
    int nc = K / KC;

    auto issue = [&](int c, uint32_t sb) {
        int k0 = c*KC;
        const __half* s0 = (k0 < ksw) ? a1 + k0 : a1b + (k0 - ksw);
        const __half* s1 = (k0 < ksw) ? a2 + k0 : a2b + (k0 - ksw);
        const __half* srcs[4] = {s0, s1, b1 + k0, b2 + k0};
#pragma unroll
        for (int t = 0; t < 4; t++) {
            if (!useT[t]) continue;
#pragma unroll
            for (int q = 0; q < 2; q++)
                CP16(sb + t*TILE_B + so[q], srcs[t] + q*8);
        }
        CP_COMMIT();
    };

    issue(0, sbase);
    if (nc > 1) issue(1, sbase + STAGE_B);

    for (int c = 0; c < nc; c++) {
        if (c + 1 < nc) CP_WAIT1();
        else            CP_WAIT0();
        __syncthreads();   // single barrier per chunk (3-stage makes trailing sync redundant)

        uint32_t stg = sbase + (uint32_t)(c % 3)*STAGE_B;
#pragma unroll
        for (int ks = 0; ks < 2; ks++) {
            // hoist A fragments for this k16-slab
            uint32_t afr[2][2][4];
#pragma unroll
            for (int as_ = 0; as_ < 2; as_++) {
                if (as_ >= nA) break;
#pragma unroll
                for (int mf = 0; mf < 2; mf++) {
                    uint32_t r  = wm*32 + mf*16 + (lane & 7) + ((lane & 8) ? 8 : 0);
                    uint32_t of = ks*32 + ((lane & 16) ? 16 : 0);
                    LDSM4(afr[as_][mf], stg + as_*TILE_B + sw64(r*64 + of));
                }
            }
            // B1 fragments; B frag mapping: row select lane&16, k-offset lane&8 (differs from A!)
            uint32_t bfr[4][4];
#pragma unroll
            for (int nq = 0; nq < 4; nq++) {
                uint32_t r  = wn*64 + nq*16 + (lane & 7) + ((lane & 16) ? 8 : 0);
                uint32_t of = ks*32 + ((lane & 8) ? 16 : 0);
                LDSM4(bfr[nq], stg + 2*TILE_B + sw64(r*64 + of));
            }
#pragma unroll
            for (int as_ = 0; as_ < 2; as_++) {
                if (as_ >= nA) break;
#pragma unroll
                for (int mf = 0; mf < 2; mf++)
#pragma unroll
                    for (int nf = 0; nf < 8; nf++)
                        MMA16816(acc[mf][nf], afr[as_][mf], bfr[nf>>1][(nf&1)*2], bfr[nf>>1][(nf&1)*2 + 1]);
            }
            if (NP == 3) {
                // B2 fragments, A1*B2
#pragma unroll
                for (int nq = 0; nq < 4; nq++) {
                    uint32_t r  = wn*64 + nq*16 + (lane & 7) + ((lane & 16) ? 8 : 0);
                    uint32_t of = ks*32 + ((lane & 8) ? 16 : 0);
                    LDSM4(bfr[nq], stg + 3*TILE_B + sw64(r*64 + of));
                }
#pragma unroll
                for (int mf = 0; mf < 2; mf++)
#pragma unroll
                    for (int nf = 0; nf < 8; nf++)
                        MMA16816(acc[mf][nf], afr[0][mf], bfr[nf>>1][(nf&1)*2], bfr[nf>>1][(nf&1)*2 + 1]);
            }
        }
        if (c + 2 < nc) issue(c + 2, sbase + (uint32_t)((c + 2) % 3)*STAGE_B);
    }
}

#define MMA_PROLOG() \
    extern __shared__ char smem[]; \
    uint32_t sbase = smem_u32(smem); \
    int tid = threadIdx.x, lane = tid & 31, wid = tid >> 5; \
    int wm = wid & 3, wn = wid >> 2; \
    int arow = tid >> 1, half_ = tid & 1; \
    float acc[2][8][4]; \
    _Pragma("unroll") for (int i = 0; i < 2; i++) \
    _Pragma("unroll") for (int j = 0; j < 8; j++) \
    _Pragma("unroll") for (int q = 0; q < 4; q++) acc[i][j][q] = 0.f;

// ---------------- fused r/k/v GEMM: grid(24, 32) ----------------
__global__ void __launch_bounds__(256, 2) rkv_mma(
    const __half* __restrict__ A1, const __half* __restrict__ A2,
    const __half* __restrict__ B1, const __half* __restrict__ B2)
{
    MMA_PROLOG();
    int m0 = blockIdx.y * 128;
    size_t aro = (size_t)(m0 + arow)*Cn + half_*16;
    size_t bro = (size_t)(blockIdx.x*128 + arow)*Cn + half_*16;
    mma_core<3>(sbase, A1 + aro, A2 + aro, A1 + aro, A2 + aro, Cn,
                B1 + bro, B2 + bro, Cn, tid, lane, wm, wn, acc);

    int mat = blockIdx.x >> 3;
    float* outp = (mat == 0) ? g_R : ((mat == 1) ? g_K : g_V);
    int cbase = (blockIdx.x & 7)*128 + wn*64;
#pragma unroll
    for (int mf = 0; mf < 2; mf++) {
        int r0 = m0 + wm*32 + mf*16 + (lane >> 2);
#pragma unroll
        for (int nf = 0; nf < 8; nf++) {
            int cc = cbase + nf*8 + (lane & 3)*2;
#pragma unroll
            for (int h = 0; h < 2; h++) {
                int r = r0 + h*8;
                float v0 = acc[mf][nf][h*2], v1 = acc[mf][nf][h*2 + 1];
                if (mat == 0) {
                    v0 = 1.f/(1.f + expf(-v0));
                    v1 = 1.f/(1.f + expf(-v1));
                }
                float* cr = outp + (size_t)r*Cn + cc;
                cr[0] = v0; cr[1] = v1;
            }
        }
    }
}

// ---------------- generic dense GEMM: MODE 0: C=acc  2: C+=acc ----------------
template<int MODE, int NP>
__global__ void __launch_bounds__(256, 2) gemm_mma(
    const __half* __restrict__ A1, const __half* __restrict__ A2,
    const __half* __restrict__ B1, const __half* __restrict__ B2,
    float* __restrict__ Cf, int K, int N)
{
    MMA_PROLOG();
    int m0 = blockIdx.y * 128;
    size_t aro = (size_t)(m0 + arow)*K + half_*16;
    size_t bro = (size_t)(blockIdx.x*128 + arow)*K + half_*16;
    mma_core<NP>(sbase, A1 + aro, A2 + aro, A1 + aro, A2 + aro, K,
                 B1 + bro, B2 + bro, K, tid, lane, wm, wn, acc);

    int cbase = blockIdx.x*128 + wn*64;
#pragma unroll
    for (int mf = 0; mf < 2; mf++) {
        int r0 = m0 + wm*32 + mf*16 + (lane >> 2);
#pragma unroll
        for (int nf = 0; nf < 8; nf++) {
            int cc = cbase + nf*8 + (lane & 3)*2;
#pragma unroll
            for (int h = 0; h < 2; h++) {
                int r = r0 + h*8;
                float v0 = acc[mf][nf][h*2], v1 = acc[mf][nf][h*2 + 1];
                float* cr = Cf + (size_t)r*N + cc;
                if (MODE == 2) { cr[0] += v0; cr[1] += v1; }
                else           { cr[0] = v0;  cr[1] = v1; }
            }
        }
    }
}

// ---------------- fused expert up-proj: grid(32, 32, 3); A row stride Cn, switch at ksw=Cn
struct UpArgs {
    const __half* A1[3]; const __half* A2[3];
    const __half* A1b[3]; const __half* A2b[3];
    const __half* B1[3]; const __half* B2[3];
    int K[3];
};
template<int NP>
__global__ void __launch_bounds__(256, 2) up3_mma(UpArgs ua) {
    int z = blockIdx.z;
    int Meff = g_CNT[z];
    int m0 = blockIdx.y * 128;
    if (m0 >= Meff) return;
    const int* rows = g_LIST + z*BT;
    int K = ua.K[z];

    MMA_PROLOG();
    int am = m0 + arow;
    int amc = (am < Meff) ? am : (Meff - 1);
    size_t aro = (size_t)rows[amc]*Cn + half_*16;
    size_t bro = (size_t)(blockIdx.x*128 + arow)*K + half_*16;
    mma_core<NP>(sbase, ua.A1[z] + aro, ua.A2[z] + aro, ua.A1b[z] + aro, ua.A2b[z] + aro, Cn,
                 ua.B1[z] + bro, ua.B2[z] + bro, K, tid, lane, wm, wn, acc);

    int cbase = blockIdx.x*128 + wn*64;
#pragma unroll
    for (int mf = 0; mf < 2; mf++) {
        int r0 = m0 + wm*32 + mf*16 + (lane >> 2);
#pragma unroll
        for (int nf = 0; nf < 8; nf++) {
            int cc = cbase + nf*8 + (lane & 3)*2;
#pragma unroll
            for (int h = 0; h < 2; h++) {
                int r = r0 + h*8;
                if (r >= Meff) continue;
                size_t o = (size_t)rows[r]*Hn + cc;
                float v0 = fmaxf(acc[mf][nf][h*2],     0.f);
                float v1 = fmaxf(acc[mf][nf][h*2 + 1], 0.f);
                split2(v0, g_HD1[o],   g_HD2[o]);
                split2(v1, g_HD1[o+1], g_HD2[o+1]);
            }
        }
    }
}

// ---------------- fused expert down-proj: grid(8, 32, 3) ----------------
struct DnArgs { const __half* B1[3]; const __half* B2[3]; };
template<int NP>
__global__ void __launch_bounds__(256, 2) dn3_mma(DnArgs da) {
    int z = blockIdx.z;
    int Meff = g_CNT[z];
    int m0 = blockIdx.y * 128;
    if (m0 >= Meff) return;
    const int* rows = g_LIST + z*BT;

    MMA_PROLOG();
    int am = m0 + arow;
    int amc = (am < Meff) ? am : (Meff - 1);
    size_t aro = (size_t)rows[amc]*Hn + half_*16;
    size_t bro = (size_t)(blockIdx.x*128 + arow)*Hn + half_*16;
    mma_core<NP>(sbase, g_HD1 + aro, g_HD2 + aro, g_HD1 + aro, g_HD2 + aro, Hn,
                 da.B1[z] + bro, da.B2[z] + bro, Hn, tid, lane, wm, wn, acc);

    int cbase = blockIdx.x*128 + wn*64;
#pragma unroll
    for (int mf = 0; mf < 2; mf++) {
        int r0 = m0 + wm*32 + mf*16 + (lane >> 2);
#pragma unroll
        for (int nf = 0; nf < 8; nf++) {
            int cc = cbase + nf*8 + (lane & 3)*2;
#pragma unroll
            for (int h = 0; h < 2; h++) {
                int r = r0 + h*8;
                if (r >= Meff) continue;
                int tok = rows[r];
                float sc = g_SC[tok];
                float* xr = g_X + (size_t)tok*Cn + cc;
                xr[0] += acc[mf][nf][h*2]*sc;
                xr[1] += acc[mf][nf][h*2 + 1]*sc;
            }
        }
    }
}

// ---------------- embedding gather ----------------
__global__ void embed_k(const int* __restrict__ idx, const float* __restrict__ emb) {
    int i = blockIdx.x*blockDim.x + threadIdx.x;
    if (i >= BT*Cn) return;
    int row = i >> 10, c = i & 1023;
    g_X[i] = emb[(size_t)idx[row]*Cn + c];
}

// ---------------- fused ln1 + token-shift mix -> MX pair ----------------
__global__ void ln1mix_k(const float* __restrict__ in, const float* __restrict__ g,
                         const float* __restrict__ b) {
    int row = blockIdx.x;
    int t = row & (Tn - 1);
    const float* p = in + (size_t)row*Cn;
    const float* pp = in + (size_t)(row-1)*Cn;
    float v[4], u[4];
    float s = 0.f, ss = 0.f, su = 0.f, ssu = 0.f;
#pragma unroll
    for (int j = 0; j < 4; j++) {
        int c = threadIdx.x + j*256;
        v[j] = p[c];
        s += v[j]; ss += v[j]*v[j];
        u[j] = (t > 0) ? pp[c] : 0.f;
        su += u[j]; ssu += u[j]*u[j];
    }
#pragma unroll
    for (int o = 16; o > 0; o >>= 1) {
        s   += __shfl_xor_sync(0xffffffffu, s,   o);
        ss  += __shfl_xor_sync(0xffffffffu, ss,  o);
        su  += __shfl_xor_sync(0xffffffffu, su,  o);
        ssu += __shfl_xor_sync(0xffffffffu, ssu, o);
    }
    __shared__ float sh[4][8];
    int w = threadIdx.x >> 5;
    if ((threadIdx.x & 31) == 0) { sh[0][w] = s; sh[1][w] = ss; sh[2][w] = su; sh[3][w] = ssu; }
    __syncthreads();
    s = 0.f; ss = 0.f; su = 0.f; ssu = 0.f;
#pragma unroll
    for (int j = 0; j < 8; j++) { s += sh[0][j]; ss += sh[1][j]; su += sh[2][j]; ssu += sh[3][j]; }
    float mv = s*(1.f/Cn),  rv = rsqrtf(ss*(1.f/Cn) - mv*mv + 1e-5f);
    float mu = su*(1.f/Cn), ru = rsqrtf(ssu*(1.f/Cn) - mu*mu + 1e-5f);
#pragma unroll
    for (int j = 0; j < 4; j++) {
        int c = threadIdx.x + j*256;
        float hv = (v[j]-mv)*rv*g[c] + b[c];
        float hu = (t > 0) ? ((u[j]-mu)*ru*g[c] + b[c]) : 0.f;
        float mix = 0.5f*(hv + hu);
        size_t id = (size_t)row*Cn + c;
        split2(mix, g_MX1[id], g_MX2[id]);
    }
}

// ---------------- fused ln2 + route (or plain lnf) -> HB pair ----------------
template<bool ROUTE>
__global__ void ln2r_k(const float* __restrict__ in, const float* __restrict__ g,
                       const float* __restrict__ b,
                       __half* __restrict__ o1, __half* __restrict__ o2,
                       const float* __restrict__ wc, const float* __restrict__ wa,
                       const float* __restrict__ shp) {
    int row = blockIdx.x;
    const float* p = in + (size_t)row*Cn;
    float v[4];
    float s = 0.f, ss = 0.f;
#pragma unroll
    for (int j = 0; j < 4; j++) {
        v[j] = p[threadIdx.x + j*256];
        s += v[j]; ss += v[j]*v[j];
    }
#pragma unroll
    for (int o = 16; o > 0; o >>= 1) {
        s  += __shfl_xor_sync(0xffffffffu, s,  o);
        ss += __shfl_xor_sync(0xffffffffu, ss, o);
    }
    __shared__ float sh[2][8];
    int w = threadIdx.x >> 5;
    if ((threadIdx.x & 31) == 0) { sh[0][w] = s; sh[1][w] = ss; }
    __syncthreads();
    s = 0.f; ss = 0.f;
#pragma unroll
    for (int j = 0; j < 8; j++) { s += sh[0][j]; ss += sh[1][j]; }
    float mean = s * (1.f/Cn);
    float rstd = rsqrtf(ss*(1.f/Cn) - mean*mean + 1e-5f);

    float pq[6] = {0,0,0,0,0,0};
#pragma unroll
    for (int j = 0; j < 4; j++) {
        int c = threadIdx.x + j*256;
        float val = (v[j]-mean)*rstd*g[c] + b[c];
        size_t id = (size_t)row*Cn + c;
        split2(val, o1[id], o2[id]);
        if (ROUTE) {
            pq[0] += val*wc[c];
            pq[1] += val*wc[Cn + c];
            pq[2] += val*wc[2*Cn + c];
            pq[3] += val*wa[c*En + 0];
            pq[4] += val*wa[c*En + 1];
            pq[5] += val*wa[c*En + 2];
        }
    }
    if (ROUTE) {
#pragma unroll
        for (int o = 16; o > 0; o >>= 1)
#pragma unroll
            for (int q = 0; q < 6; q++) pq[q] += __shfl_xor_sync(0xffffffffu, pq[q], o);
        __shared__ float sm[8][6];
        if ((threadIdx.x & 31) == 0)
#pragma unroll
            for (int q = 0; q < 6; q++) sm[w][q] = pq[q];
        __syncthreads();
        if (threadIdx.x == 0) {
            float d[6];
#pragma unroll
            for (int q = 0; q < 6; q++) {
                d[q] = 0.f;
#pragma unroll
                for (int ww = 0; ww < 8; ww++) d[q] += sm[ww][q];
            }
            float best = -3.4e38f, wcf = 0.f;
            int wi = 0;
#pragma unroll
            for (int e = 0; e < En; e++) {
                float conf = 1.f/(1.f + expf(-d[e]));
                float bid  = conf*shp[e] + d[3+e];
                if (bid > best) { best = bid; wi = e; wcf = conf; }
            }
            g_SC[row] = wcf / (wcf + 1e-6f);
            int pos = atomicAdd(&g_CNT[wi], 1);
            g_LIST[wi*BT + pos] = row;
        }
    }
}

// ---------------- scan phase 1 (+ CNT zeroing for this layer's routing) ----------------
__global__ void scan1_k() {
    if (blockIdx.x == 0 && threadIdx.x < En) g_CNT[threadIdx.x] = 0;
    int i = blockIdx.x*blockDim.x + threadIdx.x;
    if (i >= Bsz*CH*Cn) return;
    int c  = i & 1023;
    int ch = (i >> 10) & (CH - 1);
    int b  = i >> 14;
    size_t base = (size_t)b*Tn*Cn + (size_t)ch*CL*Cn + c;
    float s = 0.f;
#pragma unroll 4
    for (int t = 0; t < CL; t++) {
        size_t id = base + (size_t)t*Cn;
        s += g_K[id]*g_V[id];
    }
    g_PART[i] = s;
}
// ---------------- scan phase 2+3 fused ----------------
__global__ void scan3_k() {
    int i = blockIdx.x*blockDim.x + threadIdx.x;
    if (i >= Bsz*CH*Cn) return;
    int c  = i & 1023;
    int ch = (i >> 10) & (CH - 1);
    int b  = i >> 14;
    float acc = 0.f;
    for (int j = 0; j < CH; j++)
        if (j < ch) acc += g_PART[((b*CH + j) << 10) | c];
    size_t base = (size_t)b*Tn*Cn + (size_t)ch*CL*Cn + c;
    int t0 = ch*CL;
#pragma unroll 4
    for (int t = 0; t < CL; t++) {
        size_t id = base + (size_t)t*Cn;
        acc += g_K[id]*g_V[id];
        float st = acc / (float)(t0 + t + 1);
        split2(st, g_SP1[id], g_SP2[id]);
        float rs = g_R[id]*st;
        split2(rs, g_MX1[id], g_MX2[id]);
    }
}

// ---------------- batched weight transpose+split ----------------
__global__ void tsplit_k(const float* __restrict__ W,
                         __half* __restrict__ o1, __half* __restrict__ o2,
                         int K, int N, size_t srcStride, size_t dstStride) {
    __shared__ __half s1[32][33], s2[32][33];
    int z = blockIdx.z;
    W  += (size_t)z*srcStride;
    o1 += (size_t)z*dstStride;
    o2 += (size_t)z*dstStride;
    int n0 = blockIdx.x*32, k0 = blockIdx.y*32;
    int tx = threadIdx.x, ty = threadIdx.y;
#pragma unroll
    for (int j = 0; j < 4; j++) {
        int k = k0 + ty + j*8;
        float v = W[(size_t)k*N + n0 + tx];
        split2(v, s1[ty+j*8][tx], s2[ty+j*8][tx]);
    }
    __syncthreads();
#pragma unroll
    for (int j = 0; j < 4; j++) {
        int n = n0 + ty + j*8;
        size_t o = (size_t)n*K + k0 + tx;
        o1[o] = s1[tx][ty+j*8];
        o2[o] = s2[tx][ty+j*8];
    }
}

// ---------------- launch ----------------
extern "C" void kernel_launch(void* const* d_in, const int* in_sizes, int n_in,
                              void* d_out, int out_size)
{
    const int*   idx   = (const int*)  d_in[0];
    const float* shares= (const float*)d_in[1];
    const float* emb   = (const float*)d_in[2];
    const float* ln1g  = (const float*)d_in[3];
    const float* ln1b  = (const float*)d_in[4];
    const float* ln2g  = (const float*)d_in[5];
    const float* ln2b  = (const float*)d_in[6];
    const float* Wr    = (const float*)d_in[7];
    const float* Wk    = (const float*)d_in[8];
    const float* Wv    = (const float*)d_in[9];
    const float* Wo    = (const float*)d_in[10];
    const float* W1    = (const float*)d_in[11];
    const float* W2    = (const float*)d_in[12];
    const float* wconf = (const float*)d_in[13];
    const float* Wl1   = (const float*)d_in[14];
    const float* Wl2   = (const float*)d_in[15];
    const float* Waff  = (const float*)d_in[17];
    const float* lnfg  = (const float*)d_in[18];
    const float* lnfb  = (const float*)d_in[19];
    const float* headW = (const float*)d_in[20];
    float* out = (float*)d_out;
    (void)in_sizes; (void)n_in; (void)out_size;

    float *X;
    __half *MX1,*MX2, *SP1,*SP2, *HB1,*HB2, *WT1,*WT2;
    cudaGetSymbolAddress((void**)&X,   g_X);
    cudaGetSymbolAddress((void**)&MX1, g_MX1); cudaGetSymbolAddress((void**)&MX2, g_MX2);
    cudaGetSymbolAddress((void**)&SP1, g_SP1); cudaGetSymbolAddress((void**)&SP2, g_SP2);
    cudaGetSymbolAddress((void**)&HB1, g_HB1); cudaGetSymbolAddress((void**)&HB2, g_HB2);
    cudaGetSymbolAddress((void**)&WT1, g_WT1); cudaGetSymbolAddress((void**)&WT2, g_WT2);

    cudaFuncSetAttribute(rkv_mma,        cudaFuncAttributeMaxDynamicSharedMemorySize, SMEMB);
    cudaFuncSetAttribute(gemm_mma<2,3>,  cudaFuncAttributeMaxDynamicSharedMemorySize, SMEMB);
    cudaFuncSetAttribute(gemm_mma<0,1>,  cudaFuncAttributeMaxDynamicSharedMemorySize, SMEMB);
    cudaFuncSetAttribute(up3_mma<3>,     cudaFuncAttributeMaxDynamicSharedMemorySize, SMEMB);
    cudaFuncSetAttribute(up3_mma<2>,     cudaFuncAttributeMaxDynamicSharedMemorySize, SMEMB);
    cudaFuncSetAttribute(dn3_mma<3>,     cudaFuncAttributeMaxDynamicSharedMemorySize, SMEMB);
    cudaFuncSetAttribute(dn3_mma<2>,     cudaFuncAttributeMaxDynamicSharedMemorySize, SMEMB);

    dim3 tb(32, 8);
    // arena per layer: Wr@0 Wk@CC Wv@2CC Wo@3CC | W1e0@4CC W1e1@8CC | W2e0@12CC W2e1@16CC | Wl1@20CC Wl2@28CC
    tsplit_k<<<dim3(Cn/32, Cn/32, Ln), tb>>>(Wr, WT1,              WT2,              Cn, Cn, CC, WPL);
    tsplit_k<<<dim3(Cn/32, Cn/32, Ln), tb>>>(Wk, WT1+CC,           WT2+CC,           Cn, Cn, CC, WPL);
    tsplit_k<<<dim3(Cn/32, Cn/32, Ln), tb>>>(Wv, WT1+2*(size_t)CC, WT2+2*(size_t)CC, Cn, Cn, CC, WPL);
    tsplit_k<<<dim3(Cn/32, Cn/32, Ln), tb>>>(Wo, WT1+3*(size_t)CC, WT2+3*(size_t)CC, Cn, Cn, CC, WPL);
    tsplit_k<<<dim3(Hn/32, Cn/32, Ln), tb>>>(W1,                 WT1+4*(size_t)CC,  WT2+4*(size_t)CC,  Cn, Hn, 2*(size_t)Cn*Hn, WPL);
    tsplit_k<<<dim3(Hn/32, Cn/32, Ln), tb>>>(W1 + (size_t)Cn*Hn, WT1+8*(size_t)CC,  WT2+8*(size_t)CC,  Cn, Hn, 2*(size_t)Cn*Hn, WPL);
    tsplit_k<<<dim3(Cn/32, Hn/32, Ln), tb>>>(W2,                 WT1+12*(size_t)CC, WT2+12*(size_t)CC, Hn, Cn, 2*(size_t)Hn*Cn, WPL);
    tsplit_k<<<dim3(Cn/32, Hn/32, Ln), tb>>>(W2 + (size_t)Hn*Cn, WT1+16*(size_t)CC, WT2+16*(size_t)CC, Hn, Cn, 2*(size_t)Hn*Cn, WPL);
    tsplit_k<<<dim3(Hn/32, 2*Cn/32, Ln), tb>>>(Wl1, WT1+20*(size_t)CC, WT2+20*(size_t)CC, 2*Cn, Hn, 2*(size_t)Cn*Hn, WPL);
    tsplit_k<<<dim3(Cn/32, Hn/32, Ln), tb>>>(Wl2, WT1+28*(size_t)CC, WT2+28*(size_t)CC, Hn, Cn, (size_t)Hn*Cn, WPL);
    tsplit_k<<<dim3(Vn/32, Cn/32, 1), tb>>>(headW, WT1+WHEAD, WT2+WHEAD, Cn, Vn, 0, 0);

    embed_k<<<(BT*Cn)/256, 256>>>(idx, emb);

    for (int l = 0; l < Ln; l++) {
        size_t LB = (size_t)l*WPL;
        ln1mix_k<<<BT, 256>>>(X, ln1g + (size_t)l*Cn, ln1b + (size_t)l*Cn);

        rkv_mma<<<dim3(24, 32), 256, SMEMB>>>(MX1, MX2, WT1+LB, WT2+LB);

        scan1_k<<<(Bsz*CH*Cn)/256, 256>>>();   // also zeroes CNT for this layer
        scan3_k<<<(Bsz*CH*Cn)/256, 256>>>();

        gemm_mma<2,3><<<dim3(8, 32), 256, SMEMB>>>(MX1, MX2, WT1+LB+3*(size_t)CC, WT2+LB+3*(size_t)CC, X, Cn, Cn);

        ln2r_k<true><<<BT, 256>>>(X, ln2g + (size_t)l*Cn, ln2b + (size_t)l*Cn, HB1, HB2,
                                  wconf + (size_t)l*En*Cn, Waff + (size_t)l*Cn*En,
                                  shares + (size_t)l*En);

        UpArgs ua;
        DnArgs da;
        for (int e = 0; e < 2; e++) {
            size_t o1 = LB + (4 + 4*e)*(size_t)CC;
            size_t o2 = LB + (12 + 4*e)*(size_t)CC;
            ua.A1[e] = HB1; ua.A2[e] = HB2;
            ua.A1b[e] = HB1; ua.A2b[e] = HB2;   // unused (K=Cn)
            ua.B1[e] = WT1 + o1; ua.B2[e] = WT2 + o1;
            ua.K[e] = Cn;
            da.B1[e] = WT1 + o2; da.B2[e] = WT2 + o2;
        }
        ua.A1[2] = HB1; ua.A2[2] = HB2;
        ua.A1b[2] = SP1; ua.A2b[2] = SP2;       // second half of hz = state pair
        ua.B1[2] = WT1 + LB + 20*(size_t)CC; ua.B2[2] = WT2 + LB + 20*(size_t)CC;
        ua.K[2] = 2*Cn;
        da.B1[2] = WT1 + LB + 28*(size_t)CC; da.B2[2] = WT2 + LB + 28*(size_t)CC;

        if (l == Ln - 1) {
            // last layer: expert outputs feed only lnf/head (no further routing) ->
            // 2-product suffices (error class validated at ~2e-4 on logits)
            up3_mma<2><<<dim3(32, 32, 3), 256, SMEMB>>>(ua);
            dn3_mma<2><<<dim3(8, 32, 3), 256, SMEMB>>>(da);
        } else {
            up3_mma<3><<<dim3(32, 32, 3), 256, SMEMB>>>(ua);
            dn3_mma<3><<<dim3(8, 32, 3), 256, SMEMB>>>(da);
        }
    }

    ln2r_k<false><<<BT, 256>>>(X, lnfg, lnfb, HB1, HB2, nullptr, nullptr, nullptr);
    // head: pure fp16 single product (error model: ~2.9e-4, validated margin under 1e-3)
    gemm_mma<0,1><<<dim3(Vn/128, BT/128), 256, SMEMB>>>(HB1, HB2, WT1+WHEAD, WT2+WHEAD, out, Cn, Vn);
}